// round 6
// baseline (speedup 1.0000x reference)
#include <cuda_runtime.h>
#include <cuda_bf16.h>
#include <stdint.h>
#include <math.h>

#define LAYERS_   10
#define NL_       40
#define RC_       32
#define DC_       32
#define SC_       256
#define EC_       256
#define CL_       256
#define B_        8
#define T_        16384
#define BT_       131072   /* B_*T_ */

typedef unsigned long long u64;

// ---------------- scratch (static device globals; no allocations) -------------
__device__ float g_h[32 * BT_];                       // residual state, [c][BT]
__device__ float g_z[167772160];                      // 40*32*BT, [layer][c][BT] (tf32-rounded)
__device__ float g_skip[SC_ * BT_];                   // [c][BT]  relu(skip), tf32-rounded
__device__ float g_out1[EC_ * BT_];                   // [c][BT]  relu(out1), tf32-rounded
__device__ float g_skipb[SC_];
__device__ unsigned g_wA[786432];                     // packed tf32 weights, K-major

#define WOFF_SKIP 0
#define WOFF_E1   655360
#define WOFF_E2   720896

// ---------------- small helpers ----------------
__device__ __forceinline__ unsigned f2tf(float x) {
    unsigned r;
    asm("cvt.rna.tf32.f32 %0, %1;" : "=r"(r) : "f"(x));
    return r;
}
__device__ __forceinline__ float rtf(float x) {      // RN-round to tf32, as float
    return __uint_as_float(f2tf(x));
}
__device__ __forceinline__ void mma8(float* d, const unsigned* a, const unsigned* b) {
    asm volatile(
        "mma.sync.aligned.m16n8k8.row.col.f32.tf32.tf32.f32 "
        "{%0,%1,%2,%3},{%4,%5,%6,%7},{%8,%9},{%0,%1,%2,%3};\n"
        : "+f"(d[0]), "+f"(d[1]), "+f"(d[2]), "+f"(d[3])
        : "r"(a[0]), "r"(a[1]), "r"(a[2]), "r"(a[3]), "r"(b[0]), "r"(b[1]));
}

// packed f32x2 fma: d.lo += a.lo*b.lo ; d.hi += a.hi*b.hi
__device__ __forceinline__ void fma2(u64& d, u64 a, u64 b) {
    asm("fma.rn.f32x2 %0, %1, %2, %0;" : "+l"(d) : "l"(a), "l"(b));
}
__device__ __forceinline__ u64 dup2(float x) {
    u64 r; unsigned xi = __float_as_uint(x);
    asm("mov.b64 %0, {%1, %1};" : "=l"(r) : "r"(xi));
    return r;
}
__device__ __forceinline__ float2 unpk(u64 v) {
    unsigned lo, hi;
    asm("mov.b64 {%0, %1}, %2;" : "=r"(lo), "=r"(hi) : "l"(v));
    return make_float2(__uint_as_float(lo), __uint_as_float(hi));
}
// load 2 adjacent tokens at offset -d with causal zero-padding
__device__ __forceinline__ float2 ld2prev(const float* __restrict__ row, int i0,
                                          int tmod, int d) {
    if (((d & 1) == 0) && tmod >= d) return *(const float2*)(row + (i0 - d));
    float2 r;
    r.x = (tmod >= d) ? row[i0 - d] : 0.f;
    r.y = (tmod + 1 >= d) ? row[i0 + 1 - d] : 0.f;
    return r;
}
// 3-MUFU activation: tanh(f)*sigmoid(g), tf32-rounded
__device__ __forceinline__ float act_z(float fx, float gx) {
    float a = __expf(-2.f * fabsf(fx));   // EX2
    float b = __expf(-gx);                // EX2
    float den = (1.f + a) * (1.f + b);
    float r;
    asm("rcp.approx.f32 %0, %1;" : "=f"(r) : "f"(den));  // RCP
    return rtf(copysignf((1.f - a) * r, fx));
}

#define CP16(dst, src) asm volatile("cp.async.cg.shared.global [%0], [%1], 16;\n" :: "r"(dst), "l"(src))
#define CPCOMMIT()     asm volatile("cp.async.commit_group;\n")
#define CPWAIT1()      asm volatile("cp.async.wait_group 1;\n" ::: "memory")
#define CPWAIT0()      asm volatile("cp.async.wait_group 0;\n" ::: "memory")

// ---------------- bias reduction for skip ----------------
__global__ void k_bias(const float* __restrict__ skip_b) {
    int o = threadIdx.x;
    float s = 0.f;
#pragma unroll 1
    for (int i = 0; i < NL_; i++) s += skip_b[i * SC_ + o];
    g_skipb[o] = s;
}

// ---------------- pack all GEMM weights K-major as tf32 ----------------
__global__ void k_pack(const float* __restrict__ skip_w,
                       const float* __restrict__ e1w,
                       const float* __restrict__ e2w) {
    int idx = blockIdx.x * 256 + threadIdx.x;
    if (idx < WOFF_E1) {
        int k = idx >> 8, m = idx & 255;
        int li = k >> 6, tap = (k >> 5) & 1, c = k & 31;
        g_wA[idx] = f2tf(skip_w[((size_t)(li * 256 + m) * 32 + c) * 2 + tap]);
    } else if (idx < WOFF_E2) {
        int local = idx - WOFF_E1;
        int k = local >> 8, m = local & 255;
        g_wA[idx] = f2tf(e1w[m * 256 + k]);
    } else if (idx < 786432) {
        int local = idx - WOFF_E2;
        int k = local >> 8, m = local & 255;
        g_wA[idx] = f2tf(e2w[m * 256 + k]);
    }
}

// ---------------- input 1x1 conv: x[8,256,16384] -> h[32][BT] ----------------
__global__ __launch_bounds__(256) void k_input(const float* __restrict__ x,
                                               const float* __restrict__ w_in,
                                               const float* __restrict__ b_in) {
    __shared__ float ws[256 * 32];   // [c][rc]
    __shared__ float bs[32];
    int tid = threadIdx.x;
    for (int e = tid; e < 256 * 32; e += 256) {
        int c = e >> 5, rc = e & 31;
        ws[e] = w_in[rc * 256 + c];
    }
    if (tid < 32) bs[tid] = b_in[tid];
    __syncthreads();

    int i0 = blockIdx.x * 512 + tid;
    int i1 = i0 + 256;
    int b0 = i0 >> 14, t0 = i0 & (T_ - 1);
    int b1 = i1 >> 14, t1 = i1 & (T_ - 1);
    const float* x0 = x + (size_t)b0 * 256 * T_ + t0;
    const float* x1 = x + (size_t)b1 * 256 * T_ + t1;

    float a0[32], a1[32];
#pragma unroll
    for (int r = 0; r < 32; r++) { a0[r] = bs[r]; a1[r] = bs[r]; }

#pragma unroll 1
    for (int c = 0; c < 256; c++) {
        float xv0 = x0[(size_t)c * T_];
        float xv1 = x1[(size_t)c * T_];
        const float* w = &ws[c * 32];
#pragma unroll
        for (int r = 0; r < 32; r++) {
            a0[r] = fmaf(w[r], xv0, a0[r]);
            a1[r] = fmaf(w[r], xv1, a1[r]);
        }
    }
#pragma unroll
    for (int r = 0; r < 32; r++) {
        g_h[r * BT_ + i0] = a0[r];
        g_h[r * BT_ + i1] = a1[r];
    }
}

// ---------------- per-layer z = tanh(filt)*sigmoid(gate), f32x2 packed -------
// thread = 2 adjacent tokens x 8 outputs (filt+gate); 4 output-groups
// block 256 threads: 64 token-slots x 4 groups; 128 tokens/block; 3 CTAs/SM
__global__ __launch_bounds__(256, 3) void k_z(const float* __restrict__ filt_w,
                                              const float* __restrict__ filt_b,
                                              const float* __restrict__ gate_w,
                                              const float* __restrict__ gate_b,
                                              int layer, int dil) {
    __shared__ __align__(16) float s_fw0[1024], s_fw1[1024], s_gw0[1024], s_gw1[1024];
    __shared__ float s_fb[32], s_gb[32];
    int tid = threadIdx.x;
    {
        const float* fwL = filt_w + layer * 2048;
        const float* gwL = gate_w + layer * 2048;
        for (int e = tid; e < 1024; e += 256) {
            int c = e >> 5, o = e & 31;
            int src = (o * 32 + c) * 2;
            s_fw0[c * 32 + o] = fwL[src];
            s_fw1[c * 32 + o] = fwL[src + 1];
            s_gw0[c * 32 + o] = gwL[src];
            s_gw1[c * 32 + o] = gwL[src + 1];
        }
        if (tid < 32) {
            s_fb[tid] = filt_b[layer * 32 + tid];
            s_gb[tid] = gate_b[layer * 32 + tid];
        }
    }
    __syncthreads();

    int og = tid >> 6;          // 0..3
    int slot = tid & 63;
    int ob = og * 8;
    int i0 = blockIdx.x * 128 + slot * 2;
    int tmod = i0 & (T_ - 1);

    u64 fa0[4], fa1[4], ga0[4], ga1[4];
#pragma unroll
    for (int p = 0; p < 4; p++) { fa0[p] = 0; fa1[p] = 0; ga0[p] = 0; ga1[p] = 0; }

    float2 hc = *(const float2*)(g_h + i0);
    float2 hp = ld2prev(g_h, i0, tmod, dil);

#pragma unroll 1
    for (int c = 0; c < 32; c++) {
        int cn = (c < 31) ? c + 1 : 31;
        const float* nrow = g_h + (size_t)cn * BT_;
        float2 nhc = *(const float2*)(nrow + i0);
        float2 nhp = ld2prev(nrow, i0, tmod, dil);

        u64 hcx = dup2(hc.x), hcy = dup2(hc.y);
        u64 hpx = dup2(hp.x), hpy = dup2(hp.y);

        const ulonglong2* wf0 = (const ulonglong2*)&s_fw0[c * 32 + ob];
        const ulonglong2* wf1 = (const ulonglong2*)&s_fw1[c * 32 + ob];
        const ulonglong2* wg0 = (const ulonglong2*)&s_gw0[c * 32 + ob];
        const ulonglong2* wg1 = (const ulonglong2*)&s_gw1[c * 32 + ob];
#pragma unroll
        for (int q = 0; q < 2; q++) {
            ulonglong2 f0 = wf0[q], f1 = wf1[q];
            fma2(fa0[2 * q], f0.x, hpx);     fma2(fa0[2 * q], f1.x, hcx);
            fma2(fa0[2 * q + 1], f0.y, hpx); fma2(fa0[2 * q + 1], f1.y, hcx);
            fma2(fa1[2 * q], f0.x, hpy);     fma2(fa1[2 * q], f1.x, hcy);
            fma2(fa1[2 * q + 1], f0.y, hpy); fma2(fa1[2 * q + 1], f1.y, hcy);
            ulonglong2 g0 = wg0[q], g1 = wg1[q];
            fma2(ga0[2 * q], g0.x, hpx);     fma2(ga0[2 * q], g1.x, hcx);
            fma2(ga0[2 * q + 1], g0.y, hpx); fma2(ga0[2 * q + 1], g1.y, hcx);
            fma2(ga1[2 * q], g0.x, hpy);     fma2(ga1[2 * q], g1.x, hcy);
            fma2(ga1[2 * q + 1], g0.y, hpy); fma2(ga1[2 * q + 1], g1.y, hcy);
        }
        hc = nhc;
        hp = nhp;
    }

    // epilogue: pair p covers outputs (ob+2p, ob+2p+1); fa0=token-lo, fa1=token-hi
#pragma unroll
    for (int p = 0; p < 4; p++) {
        int o0 = ob + 2 * p, o1 = o0 + 1;
        float2 fl = unpk(fa0[p]), fh = unpk(fa1[p]);
        float2 gl = unpk(ga0[p]), gh = unpk(ga1[p]);
        float fb0 = s_fb[o0], fb1 = s_fb[o1], gb0 = s_gb[o0], gb1 = s_gb[o1];
        float2 z0 = make_float2(act_z(fl.x + fb0, gl.x + gb0),
                                act_z(fh.x + fb0, gh.x + gb0));
        float2 z1 = make_float2(act_z(fl.y + fb1, gl.y + gb1),
                                act_z(fh.y + fb1, gh.y + gb1));
        *(float2*)(g_z + ((size_t)layer * 32 + o0) * BT_ + i0) = z0;
        *(float2*)(g_z + ((size_t)layer * 32 + o1) * BT_ + i0) = z1;
    }
}

// ---------------- per-layer residual update, f32x2 packed --------------------
// thread = 2 adjacent tokens x 16 outputs; 2 output-groups; 256 tokens/block
__global__ __launch_bounds__(256, 3) void k_res(const float* __restrict__ res_w,
                                                const float* __restrict__ res_b,
                                                int layer, int dil) {
    __shared__ __align__(16) float s_w0[1024], s_w1[1024];
    __shared__ float s_b[32];
    int tid = threadIdx.x;
    {
        const float* wL = res_w + layer * 2048;
        for (int e = tid; e < 1024; e += 256) {
            int c = e >> 5, o = e & 31;
            int src = (o * 32 + c) * 2;
            s_w0[c * 32 + o] = wL[src];
            s_w1[c * 32 + o] = wL[src + 1];
        }
        if (tid < 32) s_b[tid] = res_b[layer * 32 + tid];
    }
    __syncthreads();

    int og = tid >> 7;          // 0..1
    int slot = tid & 127;
    int ob = og * 16;
    int i0 = blockIdx.x * 256 + slot * 2;
    int tmod = i0 & (T_ - 1);
    const float* zL = g_z + (size_t)layer * 32 * BT_;

    u64 a0[8], a1[8];
#pragma unroll
    for (int p = 0; p < 8; p++) { a0[p] = 0; a1[p] = 0; }

    float2 zc = *(const float2*)(zL + i0);
    float2 zp = ld2prev(zL, i0, tmod, dil);

#pragma unroll 1
    for (int c = 0; c < 32; c++) {
        int cn = (c < 31) ? c + 1 : 31;
        const float* nrow = zL + (size_t)cn * BT_;
        float2 nzc = *(const float2*)(nrow + i0);
        float2 nzp = ld2prev(nrow, i0, tmod, dil);

        u64 zcx = dup2(zc.x), zcy = dup2(zc.y);
        u64 zpx = dup2(zp.x), zpy = dup2(zp.y);

        const ulonglong2* w0 = (const ulonglong2*)&s_w0[c * 32 + ob];
        const ulonglong2* w1 = (const ulonglong2*)&s_w1[c * 32 + ob];
#pragma unroll
        for (int q = 0; q < 4; q++) {
            ulonglong2 v0 = w0[q], v1 = w1[q];
            fma2(a0[2 * q], v0.x, zpx);     fma2(a0[2 * q], v1.x, zcx);
            fma2(a0[2 * q + 1], v0.y, zpx); fma2(a0[2 * q + 1], v1.y, zcx);
            fma2(a1[2 * q], v0.x, zpy);     fma2(a1[2 * q], v1.x, zcy);
            fma2(a1[2 * q + 1], v0.y, zpy); fma2(a1[2 * q + 1], v1.y, zcy);
        }
        zc = nzc;
        zp = nzp;
    }

#pragma unroll
    for (int p = 0; p < 8; p++) {
        int o0 = ob + 2 * p, o1 = o0 + 1;
        float2 vl = unpk(a0[p]);  // (o0 lo, o1 lo)
        float2 vh = unpk(a1[p]);  // (o0 hi, o1 hi)
        float b0 = s_b[o0], b1 = s_b[o1];
        float* r0 = g_h + (size_t)o0 * BT_ + i0;
        float* r1 = g_h + (size_t)o1 * BT_ + i0;
        float2 h0 = *(const float2*)r0;
        float2 h1 = *(const float2*)r1;
        h0.x += vl.x + b0; h0.y += vh.x + b0;
        h1.x += vl.y + b1; h1.y += vh.y + b1;
        *(float2*)r0 = h0;
        *(float2*)r1 = h1;
    }
}

// ================== unified tf32 GEMM (cp.async staged, double buffered) =====
#define SAS 264
#define SBS 136
#define BUFW 12800

template <int MODE>
__device__ __forceinline__ void stage_step(unsigned* sm, int buf, int s, int t0, int tid) {
    unsigned* sA = sm + buf * BUFW;
    unsigned* sB = sm + buf * BUFW + 32 * SAS;
    const unsigned* asrc = g_wA + (MODE == 0 ? WOFF_SKIP : (MODE == 1 ? WOFF_E1 : WOFF_E2))
                         + (size_t)s * 32 * 256;
#pragma unroll
    for (int i = 0; i < 8; i++) {
        int q = tid + i * 256;
        int row = q >> 6, col = (q & 63) * 4;
        uint32_t dst = (uint32_t)__cvta_generic_to_shared(sA + row * SAS + col);
        CP16(dst, asrc + row * 256 + col);
    }
    if (MODE != 0) {
        const float* gB = (MODE == 1) ? g_skip : g_out1;
#pragma unroll
        for (int i = 0; i < 4; i++) {
            int q = tid + i * 256;
            int row = q >> 5, col = (q & 31) * 4;
            uint32_t dst = (uint32_t)__cvta_generic_to_shared(sB + row * SBS + col);
            CP16(dst, gB + (size_t)(s * 32 + row) * BT_ + t0 + col);
        }
    } else {
        int li = s >> 1, tap = s & 1;
        int d = 1 << (li % LAYERS_);
        int j = tid >> 3, l8 = tid & 7;
        const float* zrow = g_z + ((size_t)li * 32 + j) * BT_;
        if (tap == 1) {
#pragma unroll
            for (int i = 0; i < 4; i++) {
                int q = l8 + i * 8;
                uint32_t dst = (uint32_t)__cvta_generic_to_shared(sB + j * SBS + q * 4);
                CP16(dst, zrow + t0 + q * 4);
            }
        } else {
            int r = (4 - (d & 3)) & 3;
            int t0m = t0 & (T_ - 1);
            if (t0m >= d + 4) {
                const float* src = zrow + t0 - d - r;
#pragma unroll
                for (int i = 0; i < 4; i++) {
                    int q = l8 + i * 8;
                    uint32_t dst = (uint32_t)__cvta_generic_to_shared(sB + j * SBS + q * 4);
                    CP16(dst, src + q * 4);
                }
                if (l8 == 0) {
                    uint32_t dst = (uint32_t)__cvta_generic_to_shared(sB + j * SBS + 128);
                    CP16(dst, src + 128);
                }
            } else {
                for (int t = l8; t < 128; t += 8) {
                    int gm = t0 + t;
                    float v = ((gm & (T_ - 1)) >= d) ? zrow[gm - d] : 0.f;
                    sB[j * SBS + r + t] = __float_as_uint(v);
                }
            }
        }
    }
}

template <int MODE>
__global__ __launch_bounds__(256) void k_gemm(const float* __restrict__ bias,
                                              float* __restrict__ dout) {
    extern __shared__ unsigned sm[];
    constexpr int KS = (MODE == 0) ? 80 : 8;
    int tid = threadIdx.x, warp = tid >> 5, lane = tid & 31;
    int grp = lane >> 2, tig = lane & 3;
    int t0 = blockIdx.x * 128;
    int m_off = (warp >> 1) * 64;
    int n_off = (warp & 1) * 64;

    float acc[4][8][4];
#pragma unroll
    for (int mf = 0; mf < 4; mf++)
#pragma unroll
        for (int nf = 0; nf < 8; nf++)
#pragma unroll
            for (int q = 0; q < 4; q++) acc[mf][nf][q] = 0.f;

    stage_step<MODE>(sm, 0, 0, t0, tid);
    CPCOMMIT();

    int buf = 0;
#pragma unroll 1
    for (int s = 0; s < KS; s++) {
        if (s + 1 < KS) {
            stage_step<MODE>(sm, buf ^ 1, s + 1, t0, tid);
            CPCOMMIT();
            CPWAIT1();
        } else {
            CPWAIT0();
        }
        __syncthreads();

        unsigned* sA = sm + buf * BUFW;
        unsigned* sB = sm + buf * BUFW + 32 * SAS;
        int roff = 0;
        if (MODE == 0 && !(s & 1)) {
            int d = 1 << ((s >> 1) % LAYERS_);
            roff = (4 - (d & 3)) & 3;
        }
#pragma unroll
        for (int kc = 0; kc < 32; kc += 8) {
            unsigned a[4][4], b[8][2];
#pragma unroll
            for (int mf = 0; mf < 4; mf++) {
                int r0 = m_off + mf * 16 + grp;
                a[mf][0] = sA[(kc + tig) * SAS + r0];
                a[mf][1] = sA[(kc + tig) * SAS + r0 + 8];
                a[mf][2] = sA[(kc + tig + 4) * SAS + r0];
                a[mf][3] = sA[(kc + tig + 4) * SAS + r0 + 8];
            }
#pragma unroll
            for (int nf = 0; nf < 8; nf++) {
                int ci = n_off + nf * 8 + grp + roff;
                b[nf][0] = sB[(kc + tig) * SBS + ci];
                b[nf][1] = sB[(kc + tig + 4) * SBS + ci];
            }
#pragma unroll
            for (int mf = 0; mf < 4; mf++)
#pragma unroll
                for (int nf = 0; nf < 8; nf++) mma8(acc[mf][nf], a[mf], b[nf]);
        }
        __syncthreads();
        buf ^= 1;
    }

    const float* bp = (MODE == 0) ? g_skipb : bias;

    if (MODE != 2) {
        float* out = (MODE == 0) ? g_skip : g_out1;
#pragma unroll
        for (int mf = 0; mf < 4; mf++)
#pragma unroll
            for (int nf = 0; nf < 8; nf++) {
                int row0 = m_off + mf * 16 + grp;
                int col = t0 + n_off + nf * 8 + 2 * tig;
                float b0 = bp[row0];
                float b1 = bp[row0 + 8];
                float2 v0 = make_float2(rtf(fmaxf(acc[mf][nf][0] + b0, 0.f)),
                                        rtf(fmaxf(acc[mf][nf][1] + b0, 0.f)));
                float2 v1 = make_float2(rtf(fmaxf(acc[mf][nf][2] + b1, 0.f)),
                                        rtf(fmaxf(acc[mf][nf][3] + b1, 0.f)));
                *(float2*)&out[(size_t)row0 * BT_ + col] = v0;
                *(float2*)&out[(size_t)(row0 + 8) * BT_ + col] = v1;
            }
    } else {
        float* ts = (float*)sm;  // [64 tok][260]
#pragma unroll 1
        for (int h = 0; h < 2; h++) {
            __syncthreads();
            if ((warp & 1) == h) {
#pragma unroll
                for (int mf = 0; mf < 4; mf++)
#pragma unroll
                    for (int nf = 0; nf < 8; nf++) {
                        int rowL = m_off + mf * 16 + grp;
                        int colL = nf * 8 + 2 * tig;  // 0..63
                        float b0 = bp[rowL];
                        float b1 = bp[rowL + 8];
                        ts[colL * 260 + rowL] = acc[mf][nf][0] + b0;
                        ts[(colL + 1) * 260 + rowL] = acc[mf][nf][1] + b0;
                        ts[colL * 260 + rowL + 8] = acc[mf][nf][2] + b1;
                        ts[(colL + 1) * 260 + rowL + 8] = acc[mf][nf][3] + b1;
                    }
            }
            __syncthreads();
#pragma unroll
            for (int i = 0; i < 16; i++) {
                int q = tid + i * 256;
                int tk = q >> 6, c4 = (q & 63) * 4;
                float4 v = *(const float4*)&ts[tk * 260 + c4];
                *(float4*)&dout[(size_t)(t0 + h * 64 + tk) * 256 + c4] = v;
            }
        }
    }
}

// ---------------- host launcher ----------------
extern "C" void kernel_launch(void* const* d_in, const int* in_sizes, int n_in,
                              void* d_out, int out_size) {
    const float* x      = (const float*)d_in[0];
    const float* w_in   = (const float*)d_in[1];
    const float* b_in   = (const float*)d_in[2];
    const float* filt_w = (const float*)d_in[3];
    const float* filt_b = (const float*)d_in[4];
    const float* gate_w = (const float*)d_in[5];
    const float* gate_b = (const float*)d_in[6];
    const float* res_w  = (const float*)d_in[7];
    const float* res_b  = (const float*)d_in[8];
    const float* skip_w = (const float*)d_in[9];
    const float* skip_b = (const float*)d_in[10];
    const float* end1_w = (const float*)d_in[11];
    const float* end1_b = (const float*)d_in[12];
    const float* end2_w = (const float*)d_in[13];
    const float* end2_b = (const float*)d_in[14];
    float* out = (float*)d_out;

    const int SMEM = 25600 * 4;  // 102,400 B dynamic
    cudaFuncSetAttribute(k_gemm<0>, cudaFuncAttributeMaxDynamicSharedMemorySize, SMEM);
    cudaFuncSetAttribute(k_gemm<1>, cudaFuncAttributeMaxDynamicSharedMemorySize, SMEM);
    cudaFuncSetAttribute(k_gemm<2>, cudaFuncAttributeMaxDynamicSharedMemorySize, SMEM);

    k_bias<<<1, 256>>>(skip_b);
    k_pack<<<3072, 256>>>(skip_w, end1_w, end2_w);
    k_input<<<BT_ / 512, 256>>>(x, w_in, b_in);

    for (int i = 0; i < NL_; i++) {
        int d = 1 << (i % LAYERS_);
        k_z<<<BT_ / 128, 256>>>(filt_w, filt_b, gate_w, gate_b, i, d);
        k_res<<<BT_ / 256, 256>>>(res_w, res_b, i, d);
    }

    k_gemm<0><<<BT_ / 128, 256, SMEM>>>(nullptr, nullptr);
    k_gemm<1><<<BT_ / 128, 256, SMEM>>>(end1_b, nullptr);
    k_gemm<2><<<BT_ / 128, 256, SMEM>>>(end2_b, out);
}

// round 7
// speedup vs baseline: 1.1989x; 1.1989x over previous
#include <cuda_runtime.h>
#include <cuda_bf16.h>
#include <stdint.h>
#include <math.h>

#define LAYERS_   10
#define NL_       40
#define RC_       32
#define DC_       32
#define SC_       256
#define EC_       256
#define CL_       256
#define B_        8
#define T_        16384
#define BT_       131072   /* B_*T_ */

typedef unsigned long long u64;

// ---------------- scratch (static device globals; no allocations) -------------
__device__ float g_h[32 * BT_];                       // residual state, [c][BT]
__device__ float g_z[167772160];                      // 40*32*BT, [layer][c][BT] (tf32-rounded)
__device__ float g_skip[SC_ * BT_];                   // [c][BT]  relu(skip), tf32-rounded
__device__ float g_out1[EC_ * BT_];                   // [c][BT]  relu(out1), tf32-rounded
__device__ float g_skipb[SC_];
__device__ unsigned g_wA[786432];                     // packed tf32 weights, K-major

#define WOFF_SKIP 0
#define WOFF_E1   655360
#define WOFF_E2   720896

// ---------------- small helpers ----------------
__device__ __forceinline__ unsigned f2tf(float x) {
    unsigned r;
    asm("cvt.rna.tf32.f32 %0, %1;" : "=r"(r) : "f"(x));
    return r;
}
__device__ __forceinline__ float rtf(float x) {      // RN-round to tf32, as float
    return __uint_as_float(f2tf(x));
}
__device__ __forceinline__ void mma8(float* d, const unsigned* a, const unsigned* b) {
    asm volatile(
        "mma.sync.aligned.m16n8k8.row.col.f32.tf32.tf32.f32 "
        "{%0,%1,%2,%3},{%4,%5,%6,%7},{%8,%9},{%0,%1,%2,%3};\n"
        : "+f"(d[0]), "+f"(d[1]), "+f"(d[2]), "+f"(d[3])
        : "r"(a[0]), "r"(a[1]), "r"(a[2]), "r"(a[3]), "r"(b[0]), "r"(b[1]));
}

// packed f32x2 fma: d.lo += a.lo*b.lo ; d.hi += a.hi*b.hi
__device__ __forceinline__ void fma2(u64& d, u64 a, u64 b) {
    asm("fma.rn.f32x2 %0, %1, %2, %0;" : "+l"(d) : "l"(a), "l"(b));
}
__device__ __forceinline__ u64 dup2(float x) {
    u64 r; unsigned xi = __float_as_uint(x);
    asm("mov.b64 %0, {%1, %1};" : "=l"(r) : "r"(xi));
    return r;
}
__device__ __forceinline__ float2 unpk(u64 v) {
    unsigned lo, hi;
    asm("mov.b64 {%0, %1}, %2;" : "=r"(lo), "=r"(hi) : "l"(v));
    return make_float2(__uint_as_float(lo), __uint_as_float(hi));
}
// 3-MUFU activation: tanh(f)*sigmoid(g), tf32-rounded
__device__ __forceinline__ float act_z(float fx, float gx) {
    float a = __expf(-2.f * fabsf(fx));   // EX2
    float b = __expf(-gx);                // EX2
    float den = (1.f + a) * (1.f + b);
    float r;
    asm("rcp.approx.f32 %0, %1;" : "=f"(r) : "f"(den));  // RCP
    return rtf(copysignf((1.f - a) * r, fx));
}

#define CP16(dst, src) asm volatile("cp.async.cg.shared.global [%0], [%1], 16;\n" :: "r"(dst), "l"(src))
#define CPCOMMIT()     asm volatile("cp.async.commit_group;\n")
#define CPWAIT1()      asm volatile("cp.async.wait_group 1;\n" ::: "memory")
#define CPWAIT0()      asm volatile("cp.async.wait_group 0;\n" ::: "memory")

// stage a 32ch x 256tok tile of `base` shifted by -d (causal zero-fill) into sdst[c*256+j]
__device__ __forceinline__ void stage_tile(float* sdst, const float* __restrict__ base,
                                           int t0, int d, int tid, int nthr) {
    if ((d & 3) == 0) {          // d==0 or multiple of 4: 16B chunks, chunkwise-uniform validity
#pragma unroll 4
        for (int q = tid; q < 2048; q += nthr) {
            int row = q >> 6, col = (q & 63) << 2;
            int g = t0 + col;
            bool v = (g & (T_ - 1)) >= d;
            const float* src = base + (size_t)row * BT_ + (v ? (g - d) : 0);
            uint32_t dst = (uint32_t)__cvta_generic_to_shared(sdst + row * 256 + col);
            asm volatile("cp.async.cg.shared.global [%0], [%1], 16, %2;\n"
                         :: "r"(dst), "l"(src), "r"(v ? 16u : 0u));
        }
    } else if (d == 2) {         // 8B chunks
#pragma unroll 4
        for (int q = tid; q < 4096; q += nthr) {
            int row = q >> 7, col = (q & 127) << 1;
            int g = t0 + col;
            bool v = (g & (T_ - 1)) >= 2;
            const float* src = base + (size_t)row * BT_ + (v ? (g - 2) : 0);
            uint32_t dst = (uint32_t)__cvta_generic_to_shared(sdst + row * 256 + col);
            asm volatile("cp.async.ca.shared.global [%0], [%1], 8, %2;\n"
                         :: "r"(dst), "l"(src), "r"(v ? 8u : 0u));
        }
    } else {                     // d==1: 4B
#pragma unroll 4
        for (int q = tid; q < 8192; q += nthr) {
            int row = q >> 8, col = q & 255;
            int g = t0 + col;
            bool v = (g & (T_ - 1)) >= 1;
            const float* src = base + (size_t)row * BT_ + (v ? (g - 1) : 0);
            uint32_t dst = (uint32_t)__cvta_generic_to_shared(sdst + row * 256 + col);
            asm volatile("cp.async.ca.shared.global [%0], [%1], 4, %2;\n"
                         :: "r"(dst), "l"(src), "r"(v ? 4u : 0u));
        }
    }
}

// ---------------- bias reduction for skip ----------------
__global__ void k_bias(const float* __restrict__ skip_b) {
    int o = threadIdx.x;
    float s = 0.f;
#pragma unroll 1
    for (int i = 0; i < NL_; i++) s += skip_b[i * SC_ + o];
    g_skipb[o] = s;
}

// ---------------- pack all GEMM weights K-major as tf32 ----------------
__global__ void k_pack(const float* __restrict__ skip_w,
                       const float* __restrict__ e1w,
                       const float* __restrict__ e2w) {
    int idx = blockIdx.x * 256 + threadIdx.x;
    if (idx < WOFF_E1) {
        int k = idx >> 8, m = idx & 255;
        int li = k >> 6, tap = (k >> 5) & 1, c = k & 31;
        g_wA[idx] = f2tf(skip_w[((size_t)(li * 256 + m) * 32 + c) * 2 + tap]);
    } else if (idx < WOFF_E2) {
        int local = idx - WOFF_E1;
        int k = local >> 8, m = local & 255;
        g_wA[idx] = f2tf(e1w[m * 256 + k]);
    } else if (idx < 786432) {
        int local = idx - WOFF_E2;
        int k = local >> 8, m = local & 255;
        g_wA[idx] = f2tf(e2w[m * 256 + k]);
    }
}

// ---------------- input 1x1 conv: x[8,256,16384] -> h[32][BT] ----------------
__global__ __launch_bounds__(256) void k_input(const float* __restrict__ x,
                                               const float* __restrict__ w_in,
                                               const float* __restrict__ b_in) {
    __shared__ float ws[256 * 32];   // [c][rc]
    __shared__ float bs[32];
    int tid = threadIdx.x;
    for (int e = tid; e < 256 * 32; e += 256) {
        int c = e >> 5, rc = e & 31;
        ws[e] = w_in[rc * 256 + c];
    }
    if (tid < 32) bs[tid] = b_in[tid];
    __syncthreads();

    int i0 = blockIdx.x * 512 + tid;
    int i1 = i0 + 256;
    int b0 = i0 >> 14, t0 = i0 & (T_ - 1);
    int b1 = i1 >> 14, t1 = i1 & (T_ - 1);
    const float* x0 = x + (size_t)b0 * 256 * T_ + t0;
    const float* x1 = x + (size_t)b1 * 256 * T_ + t1;

    float a0[32], a1[32];
#pragma unroll
    for (int r = 0; r < 32; r++) { a0[r] = bs[r]; a1[r] = bs[r]; }

#pragma unroll 1
    for (int c = 0; c < 256; c++) {
        float xv0 = x0[(size_t)c * T_];
        float xv1 = x1[(size_t)c * T_];
        const float* w = &ws[c * 32];
#pragma unroll
        for (int r = 0; r < 32; r++) {
            a0[r] = fmaf(w[r], xv0, a0[r]);
            a1[r] = fmaf(w[r], xv1, a1[r]);
        }
    }
#pragma unroll
    for (int r = 0; r < 32; r++) {
        g_h[r * BT_ + i0] = a0[r];
        g_h[r * BT_ + i1] = a1[r];
    }
}

// ---------------- per-layer z = tanh(filt)*sigmoid(gate), smem-staged --------
// CTA = 256 tokens; block 256 = 2 output-groups x 128 token-slots; 2 tok x 16 out/thread
// dyn smem: weights 4096f + biases 64f + hc 8192f + hp 8192f = 20544f = 82176 B
__global__ __launch_bounds__(256, 2) void k_z(const float* __restrict__ filt_w,
                                              const float* __restrict__ filt_b,
                                              const float* __restrict__ gate_w,
                                              const float* __restrict__ gate_b,
                                              int layer, int dil) {
    extern __shared__ float smz[];
    float* s_fw0 = smz;
    float* s_fw1 = smz + 1024;
    float* s_gw0 = smz + 2048;
    float* s_gw1 = smz + 3072;
    float* s_fb  = smz + 4096;
    float* s_gb  = smz + 4128;
    float* sHC   = smz + 4160;
    float* sHP   = smz + 12352;

    int tid = threadIdx.x;
    int t0 = blockIdx.x * 256;
    {
        const float* fwL = filt_w + layer * 2048;
        const float* gwL = gate_w + layer * 2048;
        for (int e = tid; e < 1024; e += 256) {
            int c = e >> 5, o = e & 31;
            int src = (o * 32 + c) * 2;
            s_fw0[c * 32 + o] = fwL[src];
            s_fw1[c * 32 + o] = fwL[src + 1];
            s_gw0[c * 32 + o] = gwL[src];
            s_gw1[c * 32 + o] = gwL[src + 1];
        }
        if (tid < 32) {
            s_fb[tid] = filt_b[layer * 32 + tid];
            s_gb[tid] = gate_b[layer * 32 + tid];
        }
    }
    stage_tile(sHC, g_h, t0, 0, tid, 256);
    stage_tile(sHP, g_h, t0, dil, tid, 256);
    CPCOMMIT();
    CPWAIT0();
    __syncthreads();

    int og = tid >> 7;          // 0..1
    int slot = tid & 127;
    int ob = og * 16;
    int i0 = t0 + slot * 2;

    u64 fa0[8], fa1[8], ga0[8], ga1[8];
#pragma unroll
    for (int p = 0; p < 8; p++) { fa0[p] = 0; fa1[p] = 0; ga0[p] = 0; ga1[p] = 0; }

#pragma unroll 8
    for (int c = 0; c < 32; c++) {
        float2 hc = *(const float2*)(sHC + c * 256 + slot * 2);
        float2 hp = *(const float2*)(sHP + c * 256 + slot * 2);
        u64 hcx = dup2(hc.x), hcy = dup2(hc.y);
        u64 hpx = dup2(hp.x), hpy = dup2(hp.y);

        const ulonglong2* wf0 = (const ulonglong2*)(s_fw0 + c * 32 + ob);
        const ulonglong2* wf1 = (const ulonglong2*)(s_fw1 + c * 32 + ob);
        const ulonglong2* wg0 = (const ulonglong2*)(s_gw0 + c * 32 + ob);
        const ulonglong2* wg1 = (const ulonglong2*)(s_gw1 + c * 32 + ob);
#pragma unroll
        for (int q = 0; q < 4; q++) {
            ulonglong2 f0 = wf0[q], f1 = wf1[q];
            fma2(fa0[2 * q], f0.x, hpx);     fma2(fa0[2 * q], f1.x, hcx);
            fma2(fa0[2 * q + 1], f0.y, hpx); fma2(fa0[2 * q + 1], f1.y, hcx);
            fma2(fa1[2 * q], f0.x, hpy);     fma2(fa1[2 * q], f1.x, hcy);
            fma2(fa1[2 * q + 1], f0.y, hpy); fma2(fa1[2 * q + 1], f1.y, hcy);
            ulonglong2 g0 = wg0[q], g1 = wg1[q];
            fma2(ga0[2 * q], g0.x, hpx);     fma2(ga0[2 * q], g1.x, hcx);
            fma2(ga0[2 * q + 1], g0.y, hpx); fma2(ga0[2 * q + 1], g1.y, hcx);
            fma2(ga1[2 * q], g0.x, hpy);     fma2(ga1[2 * q], g1.x, hcy);
            fma2(ga1[2 * q + 1], g0.y, hpy); fma2(ga1[2 * q + 1], g1.y, hcy);
        }
    }

    // epilogue: pair p covers outputs (ob+2p, ob+2p+1); fa0=token-lo, fa1=token-hi
#pragma unroll
    for (int p = 0; p < 8; p++) {
        int o0 = ob + 2 * p, o1 = o0 + 1;
        float2 fl = unpk(fa0[p]), fh = unpk(fa1[p]);
        float2 gl = unpk(ga0[p]), gh = unpk(ga1[p]);
        float fb0 = s_fb[o0], fb1 = s_fb[o1], gb0 = s_gb[o0], gb1 = s_gb[o1];
        float2 z0 = make_float2(act_z(fl.x + fb0, gl.x + gb0),
                                act_z(fh.x + fb0, gh.x + gb0));
        float2 z1 = make_float2(act_z(fl.y + fb1, gl.y + gb1),
                                act_z(fh.y + fb1, gh.y + gb1));
        *(float2*)(g_z + ((size_t)layer * 32 + o0) * BT_ + i0) = z0;
        *(float2*)(g_z + ((size_t)layer * 32 + o1) * BT_ + i0) = z1;
    }
}

// ---------------- per-layer residual update, smem-staged ---------------------
// CTA = 256 tokens; block 128; thread = 2 tok x 32 outputs
// dyn smem: weights 2048f + bias 32f + zc 8192f + zp 8192f = 18464f = 73856 B
__global__ __launch_bounds__(128, 3) void k_res(const float* __restrict__ res_w,
                                                const float* __restrict__ res_b,
                                                int layer, int dil) {
    extern __shared__ float smr[];
    float* s_w0 = smr;
    float* s_w1 = smr + 1024;
    float* s_b  = smr + 2048;
    float* sZC  = smr + 2080;
    float* sZP  = smr + 10272;

    int tid = threadIdx.x;
    int t0 = blockIdx.x * 256;
    const float* zL = g_z + (size_t)layer * 32 * BT_;
    {
        const float* wL = res_w + layer * 2048;
        for (int e = tid; e < 1024; e += 128) {
            int c = e >> 5, o = e & 31;
            int src = (o * 32 + c) * 2;
            s_w0[c * 32 + o] = wL[src];
            s_w1[c * 32 + o] = wL[src + 1];
        }
        if (tid < 32) s_b[tid] = res_b[layer * 32 + tid];
    }
    stage_tile(sZC, zL, t0, 0, tid, 128);
    stage_tile(sZP, zL, t0, dil, tid, 128);
    CPCOMMIT();
    CPWAIT0();
    __syncthreads();

    int slot = tid;             // 0..127
    int i0 = t0 + slot * 2;

    u64 a0[16], a1[16];
#pragma unroll
    for (int p = 0; p < 16; p++) { a0[p] = 0; a1[p] = 0; }

#pragma unroll 8
    for (int c = 0; c < 32; c++) {
        float2 zc = *(const float2*)(sZC + c * 256 + slot * 2);
        float2 zp = *(const float2*)(sZP + c * 256 + slot * 2);
        u64 zcx = dup2(zc.x), zcy = dup2(zc.y);
        u64 zpx = dup2(zp.x), zpy = dup2(zp.y);

        const ulonglong2* w0 = (const ulonglong2*)(s_w0 + c * 32);
        const ulonglong2* w1 = (const ulonglong2*)(s_w1 + c * 32);
#pragma unroll
        for (int q = 0; q < 8; q++) {
            ulonglong2 v0 = w0[q], v1 = w1[q];
            fma2(a0[2 * q], v0.x, zpx);     fma2(a0[2 * q], v1.x, zcx);
            fma2(a0[2 * q + 1], v0.y, zpx); fma2(a0[2 * q + 1], v1.y, zcx);
            fma2(a1[2 * q], v0.x, zpy);     fma2(a1[2 * q], v1.x, zcy);
            fma2(a1[2 * q + 1], v0.y, zpy); fma2(a1[2 * q + 1], v1.y, zcy);
        }
    }

#pragma unroll
    for (int p = 0; p < 16; p++) {
        int o0 = 2 * p, o1 = o0 + 1;
        float2 vl = unpk(a0[p]);  // (o0 lo, o1 lo)
        float2 vh = unpk(a1[p]);  // (o0 hi, o1 hi)
        float b0 = s_b[o0], b1 = s_b[o1];
        float* r0 = g_h + (size_t)o0 * BT_ + i0;
        float* r1 = g_h + (size_t)o1 * BT_ + i0;
        float2 h0 = *(const float2*)r0;
        float2 h1 = *(const float2*)r1;
        h0.x += vl.x + b0; h0.y += vh.x + b0;
        h1.x += vl.y + b1; h1.y += vh.y + b1;
        *(float2*)r0 = h0;
        *(float2*)r1 = h1;
    }
}

// ================== unified tf32 GEMM (cp.async staged, double buffered) =====
#define SAS 264
#define SBS 136
#define BUFW 12800

template <int MODE>
__device__ __forceinline__ void stage_step(unsigned* sm, int buf, int s, int t0, int tid) {
    unsigned* sA = sm + buf * BUFW;
    unsigned* sB = sm + buf * BUFW + 32 * SAS;
    const unsigned* asrc = g_wA + (MODE == 0 ? WOFF_SKIP : (MODE == 1 ? WOFF_E1 : WOFF_E2))
                         + (size_t)s * 32 * 256;
#pragma unroll
    for (int i = 0; i < 8; i++) {
        int q = tid + i * 256;
        int row = q >> 6, col = (q & 63) * 4;
        uint32_t dst = (uint32_t)__cvta_generic_to_shared(sA + row * SAS + col);
        CP16(dst, asrc + row * 256 + col);
    }
    if (MODE != 0) {
        const float* gB = (MODE == 1) ? g_skip : g_out1;
#pragma unroll
        for (int i = 0; i < 4; i++) {
            int q = tid + i * 256;
            int row = q >> 5, col = (q & 31) * 4;
            uint32_t dst = (uint32_t)__cvta_generic_to_shared(sB + row * SBS + col);
            CP16(dst, gB + (size_t)(s * 32 + row) * BT_ + t0 + col);
        }
    } else {
        int li = s >> 1, tap = s & 1;
        int d = 1 << (li % LAYERS_);
        int j = tid >> 3, l8 = tid & 7;
        const float* zrow = g_z + ((size_t)li * 32 + j) * BT_;
        if (tap == 1) {
#pragma unroll
            for (int i = 0; i < 4; i++) {
                int q = l8 + i * 8;
                uint32_t dst = (uint32_t)__cvta_generic_to_shared(sB + j * SBS + q * 4);
                CP16(dst, zrow + t0 + q * 4);
            }
        } else {
            int r = (4 - (d & 3)) & 3;
            int t0m = t0 & (T_ - 1);
            if (t0m >= d + 4) {
                const float* src = zrow + t0 - d - r;
#pragma unroll
                for (int i = 0; i < 4; i++) {
                    int q = l8 + i * 8;
                    uint32_t dst = (uint32_t)__cvta_generic_to_shared(sB + j * SBS + q * 4);
                    CP16(dst, src + q * 4);
                }
                if (l8 == 0) {
                    uint32_t dst = (uint32_t)__cvta_generic_to_shared(sB + j * SBS + 128);
                    CP16(dst, src + 128);
                }
            } else {
                for (int t = l8; t < 128; t += 8) {
                    int gm = t0 + t;
                    float v = ((gm & (T_ - 1)) >= d) ? zrow[gm - d] : 0.f;
                    sB[j * SBS + r + t] = __float_as_uint(v);
                }
            }
        }
    }
}

template <int MODE>
__global__ __launch_bounds__(256) void k_gemm(const float* __restrict__ bias,
                                              float* __restrict__ dout) {
    extern __shared__ unsigned sm[];
    constexpr int KS = (MODE == 0) ? 80 : 8;
    int tid = threadIdx.x, warp = tid >> 5, lane = tid & 31;
    int grp = lane >> 2, tig = lane & 3;
    int t0 = blockIdx.x * 128;
    int m_off = (warp >> 1) * 64;
    int n_off = (warp & 1) * 64;

    float acc[4][8][4];
#pragma unroll
    for (int mf = 0; mf < 4; mf++)
#pragma unroll
        for (int nf = 0; nf < 8; nf++)
#pragma unroll
            for (int q = 0; q < 4; q++) acc[mf][nf][q] = 0.f;

    stage_step<MODE>(sm, 0, 0, t0, tid);
    CPCOMMIT();

    int buf = 0;
#pragma unroll 1
    for (int s = 0; s < KS; s++) {
        if (s + 1 < KS) {
            stage_step<MODE>(sm, buf ^ 1, s + 1, t0, tid);
            CPCOMMIT();
            CPWAIT1();
        } else {
            CPWAIT0();
        }
        __syncthreads();

        unsigned* sA = sm + buf * BUFW;
        unsigned* sB = sm + buf * BUFW + 32 * SAS;
        int roff = 0;
        if (MODE == 0 && !(s & 1)) {
            int d = 1 << ((s >> 1) % LAYERS_);
            roff = (4 - (d & 3)) & 3;
        }
#pragma unroll
        for (int kc = 0; kc < 32; kc += 8) {
            unsigned a[4][4], b[8][2];
#pragma unroll
            for (int mf = 0; mf < 4; mf++) {
                int r0 = m_off + mf * 16 + grp;
                a[mf][0] = sA[(kc + tig) * SAS + r0];
                a[mf][1] = sA[(kc + tig) * SAS + r0 + 8];
                a[mf][2] = sA[(kc + tig + 4) * SAS + r0];
                a[mf][3] = sA[(kc + tig + 4) * SAS + r0 + 8];
            }
#pragma unroll
            for (int nf = 0; nf < 8; nf++) {
                int ci = n_off + nf * 8 + grp + roff;
                b[nf][0] = sB[(kc + tig) * SBS + ci];
                b[nf][1] = sB[(kc + tig + 4) * SBS + ci];
            }
#pragma unroll
            for (int mf = 0; mf < 4; mf++)
#pragma unroll
                for (int nf = 0; nf < 8; nf++) mma8(acc[mf][nf], a[mf], b[nf]);
        }
        __syncthreads();
        buf ^= 1;
    }

    const float* bp = (MODE == 0) ? g_skipb : bias;

    if (MODE != 2) {
        float* out = (MODE == 0) ? g_skip : g_out1;
#pragma unroll
        for (int mf = 0; mf < 4; mf++)
#pragma unroll
            for (int nf = 0; nf < 8; nf++) {
                int row0 = m_off + mf * 16 + grp;
                int col = t0 + n_off + nf * 8 + 2 * tig;
                float b0 = bp[row0];
                float b1 = bp[row0 + 8];
                float2 v0 = make_float2(rtf(fmaxf(acc[mf][nf][0] + b0, 0.f)),
                                        rtf(fmaxf(acc[mf][nf][1] + b0, 0.f)));
                float2 v1 = make_float2(rtf(fmaxf(acc[mf][nf][2] + b1, 0.f)),
                                        rtf(fmaxf(acc[mf][nf][3] + b1, 0.f)));
                *(float2*)&out[(size_t)row0 * BT_ + col] = v0;
                *(float2*)&out[(size_t)(row0 + 8) * BT_ + col] = v1;
            }
    } else {
        float* ts = (float*)sm;  // [64 tok][260]
#pragma unroll 1
        for (int h = 0; h < 2; h++) {
            __syncthreads();
            if ((warp & 1) == h) {
#pragma unroll
                for (int mf = 0; mf < 4; mf++)
#pragma unroll
                    for (int nf = 0; nf < 8; nf++) {
                        int rowL = m_off + mf * 16 + grp;
                        int colL = nf * 8 + 2 * tig;  // 0..63
                        float b0 = bp[rowL];
                        float b1 = bp[rowL + 8];
                        ts[colL * 260 + rowL] = acc[mf][nf][0] + b0;
                        ts[(colL + 1) * 260 + rowL] = acc[mf][nf][1] + b0;
                        ts[colL * 260 + rowL + 8] = acc[mf][nf][2] + b1;
                        ts[(colL + 1) * 260 + rowL + 8] = acc[mf][nf][3] + b1;
                    }
            }
            __syncthreads();
#pragma unroll
            for (int i = 0; i < 16; i++) {
                int q = tid + i * 256;
                int tk = q >> 6, c4 = (q & 63) * 4;
                float4 v = *(const float4*)&ts[tk * 260 + c4];
                *(float4*)&dout[(size_t)(t0 + h * 64 + tk) * 256 + c4] = v;
            }
        }
    }
}

// ---------------- host launcher ----------------
extern "C" void kernel_launch(void* const* d_in, const int* in_sizes, int n_in,
                              void* d_out, int out_size) {
    const float* x      = (const float*)d_in[0];
    const float* w_in   = (const float*)d_in[1];
    const float* b_in   = (const float*)d_in[2];
    const float* filt_w = (const float*)d_in[3];
    const float* filt_b = (const float*)d_in[4];
    const float* gate_w = (const float*)d_in[5];
    const float* gate_b = (const float*)d_in[6];
    const float* res_w  = (const float*)d_in[7];
    const float* res_b  = (const float*)d_in[8];
    const float* skip_w = (const float*)d_in[9];
    const float* skip_b = (const float*)d_in[10];
    const float* end1_w = (const float*)d_in[11];
    const float* end1_b = (const float*)d_in[12];
    const float* end2_w = (const float*)d_in[13];
    const float* end2_b = (const float*)d_in[14];
    float* out = (float*)d_out;

    const int SMEM  = 25600 * 4;   // GEMM: 102,400 B dynamic
    const int SMZ   = 20544 * 4;   // k_z : 82,176 B
    const int SMR   = 18464 * 4;   // k_res: 73,856 B
    cudaFuncSetAttribute(k_gemm<0>, cudaFuncAttributeMaxDynamicSharedMemorySize, SMEM);
    cudaFuncSetAttribute(k_gemm<1>, cudaFuncAttributeMaxDynamicSharedMemorySize, SMEM);
    cudaFuncSetAttribute(k_gemm<2>, cudaFuncAttributeMaxDynamicSharedMemorySize, SMEM);
    cudaFuncSetAttribute(k_z,   cudaFuncAttributeMaxDynamicSharedMemorySize, SMZ);
    cudaFuncSetAttribute(k_res, cudaFuncAttributeMaxDynamicSharedMemorySize, SMR);

    k_bias<<<1, 256>>>(skip_b);
    k_pack<<<3072, 256>>>(skip_w, end1_w, end2_w);
    k_input<<<BT_ / 512, 256>>>(x, w_in, b_in);

    for (int i = 0; i < NL_; i++) {
        int d = 1 << (i % LAYERS_);
        k_z<<<BT_ / 256, 256, SMZ>>>(filt_w, filt_b, gate_w, gate_b, i, d);
        k_res<<<BT_ / 256, 128, SMR>>>(res_w, res_b, i, d);
    }

    k_gemm<0><<<BT_ / 128, 256, SMEM>>>(nullptr, nullptr);
    k_gemm<1><<<BT_ / 128, 256, SMEM>>>(end1_b, nullptr);
    k_gemm<2><<<BT_ / 128, 256, SMEM>>>(end2_b, out);
}

// round 8
// speedup vs baseline: 1.2249x; 1.0217x over previous
#include <cuda_runtime.h>
#include <cuda_bf16.h>
#include <stdint.h>
#include <math.h>

#define LAYERS_   10
#define NL_       40
#define RC_       32
#define DC_       32
#define SC_       256
#define EC_       256
#define CL_       256
#define B_        8
#define T_        16384
#define BT_       131072   /* B_*T_ */

typedef unsigned long long u64;

// ---------------- scratch (static device globals; no allocations) -------------
__device__ float g_h[32 * BT_];                       // residual state, [c][BT]
__device__ float g_z[167772160];                      // 40*32*BT, [layer][c][BT] (tf32-rounded)
__device__ float g_skip[SC_ * BT_];                   // [c][BT]  relu(skip), tf32-rounded
__device__ float g_out1[EC_ * BT_];                   // [c][BT]  relu(out1), tf32-rounded
__device__ float g_skipb[SC_];
__device__ unsigned g_wA[786432];                     // packed tf32 weights, K-major

#define WOFF_SKIP 0
#define WOFF_E1   655360
#define WOFF_E2   720896

// ---------------- small helpers ----------------
__device__ __forceinline__ unsigned f2tf(float x) {
    unsigned r;
    asm("cvt.rna.tf32.f32 %0, %1;" : "=r"(r) : "f"(x));
    return r;
}
__device__ __forceinline__ float rtf(float x) {      // RN-round to tf32, as float
    return __uint_as_float(f2tf(x));
}
__device__ __forceinline__ void mma8(float* d, const unsigned* a, const unsigned* b) {
    asm volatile(
        "mma.sync.aligned.m16n8k8.row.col.f32.tf32.tf32.f32 "
        "{%0,%1,%2,%3},{%4,%5,%6,%7},{%8,%9},{%0,%1,%2,%3};\n"
        : "+f"(d[0]), "+f"(d[1]), "+f"(d[2]), "+f"(d[3])
        : "r"(a[0]), "r"(a[1]), "r"(a[2]), "r"(a[3]), "r"(b[0]), "r"(b[1]));
}

// packed f32x2 fma: d.lo += a.lo*b.lo ; d.hi += a.hi*b.hi
__device__ __forceinline__ void fma2(u64& d, u64 a, u64 b) {
    asm("fma.rn.f32x2 %0, %1, %2, %0;" : "+l"(d) : "l"(a), "l"(b));
}
__device__ __forceinline__ u64 dup2(float x) {
    u64 r; unsigned xi = __float_as_uint(x);
    asm("mov.b64 %0, {%1, %1};" : "=l"(r) : "r"(xi));
    return r;
}
__device__ __forceinline__ float2 unpk(u64 v) {
    unsigned lo, hi;
    asm("mov.b64 {%0, %1}, %2;" : "=r"(lo), "=r"(hi) : "l"(v));
    return make_float2(__uint_as_float(lo), __uint_as_float(hi));
}
// 3-MUFU activation: tanh(f)*sigmoid(g), tf32-rounded
__device__ __forceinline__ float act_z(float fx, float gx) {
    float a = __expf(-2.f * fabsf(fx));   // EX2
    float b = __expf(-gx);                // EX2
    float den = (1.f + a) * (1.f + b);
    float r;
    asm("rcp.approx.f32 %0, %1;" : "=f"(r) : "f"(den));  // RCP
    return rtf(copysignf((1.f - a) * r, fx));
}

#define CP16(dst, src) asm volatile("cp.async.cg.shared.global [%0], [%1], 16;\n" :: "r"(dst), "l"(src))
#define CPCOMMIT()     asm volatile("cp.async.commit_group;\n")
#define CPWAIT1()      asm volatile("cp.async.wait_group 1;\n" ::: "memory")
#define CPWAIT0()      asm volatile("cp.async.wait_group 0;\n" ::: "memory")

// stage channels [c0,c1) of a 256-token tile of `base` shifted by -d (causal
// zero-fill) into sdst[c*256+j]
__device__ __forceinline__ void stage_tile(float* sdst, const float* __restrict__ base,
                                           int t0, int d, int tid, int nthr,
                                           int c0, int c1) {
    int nrow = c1 - c0;
    if ((d & 3) == 0) {          // d==0 or multiple of 4: 16B chunks
#pragma unroll 4
        for (int q = tid; q < nrow * 64; q += nthr) {
            int row = c0 + (q >> 6), col = (q & 63) << 2;
            int g = t0 + col;
            bool v = (g & (T_ - 1)) >= d;
            const float* src = base + (size_t)row * BT_ + (v ? (g - d) : 0);
            uint32_t dst = (uint32_t)__cvta_generic_to_shared(sdst + row * 256 + col);
            asm volatile("cp.async.cg.shared.global [%0], [%1], 16, %2;\n"
                         :: "r"(dst), "l"(src), "r"(v ? 16u : 0u));
        }
    } else if (d == 2) {         // 8B chunks
#pragma unroll 4
        for (int q = tid; q < nrow * 128; q += nthr) {
            int row = c0 + (q >> 7), col = (q & 127) << 1;
            int g = t0 + col;
            bool v = (g & (T_ - 1)) >= 2;
            const float* src = base + (size_t)row * BT_ + (v ? (g - 2) : 0);
            uint32_t dst = (uint32_t)__cvta_generic_to_shared(sdst + row * 256 + col);
            asm volatile("cp.async.ca.shared.global [%0], [%1], 8, %2;\n"
                         :: "r"(dst), "l"(src), "r"(v ? 8u : 0u));
        }
    } else {                     // d==1: 4B
#pragma unroll 4
        for (int q = tid; q < nrow * 256; q += nthr) {
            int row = c0 + (q >> 8), col = q & 255;
            int g = t0 + col;
            bool v = (g & (T_ - 1)) >= 1;
            const float* src = base + (size_t)row * BT_ + (v ? (g - 1) : 0);
            uint32_t dst = (uint32_t)__cvta_generic_to_shared(sdst + row * 256 + col);
            asm volatile("cp.async.ca.shared.global [%0], [%1], 4, %2;\n"
                         :: "r"(dst), "l"(src), "r"(v ? 4u : 0u));
        }
    }
}

// ---------------- bias reduction for skip ----------------
__global__ void k_bias(const float* __restrict__ skip_b) {
    int o = threadIdx.x;
    float s = 0.f;
#pragma unroll 1
    for (int i = 0; i < NL_; i++) s += skip_b[i * SC_ + o];
    g_skipb[o] = s;
}

// ---------------- pack all GEMM weights K-major as tf32 ----------------
__global__ void k_pack(const float* __restrict__ skip_w,
                       const float* __restrict__ e1w,
                       const float* __restrict__ e2w) {
    int idx = blockIdx.x * 256 + threadIdx.x;
    if (idx < WOFF_E1) {
        int k = idx >> 8, m = idx & 255;
        int li = k >> 6, tap = (k >> 5) & 1, c = k & 31;
        g_wA[idx] = f2tf(skip_w[((size_t)(li * 256 + m) * 32 + c) * 2 + tap]);
    } else if (idx < WOFF_E2) {
        int local = idx - WOFF_E1;
        int k = local >> 8, m = local & 255;
        g_wA[idx] = f2tf(e1w[m * 256 + k]);
    } else if (idx < 786432) {
        int local = idx - WOFF_E2;
        int k = local >> 8, m = local & 255;
        g_wA[idx] = f2tf(e2w[m * 256 + k]);
    }
}

// ---------------- input 1x1 conv: x[8,256,16384] -> h[32][BT] ----------------
__global__ __launch_bounds__(256) void k_input(const float* __restrict__ x,
                                               const float* __restrict__ w_in,
                                               const float* __restrict__ b_in) {
    __shared__ float ws[256 * 32];   // [c][rc]
    __shared__ float bs[32];
    int tid = threadIdx.x;
    for (int e = tid; e < 256 * 32; e += 256) {
        int c = e >> 5, rc = e & 31;
        ws[e] = w_in[rc * 256 + c];
    }
    if (tid < 32) bs[tid] = b_in[tid];
    __syncthreads();

    int i0 = blockIdx.x * 512 + tid;
    int i1 = i0 + 256;
    int b0 = i0 >> 14, t0 = i0 & (T_ - 1);
    int b1 = i1 >> 14, t1 = i1 & (T_ - 1);
    const float* x0 = x + (size_t)b0 * 256 * T_ + t0;
    const float* x1 = x + (size_t)b1 * 256 * T_ + t1;

    float a0[32], a1[32];
#pragma unroll
    for (int r = 0; r < 32; r++) { a0[r] = bs[r]; a1[r] = bs[r]; }

#pragma unroll 1
    for (int c = 0; c < 256; c++) {
        float xv0 = x0[(size_t)c * T_];
        float xv1 = x1[(size_t)c * T_];
        const float* w = &ws[c * 32];
#pragma unroll
        for (int r = 0; r < 32; r++) {
            a0[r] = fmaf(w[r], xv0, a0[r]);
            a1[r] = fmaf(w[r], xv1, a1[r]);
        }
    }
#pragma unroll
    for (int r = 0; r < 32; r++) {
        g_h[r * BT_ + i0] = a0[r];
        g_h[r * BT_ + i1] = a1[r];
    }
}

// ---------------- per-layer z = tanh(filt)*sigmoid(gate), smem-staged --------
// CTA = 256 tokens; block 256 = 2 output-groups x 128 token-slots; 2 tok x 16 out/thread
// dyn smem: weights 4096f + biases 64f + hc 8192f + hp 8192f = 20544f = 82176 B
__global__ __launch_bounds__(256, 2) void k_z(const float* __restrict__ filt_w,
                                              const float* __restrict__ filt_b,
                                              const float* __restrict__ gate_w,
                                              const float* __restrict__ gate_b,
                                              int layer, int dil) {
    extern __shared__ float smz[];
    float* s_fw0 = smz;
    float* s_fw1 = smz + 1024;
    float* s_gw0 = smz + 2048;
    float* s_gw1 = smz + 3072;
    float* s_fb  = smz + 4096;
    float* s_gb  = smz + 4128;
    float* sHC   = smz + 4160;
    float* sHP   = smz + 12352;

    int tid = threadIdx.x;
    int t0 = blockIdx.x * 256;

    // split-half staging: [0,16) group, [16,32) group
    stage_tile(sHC, g_h, t0, 0, tid, 256, 0, 16);
    stage_tile(sHP, g_h, t0, dil, tid, 256, 0, 16);
    CPCOMMIT();
    stage_tile(sHC, g_h, t0, 0, tid, 256, 16, 32);
    stage_tile(sHP, g_h, t0, dil, tid, 256, 16, 32);
    CPCOMMIT();

    {
        const float* fwL = filt_w + layer * 2048;
        const float* gwL = gate_w + layer * 2048;
        for (int e = tid; e < 1024; e += 256) {
            int c = e >> 5, o = e & 31;
            int src = (o * 32 + c) * 2;
            s_fw0[c * 32 + o] = fwL[src];
            s_fw1[c * 32 + o] = fwL[src + 1];
            s_gw0[c * 32 + o] = gwL[src];
            s_gw1[c * 32 + o] = gwL[src + 1];
        }
        if (tid < 32) {
            s_fb[tid] = filt_b[layer * 32 + tid];
            s_gb[tid] = gate_b[layer * 32 + tid];
        }
    }

    int og = tid >> 7;          // 0..1
    int slot = tid & 127;
    int ob = og * 16;
    int i0 = t0 + slot * 2;

    u64 fa0[8], fa1[8], ga0[8], ga1[8];
#pragma unroll
    for (int p = 0; p < 8; p++) { fa0[p] = 0; fa1[p] = 0; ga0[p] = 0; ga1[p] = 0; }

    CPWAIT1();
    __syncthreads();

#pragma unroll 1
    for (int half = 0; half < 2; half++) {
        int cbeg = half * 16;
#pragma unroll 8
        for (int ci = 0; ci < 16; ci++) {
            int c = cbeg + ci;
            float2 hc = *(const float2*)(sHC + c * 256 + slot * 2);
            float2 hp = *(const float2*)(sHP + c * 256 + slot * 2);
            u64 hcx = dup2(hc.x), hcy = dup2(hc.y);
            u64 hpx = dup2(hp.x), hpy = dup2(hp.y);

            const ulonglong2* wf0 = (const ulonglong2*)(s_fw0 + c * 32 + ob);
            const ulonglong2* wf1 = (const ulonglong2*)(s_fw1 + c * 32 + ob);
            const ulonglong2* wg0 = (const ulonglong2*)(s_gw0 + c * 32 + ob);
            const ulonglong2* wg1 = (const ulonglong2*)(s_gw1 + c * 32 + ob);
#pragma unroll
            for (int q = 0; q < 4; q++) {
                ulonglong2 f0 = wf0[q], f1 = wf1[q];
                fma2(fa0[2 * q], f0.x, hpx);     fma2(fa0[2 * q], f1.x, hcx);
                fma2(fa0[2 * q + 1], f0.y, hpx); fma2(fa0[2 * q + 1], f1.y, hcx);
                fma2(fa1[2 * q], f0.x, hpy);     fma2(fa1[2 * q], f1.x, hcy);
                fma2(fa1[2 * q + 1], f0.y, hpy); fma2(fa1[2 * q + 1], f1.y, hcy);
                ulonglong2 g0 = wg0[q], g1 = wg1[q];
                fma2(ga0[2 * q], g0.x, hpx);     fma2(ga0[2 * q], g1.x, hcx);
                fma2(ga0[2 * q + 1], g0.y, hpx); fma2(ga0[2 * q + 1], g1.y, hcx);
                fma2(ga1[2 * q], g0.x, hpy);     fma2(ga1[2 * q], g1.x, hcy);
                fma2(ga1[2 * q + 1], g0.y, hpy); fma2(ga1[2 * q + 1], g1.y, hcy);
            }
        }
        if (half == 0) {
            CPWAIT0();
            __syncthreads();
        }
    }

    // epilogue: pair p covers outputs (ob+2p, ob+2p+1); fa0=token-lo, fa1=token-hi
#pragma unroll
    for (int p = 0; p < 8; p++) {
        int o0 = ob + 2 * p, o1 = o0 + 1;
        float2 fl = unpk(fa0[p]), fh = unpk(fa1[p]);
        float2 gl = unpk(ga0[p]), gh = unpk(ga1[p]);
        float fb0 = s_fb[o0], fb1 = s_fb[o1], gb0 = s_gb[o0], gb1 = s_gb[o1];
        float2 z0 = make_float2(act_z(fl.x + fb0, gl.x + gb0),
                                act_z(fh.x + fb0, gh.x + gb0));
        float2 z1 = make_float2(act_z(fl.y + fb1, gl.y + gb1),
                                act_z(fh.y + fb1, gh.y + gb1));
        *(float2*)(g_z + ((size_t)layer * 32 + o0) * BT_ + i0) = z0;
        *(float2*)(g_z + ((size_t)layer * 32 + o1) * BT_ + i0) = z1;
    }
}

// ---------------- per-layer residual update, smem-staged ---------------------
// CTA = 256 tokens; block 256 = 2 output-groups x 128 slots; 2 tok x 16 out/thread
// dyn smem: weights 2048f + bias 32f + zc 8192f + zp 8192f = 18464f = 73856 B
__global__ __launch_bounds__(256, 2) void k_res(const float* __restrict__ res_w,
                                                const float* __restrict__ res_b,
                                                int layer, int dil) {
    extern __shared__ float smr[];
    float* s_w0 = smr;
    float* s_w1 = smr + 1024;
    float* s_b  = smr + 2048;
    float* sZC  = smr + 2080;
    float* sZP  = smr + 10272;

    int tid = threadIdx.x;
    int t0 = blockIdx.x * 256;
    const float* zL = g_z + (size_t)layer * 32 * BT_;

    stage_tile(sZC, zL, t0, 0, tid, 256, 0, 16);
    stage_tile(sZP, zL, t0, dil, tid, 256, 0, 16);
    CPCOMMIT();
    stage_tile(sZC, zL, t0, 0, tid, 256, 16, 32);
    stage_tile(sZP, zL, t0, dil, tid, 256, 16, 32);
    CPCOMMIT();

    {
        const float* wL = res_w + layer * 2048;
        for (int e = tid; e < 1024; e += 256) {
            int c = e >> 5, o = e & 31;
            int src = (o * 32 + c) * 2;
            s_w0[c * 32 + o] = wL[src];
            s_w1[c * 32 + o] = wL[src + 1];
        }
        if (tid < 32) s_b[tid] = res_b[layer * 32 + tid];
    }

    int og = tid >> 7;          // 0..1
    int slot = tid & 127;
    int ob = og * 16;
    int i0 = t0 + slot * 2;

    u64 a0[8], a1[8];
#pragma unroll
    for (int p = 0; p < 8; p++) { a0[p] = 0; a1[p] = 0; }

    CPWAIT1();
    __syncthreads();

#pragma unroll 1
    for (int half = 0; half < 2; half++) {
        int cbeg = half * 16;
#pragma unroll 8
        for (int ci = 0; ci < 16; ci++) {
            int c = cbeg + ci;
            float2 zc = *(const float2*)(sZC + c * 256 + slot * 2);
            float2 zp = *(const float2*)(sZP + c * 256 + slot * 2);
            u64 zcx = dup2(zc.x), zcy = dup2(zc.y);
            u64 zpx = dup2(zp.x), zpy = dup2(zp.y);

            const ulonglong2* w0 = (const ulonglong2*)(s_w0 + c * 32 + ob);
            const ulonglong2* w1 = (const ulonglong2*)(s_w1 + c * 32 + ob);
#pragma unroll
            for (int q = 0; q < 4; q++) {
                ulonglong2 v0 = w0[q], v1 = w1[q];
                fma2(a0[2 * q], v0.x, zpx);     fma2(a0[2 * q], v1.x, zcx);
                fma2(a0[2 * q + 1], v0.y, zpx); fma2(a0[2 * q + 1], v1.y, zcx);
                fma2(a1[2 * q], v0.x, zpy);     fma2(a1[2 * q], v1.x, zcy);
                fma2(a1[2 * q + 1], v0.y, zpy); fma2(a1[2 * q + 1], v1.y, zcy);
            }
        }
        if (half == 0) {
            CPWAIT0();
            __syncthreads();
        }
    }

#pragma unroll
    for (int p = 0; p < 8; p++) {
        int o0 = ob + 2 * p, o1 = o0 + 1;
        float2 vl = unpk(a0[p]);  // (o0 lo, o1 lo)
        float2 vh = unpk(a1[p]);  // (o0 hi, o1 hi)
        float b0 = s_b[o0], b1 = s_b[o1];
        float* r0 = g_h + (size_t)o0 * BT_ + i0;
        float* r1 = g_h + (size_t)o1 * BT_ + i0;
        float2 h0 = *(const float2*)r0;
        float2 h1 = *(const float2*)r1;
        h0.x += vl.x + b0; h0.y += vh.x + b0;
        h1.x += vl.y + b1; h1.y += vh.y + b1;
        *(float2*)r0 = h0;
        *(float2*)r1 = h1;
    }
}

// ================== unified tf32 GEMM (cp.async staged, double buffered) =====
#define SAS 264
#define SBS 136
#define BUFW 12800

template <int MODE>
__device__ __forceinline__ void stage_step(unsigned* sm, int buf, int s, int t0, int tid) {
    unsigned* sA = sm + buf * BUFW;
    unsigned* sB = sm + buf * BUFW + 32 * SAS;
    const unsigned* asrc = g_wA + (MODE == 0 ? WOFF_SKIP : (MODE == 1 ? WOFF_E1 : WOFF_E2))
                         + (size_t)s * 32 * 256;
#pragma unroll
    for (int i = 0; i < 8; i++) {
        int q = tid + i * 256;
        int row = q >> 6, col = (q & 63) * 4;
        uint32_t dst = (uint32_t)__cvta_generic_to_shared(sA + row * SAS + col);
        CP16(dst, asrc + row * 256 + col);
    }
    if (MODE != 0) {
        const float* gB = (MODE == 1) ? g_skip : g_out1;
#pragma unroll
        for (int i = 0; i < 4; i++) {
            int q = tid + i * 256;
            int row = q >> 5, col = (q & 31) * 4;
            uint32_t dst = (uint32_t)__cvta_generic_to_shared(sB + row * SBS + col);
            CP16(dst, gB + (size_t)(s * 32 + row) * BT_ + t0 + col);
        }
    } else {
        int li = s >> 1, tap = s & 1;
        int d = 1 << (li % LAYERS_);
        int j = tid >> 3, l8 = tid & 7;
        const float* zrow = g_z + ((size_t)li * 32 + j) * BT_;
        if (tap == 1) {
#pragma unroll
            for (int i = 0; i < 4; i++) {
                int q = l8 + i * 8;
                uint32_t dst = (uint32_t)__cvta_generic_to_shared(sB + j * SBS + q * 4);
                CP16(dst, zrow + t0 + q * 4);
            }
        } else {
            int r = (4 - (d & 3)) & 3;
            int t0m = t0 & (T_ - 1);
            if (t0m >= d + 4) {
                const float* src = zrow + t0 - d - r;
#pragma unroll
                for (int i = 0; i < 4; i++) {
                    int q = l8 + i * 8;
                    uint32_t dst = (uint32_t)__cvta_generic_to_shared(sB + j * SBS + q * 4);
                    CP16(dst, src + q * 4);
                }
                if (l8 == 0) {
                    uint32_t dst = (uint32_t)__cvta_generic_to_shared(sB + j * SBS + 128);
                    CP16(dst, src + 128);
                }
            } else {
                for (int t = l8; t < 128; t += 8) {
                    int gm = t0 + t;
                    float v = ((gm & (T_ - 1)) >= d) ? zrow[gm - d] : 0.f;
                    sB[j * SBS + r + t] = __float_as_uint(v);
                }
            }
        }
    }
}

template <int MODE>
__global__ __launch_bounds__(256) void k_gemm(const float* __restrict__ bias,
                                              float* __restrict__ dout) {
    extern __shared__ unsigned sm[];
    constexpr int KS = (MODE == 0) ? 80 : 8;
    int tid = threadIdx.x, warp = tid >> 5, lane = tid & 31;
    int grp = lane >> 2, tig = lane & 3;
    int t0 = blockIdx.x * 128;
    int m_off = (warp >> 1) * 64;
    int n_off = (warp & 1) * 64;

    float acc[4][8][4];
#pragma unroll
    for (int mf = 0; mf < 4; mf++)
#pragma unroll
        for (int nf = 0; nf < 8; nf++)
#pragma unroll
            for (int q = 0; q < 4; q++) acc[mf][nf][q] = 0.f;

    stage_step<MODE>(sm, 0, 0, t0, tid);
    CPCOMMIT();

    int buf = 0;
#pragma unroll 1
    for (int s = 0; s < KS; s++) {
        if (s + 1 < KS) {
            stage_step<MODE>(sm, buf ^ 1, s + 1, t0, tid);
            CPCOMMIT();
            CPWAIT1();
        } else {
            CPWAIT0();
        }
        __syncthreads();

        unsigned* sA = sm + buf * BUFW;
        unsigned* sB = sm + buf * BUFW + 32 * SAS;
        int roff = 0;
        if (MODE == 0 && !(s & 1)) {
            int d = 1 << ((s >> 1) % LAYERS_);
            roff = (4 - (d & 3)) & 3;
        }
#pragma unroll
        for (int kc = 0; kc < 32; kc += 8) {
            unsigned a[4][4], b[8][2];
#pragma unroll
            for (int mf = 0; mf < 4; mf++) {
                int r0 = m_off + mf * 16 + grp;
                a[mf][0] = sA[(kc + tig) * SAS + r0];
                a[mf][1] = sA[(kc + tig) * SAS + r0 + 8];
                a[mf][2] = sA[(kc + tig + 4) * SAS + r0];
                a[mf][3] = sA[(kc + tig + 4) * SAS + r0 + 8];
            }
#pragma unroll
            for (int nf = 0; nf < 8; nf++) {
                int ci = n_off + nf * 8 + grp + roff;
                b[nf][0] = sB[(kc + tig) * SBS + ci];
                b[nf][1] = sB[(kc + tig + 4) * SBS + ci];
            }
#pragma unroll
            for (int mf = 0; mf < 4; mf++)
#pragma unroll
                for (int nf = 0; nf < 8; nf++) mma8(acc[mf][nf], a[mf], b[nf]);
        }
        __syncthreads();
        buf ^= 1;
    }

    const float* bp = (MODE == 0) ? g_skipb : bias;

    if (MODE != 2) {
        float* out = (MODE == 0) ? g_skip : g_out1;
#pragma unroll
        for (int mf = 0; mf < 4; mf++)
#pragma unroll
            for (int nf = 0; nf < 8; nf++) {
                int row0 = m_off + mf * 16 + grp;
                int col = t0 + n_off + nf * 8 + 2 * tig;
                float b0 = bp[row0];
                float b1 = bp[row0 + 8];
                float2 v0 = make_float2(rtf(fmaxf(acc[mf][nf][0] + b0, 0.f)),
                                        rtf(fmaxf(acc[mf][nf][1] + b0, 0.f)));
                float2 v1 = make_float2(rtf(fmaxf(acc[mf][nf][2] + b1, 0.f)),
                                        rtf(fmaxf(acc[mf][nf][3] + b1, 0.f)));
                *(float2*)&out[(size_t)row0 * BT_ + col] = v0;
                *(float2*)&out[(size_t)(row0 + 8) * BT_ + col] = v1;
            }
    } else {
        float* ts = (float*)sm;  // [64 tok][260]
#pragma unroll 1
        for (int h = 0; h < 2; h++) {
            __syncthreads();
            if ((warp & 1) == h) {
#pragma unroll
                for (int mf = 0; mf < 4; mf++)
#pragma unroll
                    for (int nf = 0; nf < 8; nf++) {
                        int rowL = m_off + mf * 16 + grp;
                        int colL = nf * 8 + 2 * tig;  // 0..63
                        float b0 = bp[rowL];
                        float b1 = bp[rowL + 8];
                        ts[colL * 260 + rowL] = acc[mf][nf][0] + b0;
                        ts[(colL + 1) * 260 + rowL] = acc[mf][nf][1] + b0;
                        ts[colL * 260 + rowL + 8] = acc[mf][nf][2] + b1;
                        ts[(colL + 1) * 260 + rowL + 8] = acc[mf][nf][3] + b1;
                    }
            }
            __syncthreads();
#pragma unroll
            for (int i = 0; i < 16; i++) {
                int q = tid + i * 256;
                int tk = q >> 6, c4 = (q & 63) * 4;
                float4 v = *(const float4*)&ts[tk * 260 + c4];
                *(float4*)&dout[(size_t)(t0 + h * 64 + tk) * 256 + c4] = v;
            }
        }
    }
}

// ---------------- host launcher ----------------
extern "C" void kernel_launch(void* const* d_in, const int* in_sizes, int n_in,
                              void* d_out, int out_size) {
    const float* x      = (const float*)d_in[0];
    const float* w_in   = (const float*)d_in[1];
    const float* b_in   = (const float*)d_in[2];
    const float* filt_w = (const float*)d_in[3];
    const float* filt_b = (const float*)d_in[4];
    const float* gate_w = (const float*)d_in[5];
    const float* gate_b = (const float*)d_in[6];
    const float* res_w  = (const float*)d_in[7];
    const float* res_b  = (const float*)d_in[8];
    const float* skip_w = (const float*)d_in[9];
    const float* skip_b = (const float*)d_in[10];
    const float* end1_w = (const float*)d_in[11];
    const float* end1_b = (const float*)d_in[12];
    const float* end2_w = (const float*)d_in[13];
    const float* end2_b = (const float*)d_in[14];
    float* out = (float*)d_out;

    const int SMEM  = 25600 * 4;   // GEMM: 102,400 B dynamic
    const int SMZ   = 20544 * 4;   // k_z : 82,176 B
    const int SMR   = 18464 * 4;   // k_res: 73,856 B
    cudaFuncSetAttribute(k_gemm<0>, cudaFuncAttributeMaxDynamicSharedMemorySize, SMEM);
    cudaFuncSetAttribute(k_gemm<1>, cudaFuncAttributeMaxDynamicSharedMemorySize, SMEM);
    cudaFuncSetAttribute(k_gemm<2>, cudaFuncAttributeMaxDynamicSharedMemorySize, SMEM);
    cudaFuncSetAttribute(k_z,   cudaFuncAttributeMaxDynamicSharedMemorySize, SMZ);
    cudaFuncSetAttribute(k_res, cudaFuncAttributeMaxDynamicSharedMemorySize, SMR);

    k_bias<<<1, 256>>>(skip_b);
    k_pack<<<3072, 256>>>(skip_w, end1_w, end2_w);
    k_input<<<BT_ / 512, 256>>>(x, w_in, b_in);

    for (int i = 0; i < NL_; i++) {
        int d = 1 << (i % LAYERS_);
        k_z<<<BT_ / 256, 256, SMZ>>>(filt_w, filt_b, gate_w, gate_b, i, d);
        k_res<<<BT_ / 256, 256, SMR>>>(res_w, res_b, i, d);
    }

    k_gemm<0><<<BT_ / 128, 256, SMEM>>>(nullptr, nullptr);
    k_gemm<1><<<BT_ / 128, 256, SMEM>>>(end1_b, nullptr);
    k_gemm<2><<<BT_ / 128, 256, SMEM>>>(end2_b, out);
}

// round 9
// speedup vs baseline: 1.5306x; 1.2496x over previous
#include <cuda_runtime.h>
#include <cuda_bf16.h>
#include <stdint.h>
#include <math.h>

#define LAYERS_   10
#define NL_       40
#define RC_       32
#define DC_       32
#define SC_       256
#define EC_       256
#define CL_       256
#define B_        8
#define T_        16384
#define BT_       131072   /* B_*T_ */

// ---------------- scratch (static device globals; no allocations) -------------
__device__ float g_h[32 * BT_];                       // residual state, [c][BT]
__device__ float g_z[167772160];                      // 40*32*BT, [layer][c][BT] (tf32-rounded)
__device__ float g_skip[SC_ * BT_];                   // [c][BT]  relu(skip), tf32-rounded
__device__ float g_out1[EC_ * BT_];                   // [c][BT]  relu(out1), tf32-rounded
__device__ float g_skipb[SC_];
__device__ unsigned g_wA[786432];                     // packed tf32 weights, K-major (GEMMs)
__device__ unsigned g_wZ[163840];                     // k_z mma weights [layer][64k][64m] xor-swizzled
__device__ unsigned g_wR[81920];                      // k_res mma weights [layer][64k][32m] xor-swizzled

#define WOFF_SKIP 0
#define WOFF_E1   655360
#define WOFF_E2   720896

// ---------------- small helpers ----------------
__device__ __forceinline__ unsigned f2tf(float x) {
    unsigned r;
    asm("cvt.rna.tf32.f32 %0, %1;" : "=r"(r) : "f"(x));
    return r;
}
__device__ __forceinline__ float rtf(float x) {      // RN-round to tf32, as float
    return __uint_as_float(f2tf(x));
}
__device__ __forceinline__ void mma8(float* d, const unsigned* a, const unsigned* b) {
    asm volatile(
        "mma.sync.aligned.m16n8k8.row.col.f32.tf32.tf32.f32 "
        "{%0,%1,%2,%3},{%4,%5,%6,%7},{%8,%9},{%0,%1,%2,%3};\n"
        : "+f"(d[0]), "+f"(d[1]), "+f"(d[2]), "+f"(d[3])
        : "r"(a[0]), "r"(a[1]), "r"(a[2]), "r"(a[3]), "r"(b[0]), "r"(b[1]));
}
// 3-MUFU activation: tanh(f)*sigmoid(g), tf32-rounded
__device__ __forceinline__ float act_z(float fx, float gx) {
    float a = __expf(-2.f * fabsf(fx));
    float b = __expf(-gx);
    float den = (1.f + a) * (1.f + b);
    float r;
    asm("rcp.approx.f32 %0, %1;" : "=f"(r) : "f"(den));
    return rtf(copysignf((1.f - a) * r, fx));
}

#define CP16(dst, src) asm volatile("cp.async.cg.shared.global [%0], [%1], 16;\n" :: "r"(dst), "l"(src))
#define CP16Z(dst, src, n) asm volatile("cp.async.cg.shared.global [%0], [%1], 16, %2;\n" :: "r"(dst), "l"(src), "r"(n))
#define CPCOMMIT()     asm volatile("cp.async.commit_group;\n")
#define CPWAIT1()      asm volatile("cp.async.wait_group 1;\n" ::: "memory")
#define CPWAIT0()      asm volatile("cp.async.wait_group 0;\n" ::: "memory")

// ---------------- bias reduction for skip ----------------
__global__ void k_bias(const float* __restrict__ skip_b) {
    int o = threadIdx.x;
    float s = 0.f;
#pragma unroll 1
    for (int i = 0; i < NL_; i++) s += skip_b[i * SC_ + o];
    g_skipb[o] = s;
}

// ---------------- pack all weights as tf32 ----------------
__global__ void k_pack(const float* __restrict__ skip_w,
                       const float* __restrict__ e1w,
                       const float* __restrict__ e2w,
                       const float* __restrict__ filt_w,
                       const float* __restrict__ gate_w,
                       const float* __restrict__ res_w) {
    int idx = blockIdx.x * 256 + threadIdx.x;
    if (idx < WOFF_E1) {
        int k = idx >> 8, m = idx & 255;
        int li = k >> 6, tap = (k >> 5) & 1, c = k & 31;
        g_wA[idx] = f2tf(skip_w[((size_t)(li * 256 + m) * 32 + c) * 2 + tap]);
    } else if (idx < WOFF_E2) {
        int local = idx - WOFF_E1;
        int k = local >> 8, m = local & 255;
        g_wA[idx] = f2tf(e1w[m * 256 + k]);
    } else if (idx < 786432) {
        int local = idx - WOFF_E2;
        int k = local >> 8, m = local & 255;
        g_wA[idx] = f2tf(e2w[m * 256 + k]);
    } else if (idx < 786432 + 163840) {
        // k_z weights: [layer][k=c+32*tap][m], m = 16*(o>>3) + (o&7) + 8*isgate,
        // stored xor-swizzled: slot mx = m ^ ((k&3)<<3)
        int local = idx - 786432;
        int layer = local >> 12;
        int rem = local & 4095;
        int k = rem >> 6, mx = rem & 63;
        int m = mx ^ ((k & 3) << 3);
        int c = k & 31, tap = k >> 5;
        int o = ((m >> 4) << 3) + (m & 7);
        int isg = (m >> 3) & 1;
        const float* w = isg ? gate_w : filt_w;
        g_wZ[local] = f2tf(w[layer * 2048 + o * 64 + c * 2 + tap]);
    } else if (idx < 786432 + 163840 + 81920) {
        int local = idx - 786432 - 163840;
        int layer = local >> 11;
        int rem = local & 2047;
        int k = rem >> 5, mx = rem & 31;
        int m = mx ^ ((k & 3) << 3);
        int c = k & 31, tap = k >> 5;
        g_wR[local] = f2tf(res_w[layer * 2048 + m * 64 + c * 2 + tap]);
    }
}

// ---------------- input 1x1 conv: x[8,256,16384] -> h[32][BT] ----------------
__global__ __launch_bounds__(256) void k_input(const float* __restrict__ x,
                                               const float* __restrict__ w_in,
                                               const float* __restrict__ b_in) {
    __shared__ float ws[256 * 32];   // [c][rc]
    __shared__ float bs[32];
    int tid = threadIdx.x;
    for (int e = tid; e < 256 * 32; e += 256) {
        int c = e >> 5, rc = e & 31;
        ws[e] = w_in[rc * 256 + c];
    }
    if (tid < 32) bs[tid] = b_in[tid];
    __syncthreads();

    int i0 = blockIdx.x * 512 + tid;
    int i1 = i0 + 256;
    int b0 = i0 >> 14, t0 = i0 & (T_ - 1);
    int b1 = i1 >> 14, t1 = i1 & (T_ - 1);
    const float* x0 = x + (size_t)b0 * 256 * T_ + t0;
    const float* x1 = x + (size_t)b1 * 256 * T_ + t1;

    float a0[32], a1[32];
#pragma unroll
    for (int r = 0; r < 32; r++) { a0[r] = bs[r]; a1[r] = bs[r]; }

#pragma unroll 1
    for (int c = 0; c < 256; c++) {
        float xv0 = x0[(size_t)c * T_];
        float xv1 = x1[(size_t)c * T_];
        const float* w = &ws[c * 32];
#pragma unroll
        for (int r = 0; r < 32; r++) {
            a0[r] = fmaf(w[r], xv0, a0[r]);
            a1[r] = fmaf(w[r], xv1, a1[r]);
        }
    }
#pragma unroll
    for (int r = 0; r < 32; r++) {
        g_h[r * BT_ + i0] = a0[r];
        g_h[r * BT_ + i1] = a1[r];
    }
}

// ---------------- shared: stage halo tile 32ch x W tokens (t0-pad .. t0+256) --
__device__ __forceinline__ void stage_halo(float* tile, const float* __restrict__ base,
                                           int t0, int pad, int Ws, int nch, int tid) {
    int t0m = t0 & (T_ - 1);
#pragma unroll 1
    for (int c = 0; c < 32; c++) {
        const float* rowp = base + (size_t)c * BT_;
        float* srow = tile + c * Ws;
        for (int j = tid; j < nch; j += 256) {
            bool v = (t0m + 4 * j) >= pad;
            const float* src = v ? (rowp + (t0 - pad + 4 * j)) : rowp;
            uint32_t dst = (uint32_t)__cvta_generic_to_shared(srow + 4 * j);
            CP16Z(dst, src, v ? 16u : 0u);
        }
    }
}

// ---------------- k_z (mma): z = tanh(f)*sigmoid(g) ----------------
// GEMM M=64 (paired filt/gate rows), K=64 (32ch x 2taps), N=256 tokens/CTA.
// 8 warps: warp tile m64 x n32 (n_off = warp*32). A xor-swizzled, B = halo tile.
__global__ __launch_bounds__(256, 2) void k_z(const float* __restrict__ filt_b,
                                              const float* __restrict__ gate_b,
                                              int layer, int d, int pad, int Ws) {
    extern __shared__ float smz[];
    unsigned* sA = (unsigned*)smz;      // 4096 words
    float* tile = smz + 4096;           // 32 x Ws

    int tid = threadIdx.x;
    int t0 = blockIdx.x * 256;
    int nch = (256 + pad) >> 2;

    {
        const unsigned* asrc = g_wZ + layer * 4096;
#pragma unroll
        for (int i = 0; i < 4; i++) {
            int q = (tid + i * 256) * 4;
            uint32_t dst = (uint32_t)__cvta_generic_to_shared(sA + q);
            CP16(dst, asrc + q);
        }
    }
    stage_halo(tile, g_h, t0, pad, Ws, nch, tid);
    CPCOMMIT();
    CPWAIT0();
    __syncthreads();

    int warp = tid >> 5, lane = tid & 31;
    int grp = lane >> 2, tig = lane & 3;
    int n_off = warp * 32;
    int xkey = tig << 3;

    float acc[4][4][4];
#pragma unroll
    for (int mf = 0; mf < 4; mf++)
#pragma unroll
        for (int nf = 0; nf < 4; nf++)
#pragma unroll
            for (int q = 0; q < 4; q++) acc[mf][nf][q] = 0.f;

#pragma unroll
    for (int kc = 0; kc < 64; kc += 8) {
        int off = (kc < 32) ? (pad - d) : pad;
        int cb = kc & 31;
        unsigned a[4][4];
#pragma unroll
        for (int mf = 0; mf < 4; mf++) {
            int m0 = mf * 16 + grp;
            a[mf][0] = sA[(kc + tig) * 64 + (m0 ^ xkey)];
            a[mf][1] = sA[(kc + tig) * 64 + ((m0 + 8) ^ xkey)];
            a[mf][2] = sA[(kc + tig + 4) * 64 + (m0 ^ xkey)];
            a[mf][3] = sA[(kc + tig + 4) * 64 + ((m0 + 8) ^ xkey)];
        }
        unsigned b[4][2];
#pragma unroll
        for (int nf = 0; nf < 4; nf++) {
            int n = n_off + nf * 8 + grp;
            b[nf][0] = f2tf(tile[(cb + tig) * Ws + off + n]);
            b[nf][1] = f2tf(tile[(cb + tig + 4) * Ws + off + n]);
        }
#pragma unroll
        for (int mf = 0; mf < 4; mf++)
#pragma unroll
            for (int nf = 0; nf < 4; nf++) mma8(acc[mf][nf], a[mf], b[nf]);
    }

    // epilogue: acc[mf][nf][0,1] = f(tok, tok+1), [2,3] = g(tok, tok+1) for o = mf*8+grp
#pragma unroll
    for (int mf = 0; mf < 4; mf++) {
        int o = mf * 8 + grp;
        float fbv = __ldg(filt_b + layer * 32 + o);
        float gbv = __ldg(gate_b + layer * 32 + o);
        float* zrow = g_z + ((size_t)layer * 32 + o) * BT_ + t0;
#pragma unroll
        for (int nf = 0; nf < 4; nf++) {
            int col = n_off + nf * 8 + 2 * tig;
            float2 zv;
            zv.x = act_z(acc[mf][nf][0] + fbv, acc[mf][nf][2] + gbv);
            zv.y = act_z(acc[mf][nf][1] + fbv, acc[mf][nf][3] + gbv);
            *(float2*)(zrow + col) = zv;
        }
    }
}

// ---------------- k_res (mma): h += conv(z) + bias ----------------
// GEMM M=32, K=64, N=256. 8 warps: warp tile m32 x n32.
__global__ __launch_bounds__(256, 2) void k_res(const float* __restrict__ res_b,
                                                int layer, int d, int pad, int Ws) {
    extern __shared__ float smr[];
    unsigned* sR = (unsigned*)smr;      // 2048 words
    float* tile = smr + 2048;           // 32 x Ws

    int tid = threadIdx.x;
    int t0 = blockIdx.x * 256;
    int nch = (256 + pad) >> 2;
    const float* zL = g_z + (size_t)layer * 32 * BT_;

    {
        const unsigned* asrc = g_wR + layer * 2048;
#pragma unroll
        for (int i = 0; i < 2; i++) {
            int q = (tid + i * 256) * 4;
            uint32_t dst = (uint32_t)__cvta_generic_to_shared(sR + q);
            CP16(dst, asrc + q);
        }
    }
    stage_halo(tile, zL, t0, pad, Ws, nch, tid);
    CPCOMMIT();
    CPWAIT0();
    __syncthreads();

    int warp = tid >> 5, lane = tid & 31;
    int grp = lane >> 2, tig = lane & 3;
    int n_off = warp * 32;
    int xkey = tig << 3;

    float acc[2][4][4];
#pragma unroll
    for (int mf = 0; mf < 2; mf++)
#pragma unroll
        for (int nf = 0; nf < 4; nf++)
#pragma unroll
            for (int q = 0; q < 4; q++) acc[mf][nf][q] = 0.f;

#pragma unroll
    for (int kc = 0; kc < 64; kc += 8) {
        int off = (kc < 32) ? (pad - d) : pad;
        int cb = kc & 31;
        unsigned a[2][4];
#pragma unroll
        for (int mf = 0; mf < 2; mf++) {
            int m0 = mf * 16 + grp;
            a[mf][0] = sR[(kc + tig) * 32 + (m0 ^ xkey)];
            a[mf][1] = sR[(kc + tig) * 32 + ((m0 + 8) ^ xkey)];
            a[mf][2] = sR[(kc + tig + 4) * 32 + (m0 ^ xkey)];
            a[mf][3] = sR[(kc + tig + 4) * 32 + ((m0 + 8) ^ xkey)];
        }
        unsigned b[4][2];
#pragma unroll
        for (int nf = 0; nf < 4; nf++) {
            int n = n_off + nf * 8 + grp;
            b[nf][0] = __float_as_uint(tile[(cb + tig) * Ws + off + n]);      // z already tf32
            b[nf][1] = __float_as_uint(tile[(cb + tig + 4) * Ws + off + n]);
        }
#pragma unroll
        for (int mf = 0; mf < 2; mf++)
#pragma unroll
            for (int nf = 0; nf < 4; nf++) mma8(acc[mf][nf], a[mf], b[nf]);
    }

#pragma unroll
    for (int mf = 0; mf < 2; mf++) {
        int o = mf * 16 + grp;
        float b0 = __ldg(res_b + layer * 32 + o);
        float b1 = __ldg(res_b + layer * 32 + o + 8);
        float* r0base = g_h + (size_t)o * BT_ + t0;
        float* r1base = g_h + (size_t)(o + 8) * BT_ + t0;
#pragma unroll
        for (int nf = 0; nf < 4; nf++) {
            int col = n_off + nf * 8 + 2 * tig;
            float2 h0 = *(const float2*)(r0base + col);
            float2 h1 = *(const float2*)(r1base + col);
            h0.x += acc[mf][nf][0] + b0;
            h0.y += acc[mf][nf][1] + b0;
            h1.x += acc[mf][nf][2] + b1;
            h1.y += acc[mf][nf][3] + b1;
            *(float2*)(r0base + col) = h0;
            *(float2*)(r1base + col) = h1;
        }
    }
}

// ================== unified tf32 GEMM (cp.async staged, double buffered) =====
#define SAS 264
#define SBS 136
#define BUFW 12800

template <int MODE>
__device__ __forceinline__ void stage_step(unsigned* sm, int buf, int s, int t0, int tid) {
    unsigned* sA = sm + buf * BUFW;
    unsigned* sB = sm + buf * BUFW + 32 * SAS;
    const unsigned* asrc = g_wA + (MODE == 0 ? WOFF_SKIP : (MODE == 1 ? WOFF_E1 : WOFF_E2))
                         + (size_t)s * 32 * 256;
#pragma unroll
    for (int i = 0; i < 8; i++) {
        int q = tid + i * 256;
        int row = q >> 6, col = (q & 63) * 4;
        uint32_t dst = (uint32_t)__cvta_generic_to_shared(sA + row * SAS + col);
        CP16(dst, asrc + row * 256 + col);
    }
    if (MODE != 0) {
        const float* gB = (MODE == 1) ? g_skip : g_out1;
#pragma unroll
        for (int i = 0; i < 4; i++) {
            int q = tid + i * 256;
            int row = q >> 5, col = (q & 31) * 4;
            uint32_t dst = (uint32_t)__cvta_generic_to_shared(sB + row * SBS + col);
            CP16(dst, gB + (size_t)(s * 32 + row) * BT_ + t0 + col);
        }
    } else {
        int li = s >> 1, tap = s & 1;
        int d = 1 << (li % LAYERS_);
        int j = tid >> 3, l8 = tid & 7;
        const float* zrow = g_z + ((size_t)li * 32 + j) * BT_;
        if (tap == 1) {
#pragma unroll
            for (int i = 0; i < 4; i++) {
                int q = l8 + i * 8;
                uint32_t dst = (uint32_t)__cvta_generic_to_shared(sB + j * SBS + q * 4);
                CP16(dst, zrow + t0 + q * 4);
            }
        } else {
            int r = (4 - (d & 3)) & 3;
            int t0m = t0 & (T_ - 1);
            if (t0m >= d + 4) {
                const float* src = zrow + t0 - d - r;
#pragma unroll
                for (int i = 0; i < 4; i++) {
                    int q = l8 + i * 8;
                    uint32_t dst = (uint32_t)__cvta_generic_to_shared(sB + j * SBS + q * 4);
                    CP16(dst, src + q * 4);
                }
                if (l8 == 0) {
                    uint32_t dst = (uint32_t)__cvta_generic_to_shared(sB + j * SBS + 128);
                    CP16(dst, src + 128);
                }
            } else {
                for (int t = l8; t < 128; t += 8) {
                    int gm = t0 + t;
                    float v = ((gm & (T_ - 1)) >= d) ? zrow[gm - d] : 0.f;
                    sB[j * SBS + r + t] = __float_as_uint(v);
                }
            }
        }
    }
}

template <int MODE>
__global__ __launch_bounds__(256) void k_gemm(const float* __restrict__ bias,
                                              float* __restrict__ dout) {
    extern __shared__ unsigned sm[];
    constexpr int KS = (MODE == 0) ? 80 : 8;
    int tid = threadIdx.x, warp = tid >> 5, lane = tid & 31;
    int grp = lane >> 2, tig = lane & 3;
    int t0 = blockIdx.x * 128;
    int m_off = (warp >> 1) * 64;
    int n_off = (warp & 1) * 64;

    float acc[4][8][4];
#pragma unroll
    for (int mf = 0; mf < 4; mf++)
#pragma unroll
        for (int nf = 0; nf < 8; nf++)
#pragma unroll
            for (int q = 0; q < 4; q++) acc[mf][nf][q] = 0.f;

    stage_step<MODE>(sm, 0, 0, t0, tid);
    CPCOMMIT();

    int buf = 0;
#pragma unroll 1
    for (int s = 0; s < KS; s++) {
        if (s + 1 < KS) {
            stage_step<MODE>(sm, buf ^ 1, s + 1, t0, tid);
            CPCOMMIT();
            CPWAIT1();
        } else {
            CPWAIT0();
        }
        __syncthreads();

        unsigned* sA = sm + buf * BUFW;
        unsigned* sB = sm + buf * BUFW + 32 * SAS;
        int roff = 0;
        if (MODE == 0 && !(s & 1)) {
            int d = 1 << ((s >> 1) % LAYERS_);
            roff = (4 - (d & 3)) & 3;
        }
#pragma unroll
        for (int kc = 0; kc < 32; kc += 8) {
            unsigned a[4][4], b[8][2];
#pragma unroll
            for (int mf = 0; mf < 4; mf++) {
                int r0 = m_off + mf * 16 + grp;
                a[mf][0] = sA[(kc + tig) * SAS + r0];
                a[mf][1] = sA[(kc + tig) * SAS + r0 + 8];
                a[mf][2] = sA[(kc + tig + 4) * SAS + r0];
                a[mf][3] = sA[(kc + tig + 4) * SAS + r0 + 8];
            }
#pragma unroll
            for (int nf = 0; nf < 8; nf++) {
                int ci = n_off + nf * 8 + grp + roff;
                b[nf][0] = sB[(kc + tig) * SBS + ci];
                b[nf][1] = sB[(kc + tig + 4) * SBS + ci];
            }
#pragma unroll
            for (int mf = 0; mf < 4; mf++)
#pragma unroll
                for (int nf = 0; nf < 8; nf++) mma8(acc[mf][nf], a[mf], b[nf]);
        }
        __syncthreads();
        buf ^= 1;
    }

    const float* bp = (MODE == 0) ? g_skipb : bias;

    if (MODE != 2) {
        float* out = (MODE == 0) ? g_skip : g_out1;
#pragma unroll
        for (int mf = 0; mf < 4; mf++)
#pragma unroll
            for (int nf = 0; nf < 8; nf++) {
                int row0 = m_off + mf * 16 + grp;
                int col = t0 + n_off + nf * 8 + 2 * tig;
                float b0 = bp[row0];
                float b1 = bp[row0 + 8];
                float2 v0 = make_float2(rtf(fmaxf(acc[mf][nf][0] + b0, 0.f)),
                                        rtf(fmaxf(acc[mf][nf][1] + b0, 0.f)));
                float2 v1 = make_float2(rtf(fmaxf(acc[mf][nf][2] + b1, 0.f)),
                                        rtf(fmaxf(acc[mf][nf][3] + b1, 0.f)));
                *(float2*)&out[(size_t)row0 * BT_ + col] = v0;
                *(float2*)&out[(size_t)(row0 + 8) * BT_ + col] = v1;
            }
    } else {
        float* ts = (float*)sm;  // [64 tok][260]
#pragma unroll 1
        for (int h = 0; h < 2; h++) {
            __syncthreads();
            if ((warp & 1) == h) {
#pragma unroll
                for (int mf = 0; mf < 4; mf++)
#pragma unroll
                    for (int nf = 0; nf < 8; nf++) {
                        int rowL = m_off + mf * 16 + grp;
                        int colL = nf * 8 + 2 * tig;  // 0..63
                        float b0 = bp[rowL];
                        float b1 = bp[rowL + 8];
                        ts[colL * 260 + rowL] = acc[mf][nf][0] + b0;
                        ts[(colL + 1) * 260 + rowL] = acc[mf][nf][1] + b0;
                        ts[colL * 260 + rowL + 8] = acc[mf][nf][2] + b1;
                        ts[(colL + 1) * 260 + rowL + 8] = acc[mf][nf][3] + b1;
                    }
            }
            __syncthreads();
#pragma unroll
            for (int i = 0; i < 16; i++) {
                int q = tid + i * 256;
                int tk = q >> 6, c4 = (q & 63) * 4;
                float4 v = *(const float4*)&ts[tk * 260 + c4];
                *(float4*)&dout[(size_t)(t0 + h * 64 + tk) * 256 + c4] = v;
            }
        }
    }
}

// ---------------- host launcher ----------------
extern "C" void kernel_launch(void* const* d_in, const int* in_sizes, int n_in,
                              void* d_out, int out_size) {
    const float* x      = (const float*)d_in[0];
    const float* w_in   = (const float*)d_in[1];
    const float* b_in   = (const float*)d_in[2];
    const float* filt_w = (const float*)d_in[3];
    const float* filt_b = (const float*)d_in[4];
    const float* gate_w = (const float*)d_in[5];
    const float* gate_b = (const float*)d_in[6];
    const float* res_w  = (const float*)d_in[7];
    const float* res_b  = (const float*)d_in[8];
    const float* skip_w = (const float*)d_in[9];
    const float* skip_b = (const float*)d_in[10];
    const float* end1_w = (const float*)d_in[11];
    const float* end1_b = (const float*)d_in[12];
    const float* end2_w = (const float*)d_in[13];
    const float* end2_b = (const float*)d_in[14];
    float* out = (float*)d_out;

    const int SMEM  = 25600 * 4;   // GEMM: 102,400 B dynamic
    const int SMZMAX = (4096 + 32 * 772) * 4;   // 115,200 B
    const int SMRMAX = (2048 + 32 * 772) * 4;   // 107,008 B
    cudaFuncSetAttribute(k_gemm<0>, cudaFuncAttributeMaxDynamicSharedMemorySize, SMEM);
    cudaFuncSetAttribute(k_gemm<1>, cudaFuncAttributeMaxDynamicSharedMemorySize, SMEM);
    cudaFuncSetAttribute(k_gemm<2>, cudaFuncAttributeMaxDynamicSharedMemorySize, SMEM);
    cudaFuncSetAttribute(k_z,   cudaFuncAttributeMaxDynamicSharedMemorySize, SMZMAX);
    cudaFuncSetAttribute(k_res, cudaFuncAttributeMaxDynamicSharedMemorySize, SMRMAX);

    k_bias<<<1, 256>>>(skip_b);
    k_pack<<<4032, 256>>>(skip_w, end1_w, end2_w, filt_w, gate_w, res_w);
    k_input<<<BT_ / 512, 256>>>(x, w_in, b_in);

    for (int i = 0; i < NL_; i++) {
        int d = 1 << (i % LAYERS_);
        int pad = (d + 3) & ~3;
        int W = 256 + pad;
        int Ws = W + ((8 - (W & 31)) & 31);
        if (Ws == 776) Ws = 772;   // d=512: stay under SM smem limit at occ 2
        int smz = (4096 + 32 * Ws) * 4;
        int smr = (2048 + 32 * Ws) * 4;
        k_z<<<BT_ / 256, 256, smz>>>(filt_b, gate_b, i, d, pad, Ws);
        k_res<<<BT_ / 256, 256, smr>>>(res_b, i, d, pad, Ws);
    }

    k_gemm<0><<<BT_ / 128, 256, SMEM>>>(nullptr, nullptr);
    k_gemm<1><<<BT_ / 128, 256, SMEM>>>(end1_b, nullptr);
    k_gemm<2><<<BT_ / 128, 256, SMEM>>>(end2_b, out);
}

// round 11
// speedup vs baseline: 1.8187x; 1.1882x over previous
#include <cuda_runtime.h>
#include <cuda_bf16.h>
#include <stdint.h>
#include <math.h>

#define LAYERS_   10
#define NL_       40
#define RC_       32
#define DC_       32
#define SC_       256
#define EC_       256
#define CL_       256
#define B_        8
#define T_        16384
#define BT_       131072   /* B_*T_ */

typedef unsigned long long u64;

// ---------------- scratch (static device globals; no allocations) -------------
__device__ float g_h[32 * BT_];                       // residual state, [c][BT]
__device__ float g_z[167772160];                      // 40*32*BT, [layer][c][BT] (tf32-rounded)
__device__ float g_skip[SC_ * BT_];                   // [c][BT]  relu(skip), tf32-rounded
__device__ float g_out1[EC_ * BT_];                   // [c][BT]  relu(out1), tf32-rounded
__device__ float g_skipb[SC_];
__device__ unsigned g_wA[786432];                     // packed tf32 weights, K-major (GEMMs)
__device__ unsigned g_wZ[163840];                     // k_z mma weights [layer][64k][64m] xor-swizzled
__device__ unsigned g_wR[81920];                      // k_res mma weights [layer][64k][32m] xor-swizzled

#define WOFF_SKIP 0
#define WOFF_E1   655360
#define WOFF_E2   720896

// ---------------- small helpers ----------------
__device__ __forceinline__ unsigned f2tf(float x) {
    unsigned r;
    asm("cvt.rna.tf32.f32 %0, %1;" : "=r"(r) : "f"(x));
    return r;
}
__device__ __forceinline__ float rtf(float x) {      // RN-round to tf32, as float
    return __uint_as_float(f2tf(x));
}
__device__ __forceinline__ void mma8(float* d, const unsigned* a, const unsigned* b) {
    asm volatile(
        "mma.sync.aligned.m16n8k8.row.col.f32.tf32.tf32.f32 "
        "{%0,%1,%2,%3},{%4,%5,%6,%7},{%8,%9},{%0,%1,%2,%3};\n"
        : "+f"(d[0]), "+f"(d[1]), "+f"(d[2]), "+f"(d[3])
        : "r"(a[0]), "r"(a[1]), "r"(a[2]), "r"(a[3]), "r"(b[0]), "r"(b[1]));
}
__device__ __forceinline__ void fma2(u64& d, u64 a, u64 b) {
    asm("fma.rn.f32x2 %0, %1, %2, %0;" : "+l"(d) : "l"(a), "l"(b));
}
__device__ __forceinline__ u64 dup2(float x) {
    u64 r; unsigned xi = __float_as_uint(x);
    asm("mov.b64 %0, {%1, %1};" : "=l"(r) : "r"(xi));
    return r;
}
__device__ __forceinline__ float2 unpk(u64 v) {
    unsigned lo, hi;
    asm("mov.b64 {%0, %1}, %2;" : "=r"(lo), "=r"(hi) : "l"(v));
    return make_float2(__uint_as_float(lo), __uint_as_float(hi));
}
// 3-MUFU activation: tanh(f)*sigmoid(g), tf32-rounded
__device__ __forceinline__ float act_z(float fx, float gx) {
    float a = __expf(-2.f * fabsf(fx));
    float b = __expf(-gx);
    float den = (1.f + a) * (1.f + b);
    float r;
    asm("rcp.approx.f32 %0, %1;" : "=f"(r) : "f"(den));
    return rtf(copysignf((1.f - a) * r, fx));
}

#define CP16(dst, src) asm volatile("cp.async.cg.shared.global [%0], [%1], 16;\n" :: "r"(dst), "l"(src))
#define CP16Z(dst, src, n) asm volatile("cp.async.cg.shared.global [%0], [%1], 16, %2;\n" :: "r"(dst), "l"(src), "r"(n))
#define CPCOMMIT()     asm volatile("cp.async.commit_group;\n")
#define CPWAIT1()      asm volatile("cp.async.wait_group 1;\n" ::: "memory")
#define CPWAIT0()      asm volatile("cp.async.wait_group 0;\n" ::: "memory")

// ---------------- bias reduction for skip ----------------
__global__ void k_bias(const float* __restrict__ skip_b) {
    int o = threadIdx.x;
    float s = 0.f;
#pragma unroll 1
    for (int i = 0; i < NL_; i++) s += skip_b[i * SC_ + o];
    g_skipb[o] = s;
}

// ---------------- pack all weights as tf32 ----------------
__global__ void k_pack(const float* __restrict__ skip_w,
                       const float* __restrict__ e1w,
                       const float* __restrict__ e2w,
                       const float* __restrict__ filt_w,
                       const float* __restrict__ gate_w,
                       const float* __restrict__ res_w) {
    int idx = blockIdx.x * 256 + threadIdx.x;
    if (idx < WOFF_E1) {
        int k = idx >> 8, m = idx & 255;
        int li = k >> 6, tap = (k >> 5) & 1, c = k & 31;
        g_wA[idx] = f2tf(skip_w[((size_t)(li * 256 + m) * 32 + c) * 2 + tap]);
    } else if (idx < WOFF_E2) {
        int local = idx - WOFF_E1;
        int k = local >> 8, m = local & 255;
        g_wA[idx] = f2tf(e1w[m * 256 + k]);
    } else if (idx < 786432) {
        int local = idx - WOFF_E2;
        int k = local >> 8, m = local & 255;
        g_wA[idx] = f2tf(e2w[m * 256 + k]);
    } else if (idx < 786432 + 163840) {
        int local = idx - 786432;
        int layer = local >> 12;
        int rem = local & 4095;
        int k = rem >> 6, mx = rem & 63;
        int m = mx ^ ((k & 3) << 3);
        int c = k & 31, tap = k >> 5;
        int o = ((m >> 4) << 3) + (m & 7);
        int isg = (m >> 3) & 1;
        const float* w = isg ? gate_w : filt_w;
        g_wZ[local] = f2tf(w[layer * 2048 + o * 64 + c * 2 + tap]);
    } else if (idx < 786432 + 163840 + 81920) {
        int local = idx - 786432 - 163840;
        int layer = local >> 11;
        int rem = local & 2047;
        int k = rem >> 5, mx = rem & 31;
        int m = mx ^ ((k & 3) << 3);
        int c = k & 31, tap = k >> 5;
        g_wR[local] = f2tf(res_w[layer * 2048 + m * 64 + c * 2 + tap]);
    }
}

// ---------------- input 1x1 conv (fma2): x[8,256,16384] -> h[32][BT] ---------
// thread = 2 adjacent tokens x 32 outputs (16 output pairs); 512 tokens/block
__global__ __launch_bounds__(256, 2) void k_input(const float* __restrict__ x,
                                                  const float* __restrict__ w_in,
                                                  const float* __restrict__ b_in) {
    __shared__ __align__(16) float ws[256 * 32];   // [c][o]
    __shared__ float bs[32];
    int tid = threadIdx.x;
    for (int e = tid; e < 256 * 32; e += 256) {
        int c = e >> 5, rc = e & 31;
        ws[e] = w_in[rc * 256 + c];
    }
    if (tid < 32) bs[tid] = b_in[tid];
    __syncthreads();

    int i0 = blockIdx.x * 512 + tid * 2;
    int b0 = i0 >> 14, t0 = i0 & (T_ - 1);
    const float* xb = x + (size_t)b0 * 256 * T_ + t0;

    u64 a0[16], a1[16];
#pragma unroll
    for (int p = 0; p < 16; p++) { a0[p] = 0; a1[p] = 0; }

    float2 xv = *(const float2*)xb;
#pragma unroll 4
    for (int c = 0; c < 256; c++) {
        int cn = (c < 255) ? c + 1 : 255;
        float2 nxv = *(const float2*)(xb + (size_t)cn * T_);
        u64 xl = dup2(xv.x), xh = dup2(xv.y);
        const ulonglong2* w = (const ulonglong2*)&ws[c * 32];
#pragma unroll
        for (int q = 0; q < 8; q++) {
            ulonglong2 wp = w[q];
            fma2(a0[2 * q], wp.x, xl);     fma2(a0[2 * q + 1], wp.y, xl);
            fma2(a1[2 * q], wp.x, xh);     fma2(a1[2 * q + 1], wp.y, xh);
        }
        xv = nxv;
    }
#pragma unroll
    for (int p = 0; p < 16; p++) {
        int o0 = 2 * p, o1 = o0 + 1;
        float2 vl = unpk(a0[p]);   // (o0 tok0, o1 tok0)
        float2 vh = unpk(a1[p]);   // (o0 tok1, o1 tok1)
        float bb0 = bs[o0], bb1 = bs[o1];
        *(float2*)(g_h + (size_t)o0 * BT_ + i0) = make_float2(vl.x + bb0, vh.x + bb0);
        *(float2*)(g_h + (size_t)o1 * BT_ + i0) = make_float2(vl.y + bb1, vh.y + bb1);
    }
}

// host/device constexpr geometry
__host__ __device__ constexpr int padof(int d) { return (d + 3) & ~3; }
__host__ __device__ constexpr int wsof(int d) {
    int w = 256 + padof(d);
    int ws = w + ((8 - (w & 31)) & 31);
    return ws == 776 ? 772 : ws;   // d=512: fit occ 2
}

// ---------------- stage channels [c0,c0+16) of halo tile (compile-time PAD/WS)
template <int PAD, int WS>
__device__ __forceinline__ void stage_halo(float* tile, const float* __restrict__ base,
                                           int t0, int t0m, int c0, int tid) {
    constexpr int NCH = (256 + PAD) >> 2;     // 16B chunks per row
    int c = c0 + (tid >> 4);                   // 16 threads per channel, 16 channels
    int j0 = tid & 15;
    const float* rowp = base + (size_t)c * BT_;
    float* srow = tile + c * WS;
#pragma unroll 1
    for (int j = j0; j < NCH; j += 16) {
        bool v = (t0m + 4 * j) >= PAD;
        const float* src = v ? (rowp + (t0 - PAD + 4 * j)) : rowp;
        uint32_t dst = (uint32_t)__cvta_generic_to_shared(srow + 4 * j);
        CP16Z(dst, src, v ? 16u : 0u);
    }
}

// ---------------- k_z<D> (mma): z = tanh(f)*sigmoid(g) ----------------
template <int D>
__global__ __launch_bounds__(256, 2) void k_z(const float* __restrict__ filt_b,
                                              const float* __restrict__ gate_b,
                                              int layer) {
    constexpr int PAD = padof(D);
    constexpr int WS = wsof(D);
    extern __shared__ float smz[];
    unsigned* sA = (unsigned*)smz;      // 4096 words
    float* tile = smz + 4096;           // 32 x WS

    int tid = threadIdx.x;
    int t0 = blockIdx.x * 256;
    int t0m = t0 & (T_ - 1);

    // group 1: A weights + channels [0,16)
    {
        const unsigned* asrc = g_wZ + layer * 4096;
#pragma unroll
        for (int i = 0; i < 4; i++) {
            int q = (tid + i * 256) * 4;
            uint32_t dst = (uint32_t)__cvta_generic_to_shared(sA + q);
            CP16(dst, asrc + q);
        }
    }
    stage_halo<PAD, WS>(tile, g_h, t0, t0m, 0, tid);
    CPCOMMIT();
    stage_halo<PAD, WS>(tile, g_h, t0, t0m, 16, tid);
    CPCOMMIT();

    int warp = tid >> 5, lane = tid & 31;
    int grp = lane >> 2, tig = lane & 3;
    int n_off = warp * 32;
    int xkey = tig << 3;

    float acc[4][4][4];
#pragma unroll
    for (int mf = 0; mf < 4; mf++)
#pragma unroll
        for (int nf = 0; nf < 4; nf++)
#pragma unroll
            for (int q = 0; q < 4; q++) acc[mf][nf][q] = 0.f;

    CPWAIT1();
    __syncthreads();

#pragma unroll
    for (int phase = 0; phase < 2; phase++) {
#pragma unroll
        for (int tap = 0; tap < 2; tap++) {
#pragma unroll
            for (int kk = 0; kk < 2; kk++) {
                const int cb = phase * 16 + kk * 8;
                const int kc = tap * 32 + cb;
                const int off = tap ? PAD : (PAD - D);
                unsigned a[4][4];
#pragma unroll
                for (int mf = 0; mf < 4; mf++) {
                    int m0 = mf * 16 + grp;
                    a[mf][0] = sA[(kc + tig) * 64 + (m0 ^ xkey)];
                    a[mf][1] = sA[(kc + tig) * 64 + ((m0 + 8) ^ xkey)];
                    a[mf][2] = sA[(kc + tig + 4) * 64 + (m0 ^ xkey)];
                    a[mf][3] = sA[(kc + tig + 4) * 64 + ((m0 + 8) ^ xkey)];
                }
                unsigned b[4][2];
#pragma unroll
                for (int nf = 0; nf < 4; nf++) {
                    int n = n_off + nf * 8 + grp;
                    b[nf][0] = f2tf(tile[(cb + tig) * WS + off + n]);
                    b[nf][1] = f2tf(tile[(cb + tig + 4) * WS + off + n]);
                }
#pragma unroll
                for (int mf = 0; mf < 4; mf++)
#pragma unroll
                    for (int nf = 0; nf < 4; nf++) mma8(acc[mf][nf], a[mf], b[nf]);
            }
        }
        if (phase == 0) {
            CPWAIT0();
            __syncthreads();
        }
    }

    // epilogue: acc[mf][nf] = {f tok0, f tok1, g tok0, g tok1} for o = mf*8+grp
#pragma unroll
    for (int mf = 0; mf < 4; mf++) {
        int o = mf * 8 + grp;
        float fbv = __ldg(filt_b + layer * 32 + o);
        float gbv = __ldg(gate_b + layer * 32 + o);
        float* zrow = g_z + ((size_t)layer * 32 + o) * BT_ + t0;
#pragma unroll
        for (int nf = 0; nf < 4; nf++) {
            int col = n_off + nf * 8 + 2 * tig;
            float2 zv;
            zv.x = act_z(acc[mf][nf][0] + fbv, acc[mf][nf][2] + gbv);
            zv.y = act_z(acc[mf][nf][1] + fbv, acc[mf][nf][3] + gbv);
            *(float2*)(zrow + col) = zv;
        }
    }
}

// ---------------- k_res<D> (mma): h += conv(z) + bias ----------------
template <int D>
__global__ __launch_bounds__(256, 2) void k_res(const float* __restrict__ res_b,
                                                int layer) {
    constexpr int PAD = padof(D);
    constexpr int WS = wsof(D);
    extern __shared__ float smr[];
    unsigned* sR = (unsigned*)smr;      // 2048 words
    float* tile = smr + 2048;           // 32 x WS

    int tid = threadIdx.x;
    int t0 = blockIdx.x * 256;
    int t0m = t0 & (T_ - 1);
    const float* zL = g_z + (size_t)layer * 32 * BT_;

    {
        const unsigned* asrc = g_wR + layer * 2048;
#pragma unroll
        for (int i = 0; i < 2; i++) {
            int q = (tid + i * 256) * 4;
            uint32_t dst = (uint32_t)__cvta_generic_to_shared(sR + q);
            CP16(dst, asrc + q);
        }
    }
    stage_halo<PAD, WS>(tile, zL, t0, t0m, 0, tid);
    CPCOMMIT();
    stage_halo<PAD, WS>(tile, zL, t0, t0m, 16, tid);
    CPCOMMIT();

    int warp = tid >> 5, lane = tid & 31;
    int grp = lane >> 2, tig = lane & 3;
    int n_off = warp * 32;
    int xkey = tig << 3;

    float acc[2][4][4];
#pragma unroll
    for (int mf = 0; mf < 2; mf++)
#pragma unroll
        for (int nf = 0; nf < 4; nf++)
#pragma unroll
            for (int q = 0; q < 4; q++) acc[mf][nf][q] = 0.f;

    CPWAIT1();
    __syncthreads();

#pragma unroll
    for (int phase = 0; phase < 2; phase++) {
#pragma unroll
        for (int tap = 0; tap < 2; tap++) {
#pragma unroll
            for (int kk = 0; kk < 2; kk++) {
                const int cb = phase * 16 + kk * 8;
                const int kc = tap * 32 + cb;
                const int off = tap ? PAD : (PAD - D);
                unsigned a[2][4];
#pragma unroll
                for (int mf = 0; mf < 2; mf++) {
                    int m0 = mf * 16 + grp;
                    a[mf][0] = sR[(kc + tig) * 32 + (m0 ^ xkey)];
                    a[mf][1] = sR[(kc + tig) * 32 + ((m0 + 8) ^ xkey)];
                    a[mf][2] = sR[(kc + tig + 4) * 32 + (m0 ^ xkey)];
                    a[mf][3] = sR[(kc + tig + 4) * 32 + ((m0 + 8) ^ xkey)];
                }
                unsigned b[4][2];
#pragma unroll
                for (int nf = 0; nf < 4; nf++) {
                    int n = n_off + nf * 8 + grp;
                    b[nf][0] = __float_as_uint(tile[(cb + tig) * WS + off + n]);
                    b[nf][1] = __float_as_uint(tile[(cb + tig + 4) * WS + off + n]);
                }
#pragma unroll
                for (int mf = 0; mf < 2; mf++)
#pragma unroll
                    for (int nf = 0; nf < 4; nf++) mma8(acc[mf][nf], a[mf], b[nf]);
            }
        }
        if (phase == 0) {
            CPWAIT0();
            __syncthreads();
        }
    }

#pragma unroll
    for (int mf = 0; mf < 2; mf++) {
        int o = mf * 16 + grp;
        float b0 = __ldg(res_b + layer * 32 + o);
        float b1 = __ldg(res_b + layer * 32 + o + 8);
        float* r0base = g_h + (size_t)o * BT_ + t0;
        float* r1base = g_h + (size_t)(o + 8) * BT_ + t0;
#pragma unroll
        for (int nf = 0; nf < 4; nf++) {
            int col = n_off + nf * 8 + 2 * tig;
            float2 h0 = *(const float2*)(r0base + col);
            float2 h1 = *(const float2*)(r1base + col);
            h0.x += acc[mf][nf][0] + b0;
            h0.y += acc[mf][nf][1] + b0;
            h1.x += acc[mf][nf][2] + b1;
            h1.y += acc[mf][nf][3] + b1;
            *(float2*)(r0base + col) = h0;
            *(float2*)(r1base + col) = h1;
        }
    }
}

// ================== unified tf32 GEMM (cp.async staged, double buffered) =====
#define SAS 264
#define SBS 136
#define BUFW 12800

template <int MODE>
__device__ __forceinline__ void stage_step(unsigned* sm, int buf, int s, int t0, int tid) {
    unsigned* sA = sm + buf * BUFW;
    unsigned* sB = sm + buf * BUFW + 32 * SAS;
    const unsigned* asrc = g_wA + (MODE == 0 ? WOFF_SKIP : (MODE == 1 ? WOFF_E1 : WOFF_E2))
                         + (size_t)s * 32 * 256;
#pragma unroll
    for (int i = 0; i < 8; i++) {
        int q = tid + i * 256;
        int row = q >> 6, col = (q & 63) * 4;
        uint32_t dst = (uint32_t)__cvta_generic_to_shared(sA + row * SAS + col);
        CP16(dst, asrc + row * 256 + col);
    }
    if (MODE != 0) {
        const float* gB = (MODE == 1) ? g_skip : g_out1;
#pragma unroll
        for (int i = 0; i < 4; i++) {
            int q = tid + i * 256;
            int row = q >> 5, col = (q & 31) * 4;
            uint32_t dst = (uint32_t)__cvta_generic_to_shared(sB + row * SBS + col);
            CP16(dst, gB + (size_t)(s * 32 + row) * BT_ + t0 + col);
        }
    } else {
        int li = s >> 1, tap = s & 1;
        int d = 1 << (li % LAYERS_);
        int j = tid >> 3, l8 = tid & 7;
        const float* zrow = g_z + ((size_t)li * 32 + j) * BT_;
        if (tap == 1) {
#pragma unroll
            for (int i = 0; i < 4; i++) {
                int q = l8 + i * 8;
                uint32_t dst = (uint32_t)__cvta_generic_to_shared(sB + j * SBS + q * 4);
                CP16(dst, zrow + t0 + q * 4);
            }
        } else {
            int r = (4 - (d & 3)) & 3;
            int t0m = t0 & (T_ - 1);
            if (t0m >= d + 4) {
                const float* src = zrow + t0 - d - r;
#pragma unroll
                for (int i = 0; i < 4; i++) {
                    int q = l8 + i * 8;
                    uint32_t dst = (uint32_t)__cvta_generic_to_shared(sB + j * SBS + q * 4);
                    CP16(dst, src + q * 4);
                }
                if (l8 == 0) {
                    uint32_t dst = (uint32_t)__cvta_generic_to_shared(sB + j * SBS + 128);
                    CP16(dst, src + 128);
                }
            } else {
                for (int t = l8; t < 128; t += 8) {
                    int gm = t0 + t;
                    float v = ((gm & (T_ - 1)) >= d) ? zrow[gm - d] : 0.f;
                    sB[j * SBS + r + t] = __float_as_uint(v);
                }
            }
        }
    }
}

template <int MODE>
__global__ __launch_bounds__(256) void k_gemm(const float* __restrict__ bias,
                                              float* __restrict__ dout) {
    extern __shared__ unsigned sm[];
    constexpr int KS = (MODE == 0) ? 80 : 8;
    int tid = threadIdx.x, warp = tid >> 5, lane = tid & 31;
    int grp = lane >> 2, tig = lane & 3;
    int t0 = blockIdx.x * 128;
    int m_off = (warp >> 1) * 64;
    int n_off = (warp & 1) * 64;

    float acc[4][8][4];
#pragma unroll
    for (int mf = 0; mf < 4; mf++)
#pragma unroll
        for (int nf = 0; nf < 8; nf++)
#pragma unroll
            for (int q = 0; q < 4; q++) acc[mf][nf][q] = 0.f;

    stage_step<MODE>(sm, 0, 0, t0, tid);
    CPCOMMIT();

    int buf = 0;
#pragma unroll 1
    for (int s = 0; s < KS; s++) {
        if (s + 1 < KS) {
            stage_step<MODE>(sm, buf ^ 1, s + 1, t0, tid);
            CPCOMMIT();
            CPWAIT1();
        } else {
            CPWAIT0();
        }
        __syncthreads();

        unsigned* sA = sm + buf * BUFW;
        unsigned* sB = sm + buf * BUFW + 32 * SAS;
        int roff = 0;
        if (MODE == 0 && !(s & 1)) {
            int d = 1 << ((s >> 1) % LAYERS_);
            roff = (4 - (d & 3)) & 3;
        }
#pragma unroll
        for (int kc = 0; kc < 32; kc += 8) {
            unsigned a[4][4], b[8][2];
#pragma unroll
            for (int mf = 0; mf < 4; mf++) {
                int r0 = m_off + mf * 16 + grp;
                a[mf][0] = sA[(kc + tig) * SAS + r0];
                a[mf][1] = sA[(kc + tig) * SAS + r0 + 8];
                a[mf][2] = sA[(kc + tig + 4) * SAS + r0];
                a[mf][3] = sA[(kc + tig + 4) * SAS + r0 + 8];
            }
#pragma unroll
            for (int nf = 0; nf < 8; nf++) {
                int ci = n_off + nf * 8 + grp + roff;
                b[nf][0] = sB[(kc + tig) * SBS + ci];
                b[nf][1] = sB[(kc + tig + 4) * SBS + ci];
            }
#pragma unroll
            for (int mf = 0; mf < 4; mf++)
#pragma unroll
                for (int nf = 0; nf < 8; nf++) mma8(acc[mf][nf], a[mf], b[nf]);
        }
        __syncthreads();
        buf ^= 1;
    }

    const float* bp = (MODE == 0) ? g_skipb : bias;

    if (MODE != 2) {
        float* out = (MODE == 0) ? g_skip : g_out1;
#pragma unroll
        for (int mf = 0; mf < 4; mf++)
#pragma unroll
            for (int nf = 0; nf < 8; nf++) {
                int row0 = m_off + mf * 16 + grp;
                int col = t0 + n_off + nf * 8 + 2 * tig;
                float b0 = bp[row0];
                float b1 = bp[row0 + 8];
                float2 v0 = make_float2(rtf(fmaxf(acc[mf][nf][0] + b0, 0.f)),
                                        rtf(fmaxf(acc[mf][nf][1] + b0, 0.f)));
                float2 v1 = make_float2(rtf(fmaxf(acc[mf][nf][2] + b1, 0.f)),
                                        rtf(fmaxf(acc[mf][nf][3] + b1, 0.f)));
                *(float2*)&out[(size_t)row0 * BT_ + col] = v0;
                *(float2*)&out[(size_t)(row0 + 8) * BT_ + col] = v1;
            }
    } else {
        float* ts = (float*)sm;  // [64 tok][260]
#pragma unroll 1
        for (int h = 0; h < 2; h++) {
            __syncthreads();
            if ((warp & 1) == h) {
#pragma unroll
                for (int mf = 0; mf < 4; mf++)
#pragma unroll
                    for (int nf = 0; nf < 8; nf++) {
                        int rowL = m_off + mf * 16 + grp;
                        int colL = nf * 8 + 2 * tig;  // 0..63
                        float b0 = bp[rowL];
                        float b1 = bp[rowL + 8];
                        ts[colL * 260 + rowL] = acc[mf][nf][0] + b0;
                        ts[(colL + 1) * 260 + rowL] = acc[mf][nf][1] + b0;
                        ts[colL * 260 + rowL + 8] = acc[mf][nf][2] + b1;
                        ts[(colL + 1) * 260 + rowL + 8] = acc[mf][nf][3] + b1;
                    }
            }
            __syncthreads();
#pragma unroll
            for (int i = 0; i < 16; i++) {
                int q = tid + i * 256;
                int tk = q >> 6, c4 = (q & 63) * 4;
                float4 v = *(const float4*)&ts[tk * 260 + c4];
                *(float4*)&dout[(size_t)(t0 + h * 64 + tk) * 256 + c4] = v;
            }
        }
    }
}

// ---------------- host launcher ----------------
extern "C" void kernel_launch(void* const* d_in, const int* in_sizes, int n_in,
                              void* d_out, int out_size) {
    const float* x      = (const float*)d_in[0];
    const float* w_in   = (const float*)d_in[1];
    const float* b_in   = (const float*)d_in[2];
    const float* filt_w = (const float*)d_in[3];
    const float* filt_b = (const float*)d_in[4];
    const float* gate_w = (const float*)d_in[5];
    const float* gate_b = (const float*)d_in[6];
    const float* res_w  = (const float*)d_in[7];
    const float* res_b  = (const float*)d_in[8];
    const float* skip_w = (const float*)d_in[9];
    const float* skip_b = (const float*)d_in[10];
    const float* end1_w = (const float*)d_in[11];
    const float* end1_b = (const float*)d_in[12];
    const float* end2_w = (const float*)d_in[13];
    const float* end2_b = (const float*)d_in[14];
    float* out = (float*)d_out;

    const int SMEM = 25600 * 4;   // GEMM: 102,400 B dynamic
    cudaFuncSetAttribute(k_gemm<0>, cudaFuncAttributeMaxDynamicSharedMemorySize, SMEM);
    cudaFuncSetAttribute(k_gemm<1>, cudaFuncAttributeMaxDynamicSharedMemorySize, SMEM);
    cudaFuncSetAttribute(k_gemm<2>, cudaFuncAttributeMaxDynamicSharedMemorySize, SMEM);

#define SETATTR(D) \
    cudaFuncSetAttribute(k_z<D>,   cudaFuncAttributeMaxDynamicSharedMemorySize, (4096 + 32 * wsof(D)) * 4); \
    cudaFuncSetAttribute(k_res<D>, cudaFuncAttributeMaxDynamicSharedMemorySize, (2048 + 32 * wsof(D)) * 4);
    SETATTR(1) SETATTR(2) SETATTR(4) SETATTR(8) SETATTR(16)
    SETATTR(32) SETATTR(64) SETATTR(128) SETATTR(256) SETATTR(512)
#undef SETATTR

    k_bias<<<1, 256>>>(skip_b);
    k_pack<<<4032, 256>>>(skip_w, end1_w, end2_w, filt_w, gate_w, res_w);
    k_input<<<BT_ / 512, 256>>>(x, w_in, b_in);

#define LAYER(D) { \
        const int smz = (4096 + 32 * wsof(D)) * 4; \
        const int smr = (2048 + 32 * wsof(D)) * 4; \
        k_z<D><<<BT_ / 256, 256, smz>>>(filt_b, gate_b, i); \
        k_res<D><<<BT_ / 256, 256, smr>>>(res_b, i); }

    for (int i = 0; i < NL_; i++) {
        switch (i % LAYERS_) {
            case 0: LAYER(1)   break;
            case 1: LAYER(2)   break;
            case 2: LAYER(4)   break;
            case 3: LAYER(8)   break;
            case 4: LAYER(16)  break;
            case 5: LAYER(32)  break;
            case 6: LAYER(64)  break;
            case 7: LAYER(128) break;
            case 8: LAYER(256) break;
            case 9: LAYER(512) break;
        }
    }
#undef LAYER

    k_gemm<0><<<BT_ / 128, 256, SMEM>>>(nullptr, nullptr);
    k_gemm<1><<<BT_ / 128, 256, SMEM>>>(end1_b, nullptr);
    k_gemm<2><<<BT_ / 128, 256, SMEM>>>(end2_b, out);
}

// round 13
// speedup vs baseline: 1.8391x; 1.0112x over previous
#include <cuda_runtime.h>
#include <cuda_bf16.h>
#include <stdint.h>
#include <math.h>

#define LAYERS_   10
#define NL_       40
#define RC_       32
#define DC_       32
#define SC_       256
#define EC_       256
#define CL_       256
#define B_        8
#define T_        16384
#define BT_       131072   /* B_*T_ */

typedef unsigned long long u64;

// ---------------- scratch (static device globals; no allocations) -------------
__device__ float g_hA[32 * BT_];                      // residual state ping
__device__ float g_hB[32 * BT_];                      // residual state pong
__device__ float g_z[167772160];                      // 40*32*BT, [layer][c][BT] (tf32-rounded)
__device__ float g_skip[SC_ * BT_];                   // [c][BT]  relu(skip), tf32-rounded
__device__ float g_out1[EC_ * BT_];                   // [c][BT]  relu(out1), tf32-rounded
__device__ float g_skipb[SC_];
__device__ unsigned g_wA[786432];                     // packed tf32 weights, K-major (GEMMs)
__device__ unsigned g_wZ[163840];                     // k_z mma weights [layer][64k][64m] xor-swizzled
__device__ unsigned g_wR[81920];                      // k_res mma weights [layer][64k][32m] xor-swizzled

#define WOFF_SKIP 0
#define WOFF_E1   655360
#define WOFF_E2   720896

// ---------------- small helpers ----------------
__device__ __forceinline__ unsigned f2tf(float x) {
    unsigned r;
    asm("cvt.rna.tf32.f32 %0, %1;" : "=r"(r) : "f"(x));
    return r;
}
__device__ __forceinline__ float rtf(float x) {      // RN-round to tf32, as float
    return __uint_as_float(f2tf(x));
}
__device__ __forceinline__ void mma8(float* d, const unsigned* a, const unsigned* b) {
    asm volatile(
        "mma.sync.aligned.m16n8k8.row.col.f32.tf32.tf32.f32 "
        "{%0,%1,%2,%3},{%4,%5,%6,%7},{%8,%9},{%0,%1,%2,%3};\n"
        : "+f"(d[0]), "+f"(d[1]), "+f"(d[2]), "+f"(d[3])
        : "r"(a[0]), "r"(a[1]), "r"(a[2]), "r"(a[3]), "r"(b[0]), "r"(b[1]));
}
__device__ __forceinline__ void fma2(u64& d, u64 a, u64 b) {
    asm("fma.rn.f32x2 %0, %1, %2, %0;" : "+l"(d) : "l"(a), "l"(b));
}
__device__ __forceinline__ u64 dup2(float x) {
    u64 r; unsigned xi = __float_as_uint(x);
    asm("mov.b64 %0, {%1, %1};" : "=l"(r) : "r"(xi));
    return r;
}
__device__ __forceinline__ float2 unpk(u64 v) {
    unsigned lo, hi;
    asm("mov.b64 {%0, %1}, %2;" : "=r"(lo), "=r"(hi) : "l"(v));
    return make_float2(__uint_as_float(lo), __uint_as_float(hi));
}
// 3-MUFU activation: tanh(f)*sigmoid(g), tf32-rounded
__device__ __forceinline__ float act_z(float fx, float gx) {
    float a = __expf(-2.f * fabsf(fx));
    float b = __expf(-gx);
    float den = (1.f + a) * (1.f + b);
    float r;
    asm("rcp.approx.f32 %0, %1;" : "=f"(r) : "f"(den));
    return rtf(copysignf((1.f - a) * r, fx));
}

#define CP16(dst, src) asm volatile("cp.async.cg.shared.global [%0], [%1], 16;\n" :: "r"(dst), "l"(src))
#define CP16Z(dst, src, n) asm volatile("cp.async.cg.shared.global [%0], [%1], 16, %2;\n" :: "r"(dst), "l"(src), "r"(n))
#define CPCOMMIT()     asm volatile("cp.async.commit_group;\n")
#define CPWAIT1()      asm volatile("cp.async.wait_group 1;\n" ::: "memory")
#define CPWAIT0()      asm volatile("cp.async.wait_group 0;\n" ::: "memory")

// single extern-shared symbol for the whole TU (consistent type everywhere)
extern __shared__ float g_smem[];

// ---------------- bias reduction for skip ----------------
__global__ void k_bias(const float* __restrict__ skip_b) {
    int o = threadIdx.x;
    float s = 0.f;
#pragma unroll 1
    for (int i = 0; i < NL_; i++) s += skip_b[i * SC_ + o];
    g_skipb[o] = s;
}

// ---------------- pack all weights as tf32 ----------------
__global__ void k_pack(const float* __restrict__ skip_w,
                       const float* __restrict__ e1w,
                       const float* __restrict__ e2w,
                       const float* __restrict__ filt_w,
                       const float* __restrict__ gate_w,
                       const float* __restrict__ res_w) {
    int idx = blockIdx.x * 256 + threadIdx.x;
    if (idx < WOFF_E1) {
        int k = idx >> 8, m = idx & 255;
        int li = k >> 6, tap = (k >> 5) & 1, c = k & 31;
        g_wA[idx] = f2tf(skip_w[((size_t)(li * 256 + m) * 32 + c) * 2 + tap]);
    } else if (idx < WOFF_E2) {
        int local = idx - WOFF_E1;
        int k = local >> 8, m = local & 255;
        g_wA[idx] = f2tf(e1w[m * 256 + k]);
    } else if (idx < 786432) {
        int local = idx - WOFF_E2;
        int k = local >> 8, m = local & 255;
        g_wA[idx] = f2tf(e2w[m * 256 + k]);
    } else if (idx < 786432 + 163840) {
        int local = idx - 786432;
        int layer = local >> 12;
        int rem = local & 4095;
        int k = rem >> 6, mx = rem & 63;
        int m = mx ^ ((k & 3) << 3);
        int c = k & 31, tap = k >> 5;
        int o = ((m >> 4) << 3) + (m & 7);
        int isg = (m >> 3) & 1;
        const float* w = isg ? gate_w : filt_w;
        g_wZ[local] = f2tf(w[layer * 2048 + o * 64 + c * 2 + tap]);
    } else if (idx < 786432 + 163840 + 81920) {
        int local = idx - 786432 - 163840;
        int layer = local >> 11;
        int rem = local & 2047;
        int k = rem >> 5, mx = rem & 31;
        int m = mx ^ ((k & 3) << 3);
        int c = k & 31, tap = k >> 5;
        g_wR[local] = f2tf(res_w[layer * 2048 + m * 64 + c * 2 + tap]);
    }
}

// ---------------- input 1x1 conv (fma2): x[8,256,16384] -> g_hA ---------------
__global__ __launch_bounds__(256, 2) void k_input(const float* __restrict__ x,
                                                  const float* __restrict__ w_in,
                                                  const float* __restrict__ b_in) {
    __shared__ __align__(16) float ws[256 * 32];   // [c][o]
    __shared__ float bs[32];
    int tid = threadIdx.x;
    for (int e = tid; e < 256 * 32; e += 256) {
        int c = e >> 5, rc = e & 31;
        ws[e] = w_in[rc * 256 + c];
    }
    if (tid < 32) bs[tid] = b_in[tid];
    __syncthreads();

    int i0 = blockIdx.x * 512 + tid * 2;
    int b0 = i0 >> 14, t0 = i0 & (T_ - 1);
    const float* xb = x + (size_t)b0 * 256 * T_ + t0;

    u64 a0[16], a1[16];
#pragma unroll
    for (int p = 0; p < 16; p++) { a0[p] = 0; a1[p] = 0; }

    float2 xv = *(const float2*)xb;
#pragma unroll 4
    for (int c = 0; c < 256; c++) {
        int cn = (c < 255) ? c + 1 : 255;
        float2 nxv = *(const float2*)(xb + (size_t)cn * T_);
        u64 xl = dup2(xv.x), xh = dup2(xv.y);
        const ulonglong2* w = (const ulonglong2*)&ws[c * 32];
#pragma unroll
        for (int q = 0; q < 8; q++) {
            ulonglong2 wp = w[q];
            fma2(a0[2 * q], wp.x, xl);     fma2(a0[2 * q + 1], wp.y, xl);
            fma2(a1[2 * q], wp.x, xh);     fma2(a1[2 * q + 1], wp.y, xh);
        }
        xv = nxv;
    }
#pragma unroll
    for (int p = 0; p < 16; p++) {
        int o0 = 2 * p, o1 = o0 + 1;
        float2 vl = unpk(a0[p]);
        float2 vh = unpk(a1[p]);
        float bb0 = bs[o0], bb1 = bs[o1];
        *(float2*)(g_hA + (size_t)o0 * BT_ + i0) = make_float2(vl.x + bb0, vh.x + bb0);
        *(float2*)(g_hA + (size_t)o1 * BT_ + i0) = make_float2(vl.y + bb1, vh.y + bb1);
    }
}

// host/device constexpr geometry
__host__ __device__ constexpr int padof(int d) { return (d + 3) & ~3; }
__host__ __device__ constexpr int wsof(int d) {
    int w = 256 + padof(d);
    int ws = w + ((8 - (w & 31)) & 31);
    return ws == 776 ? 772 : ws;   // d=512: fit occ 2
}
// fused geometry: h halo offset + widths
__host__ __device__ constexpr int hoffof(int d) { return padof(64 + d); }
__host__ __device__ constexpr int wshof(int d) {
    int w = 256 + hoffof(d);
    return w + ((8 - (w & 31)) & 31);
}
#define WSZ 328   /* z smem tile row stride: 320 tokens + 8 pad */

// ---------------- stage channels [c0,c0+16) of halo tile (compile-time PAD/WS)
template <int PAD, int WS>
__device__ __forceinline__ void stage_halo(float* tile, const float* __restrict__ base,
                                           int t0, int t0m, int c0, int tid) {
    constexpr int NCH = (256 + PAD) >> 2;     // 16B chunks per row
    int c = c0 + (tid >> 4);                   // 16 threads per channel, 16 channels
    int j0 = tid & 15;
    const float* rowp = base + (size_t)c * BT_;
    float* srow = tile + c * WS;
#pragma unroll 1
    for (int j = j0; j < NCH; j += 16) {
        bool v = (t0m + 4 * j) >= PAD;
        const float* src = v ? (rowp + (t0 - PAD + 4 * j)) : rowp;
        uint32_t dst = (uint32_t)__cvta_generic_to_shared(srow + 4 * j);
        CP16Z(dst, src, v ? 16u : 0u);
    }
}

// ============ FUSED k_zr<D> (D<=64): z=tanh*sig over halo, then h+=conv(z) ====
// z computed for [t0-64, t0+256) (N=320, warp n-tile 40) into smem (aliasing h
// tile after sync); res mma (M=32,K=64,N=256) off the smem z; ping-pong h.
template <int D>
__global__ __launch_bounds__(256, 2) void k_zr(const float* __restrict__ filt_b,
                                               const float* __restrict__ gate_b,
                                               const float* __restrict__ res_b,
                                               int layer, int cur) {
    constexpr int HOFF = hoffof(D);
    constexpr int WSH = wshof(D);
    float* smf = g_smem;
    unsigned* zA = (unsigned*)smf;            // 4096 words
    unsigned* rA = (unsigned*)smf + 4096;     // 2048 words
    float* tile = smf + 6144;                 // h tile 32 x WSH; later z tile 32 x WSZ

    int tid = threadIdx.x;
    int t0 = blockIdx.x * 256;
    int t0m = t0 & (T_ - 1);
    const float* hin = cur ? g_hB : g_hA;
    float* hout = cur ? g_hA : g_hB;

    // stage weights + h halo (split halves for pipelining)
    {
        const unsigned* za = g_wZ + layer * 4096;
#pragma unroll
        for (int i = 0; i < 4; i++) {
            int q = (tid + i * 256) * 4;
            CP16((uint32_t)__cvta_generic_to_shared(zA + q), za + q);
        }
        const unsigned* ra = g_wR + layer * 2048;
#pragma unroll
        for (int i = 0; i < 2; i++) {
            int q = (tid + i * 256) * 4;
            CP16((uint32_t)__cvta_generic_to_shared(rA + q), ra + q);
        }
    }
    stage_halo<HOFF, WSH>(tile, hin, t0, t0m, 0, tid);
    CPCOMMIT();
    stage_halo<HOFF, WSH>(tile, hin, t0, t0m, 16, tid);
    CPCOMMIT();

    int warp = tid >> 5, lane = tid & 31;
    int grp = lane >> 2, tig = lane & 3;
    int xkey = tig << 3;

    // ---------- phase A: z mma, N=320, warp n-tile 40 ----------
    float acc[4][5][4];
#pragma unroll
    for (int mf = 0; mf < 4; mf++)
#pragma unroll
        for (int nf = 0; nf < 5; nf++)
#pragma unroll
            for (int q = 0; q < 4; q++) acc[mf][nf][q] = 0.f;

    CPWAIT1();
    __syncthreads();

#pragma unroll
    for (int phase = 0; phase < 2; phase++) {
#pragma unroll
        for (int tap = 0; tap < 2; tap++) {
#pragma unroll
            for (int kk = 0; kk < 2; kk++) {
                const int cb = phase * 16 + kk * 8;
                const int kc = tap * 32 + cb;
                const int off = tap ? (HOFF - 64) : (HOFF - 64 - D);
                unsigned a[4][4];
#pragma unroll
                for (int mf = 0; mf < 4; mf++) {
                    int m0 = mf * 16 + grp;
                    a[mf][0] = zA[(kc + tig) * 64 + (m0 ^ xkey)];
                    a[mf][1] = zA[(kc + tig) * 64 + ((m0 + 8) ^ xkey)];
                    a[mf][2] = zA[(kc + tig + 4) * 64 + (m0 ^ xkey)];
                    a[mf][3] = zA[(kc + tig + 4) * 64 + ((m0 + 8) ^ xkey)];
                }
                unsigned b[5][2];
#pragma unroll
                for (int nf = 0; nf < 5; nf++) {
                    int n = warp * 40 + nf * 8 + grp;
                    b[nf][0] = f2tf(tile[(cb + tig) * WSH + off + n]);
                    b[nf][1] = f2tf(tile[(cb + tig + 4) * WSH + off + n]);
                }
#pragma unroll
                for (int mf = 0; mf < 4; mf++)
#pragma unroll
                    for (int nf = 0; nf < 5; nf++) mma8(acc[mf][nf], a[mf], b[nf]);
            }
        }
        if (phase == 0) {
            CPWAIT0();
            __syncthreads();
        }
    }

    // all h-tile reads done; overwrite tile with z
    __syncthreads();
#pragma unroll
    for (int mf = 0; mf < 4; mf++) {
        int o = mf * 8 + grp;
        float fbv = __ldg(filt_b + layer * 32 + o);
        float gbv = __ldg(gate_b + layer * 32 + o);
        float* zrow = g_z + ((size_t)layer * 32 + o) * BT_ + t0;
#pragma unroll
        for (int nf = 0; nf < 5; nf++) {
            int p = warp * 40 + nf * 8 + 2 * tig;   // 0..318, even
            float2 zv;
            zv.x = act_z(acc[mf][nf][0] + fbv, acc[mf][nf][2] + gbv);
            zv.y = act_z(acc[mf][nf][1] + fbv, acc[mf][nf][3] + gbv);
            if (t0m == 0 && p < 64) { zv.x = 0.f; zv.y = 0.f; }  // causal zero before batch start
            *(float2*)(tile + o * WSZ + p) = zv;
            if (p >= 64) *(float2*)(zrow + p - 64) = zv;
        }
    }
    __syncthreads();

    // ---------- phase B: res mma, M=32, N=256 off smem z ----------
    float acr[2][4][4];
#pragma unroll
    for (int mf = 0; mf < 2; mf++)
#pragma unroll
        for (int nf = 0; nf < 4; nf++)
#pragma unroll
            for (int q = 0; q < 4; q++) acr[mf][nf][q] = 0.f;

#pragma unroll
    for (int tap = 0; tap < 2; tap++) {
#pragma unroll
        for (int kk = 0; kk < 4; kk++) {
            const int cb = kk * 8;
            const int kc = tap * 32 + cb;
            const int off = tap ? 64 : (64 - D);
            unsigned a[2][4];
#pragma unroll
            for (int mf = 0; mf < 2; mf++) {
                int m0 = mf * 16 + grp;
                a[mf][0] = rA[(kc + tig) * 32 + (m0 ^ xkey)];
                a[mf][1] = rA[(kc + tig) * 32 + ((m0 + 8) ^ xkey)];
                a[mf][2] = rA[(kc + tig + 4) * 32 + (m0 ^ xkey)];
                a[mf][3] = rA[(kc + tig + 4) * 32 + ((m0 + 8) ^ xkey)];
            }
            unsigned b[4][2];
#pragma unroll
            for (int nf = 0; nf < 4; nf++) {
                int n = warp * 32 + nf * 8 + grp;
                b[nf][0] = __float_as_uint(tile[(cb + tig) * WSZ + off + n]);
                b[nf][1] = __float_as_uint(tile[(cb + tig + 4) * WSZ + off + n]);
            }
#pragma unroll
            for (int mf = 0; mf < 2; mf++)
#pragma unroll
                for (int nf = 0; nf < 4; nf++) mma8(acr[mf][nf], a[mf], b[nf]);
        }
    }

#pragma unroll
    for (int mf = 0; mf < 2; mf++) {
        int o = mf * 16 + grp;
        float b0 = __ldg(res_b + layer * 32 + o);
        float b1 = __ldg(res_b + layer * 32 + o + 8);
        const float* in0 = hin + (size_t)o * BT_ + t0;
        const float* in1 = hin + (size_t)(o + 8) * BT_ + t0;
        float* out0 = hout + (size_t)o * BT_ + t0;
        float* out1 = hout + (size_t)(o + 8) * BT_ + t0;
#pragma unroll
        for (int nf = 0; nf < 4; nf++) {
            int col = warp * 32 + nf * 8 + 2 * tig;
            float2 h0 = *(const float2*)(in0 + col);
            float2 h1 = *(const float2*)(in1 + col);
            h0.x += acr[mf][nf][0] + b0;
            h0.y += acr[mf][nf][1] + b0;
            h1.x += acr[mf][nf][2] + b1;
            h1.y += acr[mf][nf][3] + b1;
            *(float2*)(out0 + col) = h0;
            *(float2*)(out1 + col) = h1;
        }
    }
}

// ---------------- k_z<D> (mma, unfused; d>=128) ----------------
template <int D>
__global__ __launch_bounds__(256, 2) void k_z(const float* __restrict__ filt_b,
                                              const float* __restrict__ gate_b,
                                              int layer, int cur) {
    constexpr int PAD = padof(D);
    constexpr int WS = wsof(D);
    float* smz = g_smem;
    unsigned* sA = (unsigned*)smz;      // 4096 words
    float* tile = smz + 4096;           // 32 x WS

    int tid = threadIdx.x;
    int t0 = blockIdx.x * 256;
    int t0m = t0 & (T_ - 1);
    const float* hin = cur ? g_hB : g_hA;

    {
        const unsigned* asrc = g_wZ + layer * 4096;
#pragma unroll
        for (int i = 0; i < 4; i++) {
            int q = (tid + i * 256) * 4;
            CP16((uint32_t)__cvta_generic_to_shared(sA + q), asrc + q);
        }
    }
    stage_halo<PAD, WS>(tile, hin, t0, t0m, 0, tid);
    CPCOMMIT();
    stage_halo<PAD, WS>(tile, hin, t0, t0m, 16, tid);
    CPCOMMIT();

    int warp = tid >> 5, lane = tid & 31;
    int grp = lane >> 2, tig = lane & 3;
    int n_off = warp * 32;
    int xkey = tig << 3;

    float acc[4][4][4];
#pragma unroll
    for (int mf = 0; mf < 4; mf++)
#pragma unroll
        for (int nf = 0; nf < 4; nf++)
#pragma unroll
            for (int q = 0; q < 4; q++) acc[mf][nf][q] = 0.f;

    CPWAIT1();
    __syncthreads();

#pragma unroll
    for (int phase = 0; phase < 2; phase++) {
#pragma unroll
        for (int tap = 0; tap < 2; tap++) {
#pragma unroll
            for (int kk = 0; kk < 2; kk++) {
                const int cb = phase * 16 + kk * 8;
                const int kc = tap * 32 + cb;
                const int off = tap ? PAD : (PAD - D);
                unsigned a[4][4];
#pragma unroll
                for (int mf = 0; mf < 4; mf++) {
                    int m0 = mf * 16 + grp;
                    a[mf][0] = sA[(kc + tig) * 64 + (m0 ^ xkey)];
                    a[mf][1] = sA[(kc + tig) * 64 + ((m0 + 8) ^ xkey)];
                    a[mf][2] = sA[(kc + tig + 4) * 64 + (m0 ^ xkey)];
                    a[mf][3] = sA[(kc + tig + 4) * 64 + ((m0 + 8) ^ xkey)];
                }
                unsigned b[4][2];
#pragma unroll
                for (int nf = 0; nf < 4; nf++) {
                    int n = n_off + nf * 8 + grp;
                    b[nf][0] = f2tf(tile[(cb + tig) * WS + off + n]);
                    b[nf][1] = f2tf(tile[(cb + tig + 4) * WS + off + n]);
                }
#pragma unroll
                for (int mf = 0; mf < 4; mf++)
#pragma unroll
                    for (int nf = 0; nf < 4; nf++) mma8(acc[mf][nf], a[mf], b[nf]);
            }
        }
        if (phase == 0) {
            CPWAIT0();
            __syncthreads();
        }
    }

#pragma unroll
    for (int mf = 0; mf < 4; mf++) {
        int o = mf * 8 + grp;
        float fbv = __ldg(filt_b + layer * 32 + o);
        float gbv = __ldg(gate_b + layer * 32 + o);
        float* zrow = g_z + ((size_t)layer * 32 + o) * BT_ + t0;
#pragma unroll
        for (int nf = 0; nf < 4; nf++) {
            int col = n_off + nf * 8 + 2 * tig;
            float2 zv;
            zv.x = act_z(acc[mf][nf][0] + fbv, acc[mf][nf][2] + gbv);
            zv.y = act_z(acc[mf][nf][1] + fbv, acc[mf][nf][3] + gbv);
            *(float2*)(zrow + col) = zv;
        }
    }
}

// ---------------- k_res<D> (mma, unfused; d>=128): hout = hin + conv(z) ------
template <int D>
__global__ __launch_bounds__(256, 2) void k_res(const float* __restrict__ res_b,
                                                int layer, int cur) {
    constexpr int PAD = padof(D);
    constexpr int WS = wsof(D);
    float* smr = g_smem;
    unsigned* sR = (unsigned*)smr;      // 2048 words
    float* tile = smr + 2048;           // 32 x WS

    int tid = threadIdx.x;
    int t0 = blockIdx.x * 256;
    int t0m = t0 & (T_ - 1);
    const float* zL = g_z + (size_t)layer * 32 * BT_;
    const float* hin = cur ? g_hB : g_hA;
    float* hout = cur ? g_hA : g_hB;

    {
        const unsigned* asrc = g_wR + layer * 2048;
#pragma unroll
        for (int i = 0; i < 2; i++) {
            int q = (tid + i * 256) * 4;
            CP16((uint32_t)__cvta_generic_to_shared(sR + q), asrc + q);
        }
    }
    stage_halo<PAD, WS>(tile, zL, t0, t0m, 0, tid);
    CPCOMMIT();
    stage_halo<PAD, WS>(tile, zL, t0, t0m, 16, tid);
    CPCOMMIT();

    int warp = tid >> 5, lane = tid & 31;
    int grp = lane >> 2, tig = lane & 3;
    int n_off = warp * 32;
    int xkey = tig << 3;

    float acc[2][4][4];
#pragma unroll
    for (int mf = 0; mf < 2; mf++)
#pragma unroll
        for (int nf = 0; nf < 4; nf++)
#pragma unroll
            for (int q = 0; q < 4; q++) acc[mf][nf][q] = 0.f;

    CPWAIT1();
    __syncthreads();

#pragma unroll
    for (int phase = 0; phase < 2; phase++) {
#pragma unroll
        for (int tap = 0; tap < 2; tap++) {
#pragma unroll
            for (int kk = 0; kk < 2; kk++) {
                const int cb = phase * 16 + kk * 8;
                const int kc = tap * 32 + cb;
                const int off = tap ? PAD : (PAD - D);
                unsigned a[2][4];
#pragma unroll
                for (int mf = 0; mf < 2; mf++) {
                    int m0 = mf * 16 + grp;
                    a[mf][0] = sR[(kc + tig) * 32 + (m0 ^ xkey)];
                    a[mf][1] = sR[(kc + tig) * 32 + ((m0 + 8) ^ xkey)];
                    a[mf][2] = sR[(kc + tig + 4) * 32 + (m0 ^ xkey)];
                    a[mf][3] = sR[(kc + tig + 4) * 32 + ((m0 + 8) ^ xkey)];
                }
                unsigned b[4][2];
#pragma unroll
                for (int nf = 0; nf < 4; nf++) {
                    int n = n_off + nf * 8 + grp;
                    b[nf][0] = __float_as_uint(tile[(cb + tig) * WS + off + n]);
                    b[nf][1] = __float_as_uint(tile[(cb + tig + 4) * WS + off + n]);
                }
#pragma unroll
                for (int mf = 0; mf < 2; mf++)
#pragma unroll
                    for (int nf = 0; nf < 4; nf++) mma8(acc[mf][nf], a[mf], b[nf]);
            }
        }
        if (phase == 0) {
            CPWAIT0();
            __syncthreads();
        }
    }

#pragma unroll
    for (int mf = 0; mf < 2; mf++) {
        int o = mf * 16 + grp;
        float b0 = __ldg(res_b + layer * 32 + o);
        float b1 = __ldg(res_b + layer * 32 + o + 8);
        const float* in0 = hin + (size_t)o * BT_ + t0;
        const float* in1 = hin + (size_t)(o + 8) * BT_ + t0;
        float* out0 = hout + (size_t)o * BT_ + t0;
        float* out1 = hout + (size_t)(o + 8) * BT_ + t0;
#pragma unroll
        for (int nf = 0; nf < 4; nf++) {
            int col = n_off + nf * 8 + 2 * tig;
            float2 h0 = *(const float2*)(in0 + col);
            float2 h1 = *(const float2*)(in1 + col);
            h0.x += acc[mf][nf][0] + b0;
            h0.y += acc[mf][nf][1] + b0;
            h1.x += acc[mf][nf][2] + b1;
            h1.y += acc[mf][nf][3] + b1;
            *(float2*)(out0 + col) = h0;
            *(float2*)(out1 + col) = h1;
        }
    }
}

// ================== unified tf32 GEMM (cp.async staged, double buffered) =====
#define SAS 264
#define SBS 136
#define BUFW 12800

template <int MODE>
__device__ __forceinline__ void stage_step(unsigned* sm, int buf, int s, int t0, int tid) {
    unsigned* sA = sm + buf * BUFW;
    unsigned* sB = sm + buf * BUFW + 32 * SAS;
    const unsigned* asrc = g_wA + (MODE == 0 ? WOFF_SKIP : (MODE == 1 ? WOFF_E1 : WOFF_E2))
                         + (size_t)s * 32 * 256;
#pragma unroll
    for (int i = 0; i < 8; i++) {
        int q = tid + i * 256;
        int row = q >> 6, col = (q & 63) * 4;
        uint32_t dst = (uint32_t)__cvta_generic_to_shared(sA + row * SAS + col);
        CP16(dst, asrc + row * 256 + col);
    }
    if (MODE != 0) {
        const float* gB = (MODE == 1) ? g_skip : g_out1;
#pragma unroll
        for (int i = 0; i < 4; i++) {
            int q = tid + i * 256;
            int row = q >> 5, col = (q & 31) * 4;
            uint32_t dst = (uint32_t)__cvta_generic_to_shared(sB + row * SBS + col);
            CP16(dst, gB + (size_t)(s * 32 + row) * BT_ + t0 + col);
        }
    } else {
        int li = s >> 1, tap = s & 1;
        int d = 1 << (li % LAYERS_);
        int j = tid >> 3, l8 = tid & 7;
        const float* zrow = g_z + ((size_t)li * 32 + j) * BT_;
        if (tap == 1) {
#pragma unroll
            for (int i = 0; i < 4; i++) {
                int q = l8 + i * 8;
                uint32_t dst = (uint32_t)__cvta_generic_to_shared(sB + j * SBS + q * 4);
                CP16(dst, zrow + t0 + q * 4);
            }
        } else {
            int r = (4 - (d & 3)) & 3;
            int t0m = t0 & (T_ - 1);
            if (t0m >= d + 4) {
                const float* src = zrow + t0 - d - r;
#pragma unroll
                for (int i = 0; i < 4; i++) {
                    int q = l8 + i * 8;
                    uint32_t dst = (uint32_t)__cvta_generic_to_shared(sB + j * SBS + q * 4);
                    CP16(dst, src + q * 4);
                }
                if (l8 == 0) {
                    uint32_t dst = (uint32_t)__cvta_generic_to_shared(sB + j * SBS + 128);
                    CP16(dst, src + 128);
                }
            } else {
                for (int t = l8; t < 128; t += 8) {
                    int gm = t0 + t;
                    float v = ((gm & (T_ - 1)) >= d) ? zrow[gm - d] : 0.f;
                    sB[j * SBS + r + t] = __float_as_uint(v);
                }
            }
        }
    }
}

template <int MODE>
__global__ __launch_bounds__(256) void k_gemm(const float* __restrict__ bias,
                                              float* __restrict__ dout) {
    unsigned* sm = (unsigned*)g_smem;
    constexpr int KS = (MODE == 0) ? 80 : 8;
    int tid = threadIdx.x, warp = tid >> 5, lane = tid & 31;
    int grp = lane >> 2, tig = lane & 3;
    int t0 = blockIdx.x * 128;
    int m_off = (warp >> 1) * 64;
    int n_off = (warp & 1) * 64;

    float acc[4][8][4];
#pragma unroll
    for (int mf = 0; mf < 4; mf++)
#pragma unroll
        for (int nf = 0; nf < 8; nf++)
#pragma unroll
            for (int q = 0; q < 4; q++) acc[mf][nf][q] = 0.f;

    stage_step<MODE>(sm, 0, 0, t0, tid);
    CPCOMMIT();

    int buf = 0;
#pragma unroll 1
    for (int s = 0; s < KS; s++) {
        if (s + 1 < KS) {
            stage_step<MODE>(sm, buf ^ 1, s + 1, t0, tid);
            CPCOMMIT();
            CPWAIT1();
        } else {
            CPWAIT0();
        }
        __syncthreads();

        unsigned* sA = sm + buf * BUFW;
        unsigned* sB = sm + buf * BUFW + 32 * SAS;
        int roff = 0;
        if (MODE == 0 && !(s & 1)) {
            int d = 1 << ((s >> 1) % LAYERS_);
            roff = (4 - (d & 3)) & 3;
        }
#pragma unroll
        for (int kc = 0; kc < 32; kc += 8) {
            unsigned a[4][4], b[8][2];
#pragma unroll
            for (int mf = 0; mf < 4; mf++) {
                int r0 = m_off + mf * 16 + grp;
                a[mf][0] = sA[(kc + tig) * SAS + r0];
                a[mf][1] = sA[(kc + tig) * SAS + r0 + 8];
                a[mf][2] = sA[(kc + tig + 4) * SAS + r0];
                a[mf][3] = sA[(kc + tig + 4) * SAS + r0 + 8];
            }
#pragma unroll
            for (int nf = 0; nf < 8; nf++) {
                int ci = n_off + nf * 8 + grp + roff;
                b[nf][0] = sB[(kc + tig) * SBS + ci];
                b[nf][1] = sB[(kc + tig + 4) * SBS + ci];
            }
#pragma unroll
            for (int mf = 0; mf < 4; mf++)
#pragma unroll
                for (int nf = 0; nf < 8; nf++) mma8(acc[mf][nf], a[mf], b[nf]);
        }
        __syncthreads();
        buf ^= 1;
    }

    const float* bp = (MODE == 0) ? g_skipb : bias;

    if (MODE != 2) {
        float* out = (MODE == 0) ? g_skip : g_out1;
#pragma unroll
        for (int mf = 0; mf < 4; mf++)
#pragma unroll
            for (int nf = 0; nf < 8; nf++) {
                int row0 = m_off + mf * 16 + grp;
                int col = t0 + n_off + nf * 8 + 2 * tig;
                float b0 = bp[row0];
                float b1 = bp[row0 + 8];
                float2 v0 = make_float2(rtf(fmaxf(acc[mf][nf][0] + b0, 0.f)),
                                        rtf(fmaxf(acc[mf][nf][1] + b0, 0.f)));
                float2 v1 = make_float2(rtf(fmaxf(acc[mf][nf][2] + b1, 0.f)),
                                        rtf(fmaxf(acc[mf][nf][3] + b1, 0.f)));
                *(float2*)&out[(size_t)row0 * BT_ + col] = v0;
                *(float2*)&out[(size_t)(row0 + 8) * BT_ + col] = v1;
            }
    } else {
        float* ts = (float*)sm;  // [64 tok][260]
#pragma unroll 1
        for (int h = 0; h < 2; h++) {
            __syncthreads();
            if ((warp & 1) == h) {
#pragma unroll
                for (int mf = 0; mf < 4; mf++)
#pragma unroll
                    for (int nf = 0; nf < 8; nf++) {
                        int rowL = m_off + mf * 16 + grp;
                        int colL = nf * 8 + 2 * tig;  // 0..63
                        float b0 = bp[rowL];
                        float b1 = bp[rowL + 8];
                        ts[colL * 260 + rowL] = acc[mf][nf][0] + b0;
                        ts[(colL + 1) * 260 + rowL] = acc[mf][nf][1] + b0;
                        ts[colL * 260 + rowL + 8] = acc[mf][nf][2] + b1;
                        ts[(colL + 1) * 260 + rowL + 8] = acc[mf][nf][3] + b1;
                    }
            }
            __syncthreads();
#pragma unroll
            for (int i = 0; i < 16; i++) {
                int q = tid + i * 256;
                int tk = q >> 6, c4 = (q & 63) * 4;
                float4 v = *(const float4*)&ts[tk * 260 + c4];
                *(float4*)&dout[(size_t)(t0 + h * 64 + tk) * 256 + c4] = v;
            }
        }
    }
}

// ---------------- host launcher ----------------
extern "C" void kernel_launch(void* const* d_in, const int* in_sizes, int n_in,
                              void* d_out, int out_size) {
    const float* x      = (const float*)d_in[0];
    const float* w_in   = (const float*)d_in[1];
    const float* b_in   = (const float*)d_in[2];
    const float* filt_w = (const float*)d_in[3];
    const float* filt_b = (const float*)d_in[4];
    const float* gate_w = (const float*)d_in[5];
    const float* gate_b = (const float*)d_in[6];
    const float* res_w  = (const float*)d_in[7];
    const float* res_b  = (const float*)d_in[8];
    const float* skip_w = (const float*)d_in[9];
    const float* skip_b = (const float*)d_in[10];
    const float* end1_w = (const float*)d_in[11];
    const float* end1_b = (const float*)d_in[12];
    const float* end2_w = (const float*)d_in[13];
    const float* end2_b = (const float*)d_in[14];
    float* out = (float*)d_out;

    const int SMEM = 25600 * 4;   // GEMM: 102,400 B dynamic
    cudaFuncSetAttribute(k_gemm<0>, cudaFuncAttributeMaxDynamicSharedMemorySize, SMEM);
    cudaFuncSetAttribute(k_gemm<1>, cudaFuncAttributeMaxDynamicSharedMemorySize, SMEM);
    cudaFuncSetAttribute(k_gemm<2>, cudaFuncAttributeMaxDynamicSharedMemorySize, SMEM);

#define SETF(D) \
    cudaFuncSetAttribute(k_zr<D>, cudaFuncAttributeMaxDynamicSharedMemorySize, (6144 + 32 * wshof(D)) * 4);
    SETF(1) SETF(2) SETF(4) SETF(8) SETF(16) SETF(32) SETF(64)
#undef SETF
#define SETU(D) \
    cudaFuncSetAttribute(k_z<D>,   cudaFuncAttributeMaxDynamicSharedMemorySize, (4096 + 32 * wsof(D)) * 4); \
    cudaFuncSetAttribute(k_res<D>, cudaFuncAttributeMaxDynamicSharedMemorySize, (2048 + 32 * wsof(D)) * 4);
    SETU(128) SETU(256) SETU(512)
#undef SETU

    k_bias<<<1, 256>>>(skip_b);
    k_pack<<<4032, 256>>>(skip_w, end1_w, end2_w, filt_w, gate_w, res_w);
    k_input<<<BT_ / 512, 256>>>(x, w_in, b_in);

#define LAYERF(D) { \
        k_zr<D><<<BT_ / 256, 256, (6144 + 32 * wshof(D)) * 4>>>(filt_b, gate_b, res_b, i, cur); }
#define LAYERU(D) { \
        k_z<D><<<BT_ / 256, 256, (4096 + 32 * wsof(D)) * 4>>>(filt_b, gate_b, i, cur); \
        k_res<D><<<BT_ / 256, 256, (2048 + 32 * wsof(D)) * 4>>>(res_b, i, cur); }

    int cur = 0;
    for (int i = 0; i < NL_; i++) {
        switch (i % LAYERS_) {
            case 0: LAYERF(1)   break;
            case 1: LAYERF(2)   break;
            case 2: LAYERF(4)   break;
            case 3: LAYERF(8)   break;
            case 4: LAYERF(16)  break;
            case 5: LAYERF(32)  break;
            case 6: LAYERF(64)  break;
            case 7: LAYERU(128) break;
            case 8: LAYERU(256) break;
            case 9: LAYERU(512) break;
        }
        cur ^= 1;
    }
#undef LAYERF
#undef LAYERU

    k_gemm<0><<<BT_ / 128, 256, SMEM>>>(nullptr, nullptr);
    k_gemm<1><<<BT_ / 128, 256, SMEM>>>(end1_b, nullptr);
    k_gemm<2><<<BT_ / 128, 256, SMEM>>>(end2_b, out);
}

// round 14
// speedup vs baseline: 1.8586x; 1.0106x over previous
#include <cuda_runtime.h>
#include <cuda_bf16.h>
#include <stdint.h>
#include <math.h>

#define LAYERS_   10
#define NL_       40
#define RC_       32
#define DC_       32
#define SC_       256
#define EC_       256
#define CL_       256
#define B_        8
#define T_        16384
#define BT_       131072   /* B_*T_ */

typedef unsigned long long u64;

// ---------------- scratch (static device globals; no allocations) -------------
__device__ float g_hA[32 * BT_];                      // residual state ping
__device__ float g_hB[32 * BT_];                      // residual state pong
__device__ float g_z[167772160];                      // 40*32*BT, [layer][c][BT] (tf32-rounded)
__device__ float g_skip[SC_ * BT_];                   // [c][BT]  relu(skip), tf32-rounded
__device__ float g_out1[EC_ * BT_];                   // [c][BT]  relu(out1), tf32-rounded
__device__ float g_skipb[SC_];
__device__ unsigned g_wA[786432];                     // packed tf32 weights, K-major (GEMMs)
__device__ unsigned g_wZ[163840];                     // k_z mma weights [layer][64k][64m] xor-swizzled
__device__ unsigned g_wR[81920];                      // k_res mma weights [layer][64k][32m] xor-swizzled

#define WOFF_SKIP 0
#define WOFF_E1   655360
#define WOFF_E2   720896

// ---------------- small helpers ----------------
__device__ __forceinline__ unsigned f2tf(float x) {
    unsigned r;
    asm("cvt.rna.tf32.f32 %0, %1;" : "=r"(r) : "f"(x));
    return r;
}
__device__ __forceinline__ float rtf(float x) {      // RN-round to tf32, as float
    return __uint_as_float(f2tf(x));
}
__device__ __forceinline__ void mma8(float* d, const unsigned* a, const unsigned* b) {
    asm volatile(
        "mma.sync.aligned.m16n8k8.row.col.f32.tf32.tf32.f32 "
        "{%0,%1,%2,%3},{%4,%5,%6,%7},{%8,%9},{%0,%1,%2,%3};\n"
        : "+f"(d[0]), "+f"(d[1]), "+f"(d[2]), "+f"(d[3])
        : "r"(a[0]), "r"(a[1]), "r"(a[2]), "r"(a[3]), "r"(b[0]), "r"(b[1]));
}
__device__ __forceinline__ void fma2(u64& d, u64 a, u64 b) {
    asm("fma.rn.f32x2 %0, %1, %2, %0;" : "+l"(d) : "l"(a), "l"(b));
}
__device__ __forceinline__ u64 dup2(float x) {
    u64 r; unsigned xi = __float_as_uint(x);
    asm("mov.b64 %0, {%1, %1};" : "=l"(r) : "r"(xi));
    return r;
}
__device__ __forceinline__ float2 unpk(u64 v) {
    unsigned lo, hi;
    asm("mov.b64 {%0, %1}, %2;" : "=r"(lo), "=r"(hi) : "l"(v));
    return make_float2(__uint_as_float(lo), __uint_as_float(hi));
}
// 3-MUFU activation: tanh(f)*sigmoid(g), tf32-rounded
__device__ __forceinline__ float act_z(float fx, float gx) {
    float a = __expf(-2.f * fabsf(fx));
    float b = __expf(-gx);
    float den = (1.f + a) * (1.f + b);
    float r;
    asm("rcp.approx.f32 %0, %1;" : "=f"(r) : "f"(den));
    return rtf(copysignf((1.f - a) * r, fx));
}

#define CP16(dst, src) asm volatile("cp.async.cg.shared.global [%0], [%1], 16;\n" :: "r"(dst), "l"(src))
#define CP16Z(dst, src, n) asm volatile("cp.async.cg.shared.global [%0], [%1], 16, %2;\n" :: "r"(dst), "l"(src), "r"(n))
#define CPCOMMIT()     asm volatile("cp.async.commit_group;\n")
#define CPWAIT1()      asm volatile("cp.async.wait_group 1;\n" ::: "memory")
#define CPWAIT0()      asm volatile("cp.async.wait_group 0;\n" ::: "memory")

// single extern-shared symbol for the whole TU (consistent type everywhere)
extern __shared__ float g_smem[];

// ---------------- bias reduction for skip ----------------
__global__ void k_bias(const float* __restrict__ skip_b) {
    int o = threadIdx.x;
    float s = 0.f;
#pragma unroll 1
    for (int i = 0; i < NL_; i++) s += skip_b[i * SC_ + o];
    g_skipb[o] = s;
}

// ---------------- pack all weights as tf32 ----------------
__global__ void k_pack(const float* __restrict__ skip_w,
                       const float* __restrict__ e1w,
                       const float* __restrict__ e2w,
                       const float* __restrict__ filt_w,
                       const float* __restrict__ gate_w,
                       const float* __restrict__ res_w) {
    int idx = blockIdx.x * 256 + threadIdx.x;
    if (idx < WOFF_E1) {
        int k = idx >> 8, m = idx & 255;
        int li = k >> 6, tap = (k >> 5) & 1, c = k & 31;
        g_wA[idx] = f2tf(skip_w[((size_t)(li * 256 + m) * 32 + c) * 2 + tap]);
    } else if (idx < WOFF_E2) {
        int local = idx - WOFF_E1;
        int k = local >> 8, m = local & 255;
        g_wA[idx] = f2tf(e1w[m * 256 + k]);
    } else if (idx < 786432) {
        int local = idx - WOFF_E2;
        int k = local >> 8, m = local & 255;
        g_wA[idx] = f2tf(e2w[m * 256 + k]);
    } else if (idx < 786432 + 163840) {
        int local = idx - 786432;
        int layer = local >> 12;
        int rem = local & 4095;
        int k = rem >> 6, mx = rem & 63;
        int m = mx ^ ((k & 3) << 3);
        int c = k & 31, tap = k >> 5;
        int o = ((m >> 4) << 3) + (m & 7);
        int isg = (m >> 3) & 1;
        const float* w = isg ? gate_w : filt_w;
        g_wZ[local] = f2tf(w[layer * 2048 + o * 64 + c * 2 + tap]);
    } else if (idx < 786432 + 163840 + 81920) {
        int local = idx - 786432 - 163840;
        int layer = local >> 11;
        int rem = local & 2047;
        int k = rem >> 5, mx = rem & 31;
        int m = mx ^ ((k & 3) << 3);
        int c = k & 31, tap = k >> 5;
        g_wR[local] = f2tf(res_w[layer * 2048 + m * 64 + c * 2 + tap]);
    }
}

// ---------------- input 1x1 conv (fma2): x[8,256,16384] -> g_hA ---------------
__global__ __launch_bounds__(256, 2) void k_input(const float* __restrict__ x,
                                                  const float* __restrict__ w_in,
                                                  const float* __restrict__ b_in) {
    __shared__ __align__(16) float ws[256 * 32];   // [c][o]
    __shared__ float bs[32];
    int tid = threadIdx.x;
    for (int e = tid; e < 256 * 32; e += 256) {
        int c = e >> 5, rc = e & 31;
        ws[e] = w_in[rc * 256 + c];
    }
    if (tid < 32) bs[tid] = b_in[tid];
    __syncthreads();

    int i0 = blockIdx.x * 512 + tid * 2;
    int b0 = i0 >> 14, t0 = i0 & (T_ - 1);
    const float* xb = x + (size_t)b0 * 256 * T_ + t0;

    u64 a0[16], a1[16];
#pragma unroll
    for (int p = 0; p < 16; p++) { a0[p] = 0; a1[p] = 0; }

    float2 xv = *(const float2*)xb;
#pragma unroll 4
    for (int c = 0; c < 256; c++) {
        int cn = (c < 255) ? c + 1 : 255;
        float2 nxv = *(const float2*)(xb + (size_t)cn * T_);
        u64 xl = dup2(xv.x), xh = dup2(xv.y);
        const ulonglong2* w = (const ulonglong2*)&ws[c * 32];
#pragma unroll
        for (int q = 0; q < 8; q++) {
            ulonglong2 wp = w[q];
            fma2(a0[2 * q], wp.x, xl);     fma2(a0[2 * q + 1], wp.y, xl);
            fma2(a1[2 * q], wp.x, xh);     fma2(a1[2 * q + 1], wp.y, xh);
        }
        xv = nxv;
    }
#pragma unroll
    for (int p = 0; p < 16; p++) {
        int o0 = 2 * p, o1 = o0 + 1;
        float2 vl = unpk(a0[p]);
        float2 vh = unpk(a1[p]);
        float bb0 = bs[o0], bb1 = bs[o1];
        *(float2*)(g_hA + (size_t)o0 * BT_ + i0) = make_float2(vl.x + bb0, vh.x + bb0);
        *(float2*)(g_hA + (size_t)o1 * BT_ + i0) = make_float2(vl.y + bb1, vh.y + bb1);
    }
}

// host/device constexpr geometry (fused kernels)
__host__ __device__ constexpr int padof(int d) { return (d + 3) & ~3; }
__host__ __device__ constexpr int hoffof(int d) { return padof(64 + d); }
__host__ __device__ constexpr int wshof(int d) {
    int w = 256 + hoffof(d);
    return w + ((8 - (w & 31)) & 31);
}
#define WSZ 328   /* z smem tile row stride: 320 tokens + 8 pad */
#define WT2 264   /* two-tile row stride: 256 tokens + 8 pad */

// ---------------- stage channels [c0,c0+16) of halo tile (compile-time PAD/WS)
template <int PAD, int WS>
__device__ __forceinline__ void stage_halo(float* tile, const float* __restrict__ base,
                                           int t0, int t0m, int c0, int tid) {
    constexpr int NCH = (256 + PAD) >> 2;     // 16B chunks per row
    int c = c0 + (tid >> 4);                   // 16 threads per channel, 16 channels
    int j0 = tid & 15;
    const float* rowp = base + (size_t)c * BT_;
    float* srow = tile + c * WS;
#pragma unroll 1
    for (int j = j0; j < NCH; j += 16) {
        bool v = (t0m + 4 * j) >= PAD;
        const float* src = v ? (rowp + (t0 - PAD + 4 * j)) : rowp;
        uint32_t dst = (uint32_t)__cvta_generic_to_shared(srow + 4 * j);
        CP16Z(dst, src, v ? 16u : 0u);
    }
}

// ---------------- stage a plain 256-token tile shifted by -D (D%4==0) --------
template <int D, int WS>
__device__ __forceinline__ void stage_shift(float* tile, const float* __restrict__ base,
                                            int t0, int t0m, int c0, int tid) {
    int c = c0 + (tid >> 4);                   // 16 threads per channel, 16 channels
    int j0 = tid & 15;
    const float* rowp = base + (size_t)c * BT_;
    float* srow = tile + c * WS;
#pragma unroll
    for (int j = j0; j < 64; j += 16) {
        bool v = (t0m + 4 * j) >= D;
        const float* src = v ? (rowp + (t0 - D + 4 * j)) : rowp;
        uint32_t dst = (uint32_t)__cvta_generic_to_shared(srow + 4 * j);
        CP16Z(dst, src, v ? 16u : 0u);
    }
}

// ============ FUSED k_zr<D> (D<=64): z=tanh*sig over halo, then h+=conv(z) ====
template <int D>
__global__ __launch_bounds__(256, 2) void k_zr(const float* __restrict__ filt_b,
                                               const float* __restrict__ gate_b,
                                               const float* __restrict__ res_b,
                                               int layer, int cur) {
    constexpr int HOFF = hoffof(D);
    constexpr int WSH = wshof(D);
    float* smf = g_smem;
    unsigned* zA = (unsigned*)smf;            // 4096 words
    unsigned* rA = (unsigned*)smf + 4096;     // 2048 words
    float* tile = smf + 6144;                 // h tile 32 x WSH; later z tile 32 x WSZ

    int tid = threadIdx.x;
    int t0 = blockIdx.x * 256;
    int t0m = t0 & (T_ - 1);
    const float* hin = cur ? g_hB : g_hA;
    float* hout = cur ? g_hA : g_hB;

    {
        const unsigned* za = g_wZ + layer * 4096;
#pragma unroll
        for (int i = 0; i < 4; i++) {
            int q = (tid + i * 256) * 4;
            CP16((uint32_t)__cvta_generic_to_shared(zA + q), za + q);
        }
        const unsigned* ra = g_wR + layer * 2048;
#pragma unroll
        for (int i = 0; i < 2; i++) {
            int q = (tid + i * 256) * 4;
            CP16((uint32_t)__cvta_generic_to_shared(rA + q), ra + q);
        }
    }
    stage_halo<HOFF, WSH>(tile, hin, t0, t0m, 0, tid);
    CPCOMMIT();
    stage_halo<HOFF, WSH>(tile, hin, t0, t0m, 16, tid);
    CPCOMMIT();

    int warp = tid >> 5, lane = tid & 31;
    int grp = lane >> 2, tig = lane & 3;
    int xkey = tig << 3;

    // ---------- phase A: z mma, N=320, warp n-tile 40 ----------
    float acc[4][5][4];
#pragma unroll
    for (int mf = 0; mf < 4; mf++)
#pragma unroll
        for (int nf = 0; nf < 5; nf++)
#pragma unroll
            for (int q = 0; q < 4; q++) acc[mf][nf][q] = 0.f;

    CPWAIT1();
    __syncthreads();

#pragma unroll
    for (int phase = 0; phase < 2; phase++) {
#pragma unroll
        for (int tap = 0; tap < 2; tap++) {
#pragma unroll
            for (int kk = 0; kk < 2; kk++) {
                const int cb = phase * 16 + kk * 8;
                const int kc = tap * 32 + cb;
                const int off = tap ? (HOFF - 64) : (HOFF - 64 - D);
                unsigned a[4][4];
#pragma unroll
                for (int mf = 0; mf < 4; mf++) {
                    int m0 = mf * 16 + grp;
                    a[mf][0] = zA[(kc + tig) * 64 + (m0 ^ xkey)];
                    a[mf][1] = zA[(kc + tig) * 64 + ((m0 + 8) ^ xkey)];
                    a[mf][2] = zA[(kc + tig + 4) * 64 + (m0 ^ xkey)];
                    a[mf][3] = zA[(kc + tig + 4) * 64 + ((m0 + 8) ^ xkey)];
                }
                unsigned b[5][2];
#pragma unroll
                for (int nf = 0; nf < 5; nf++) {
                    int n = warp * 40 + nf * 8 + grp;
                    b[nf][0] = f2tf(tile[(cb + tig) * WSH + off + n]);
                    b[nf][1] = f2tf(tile[(cb + tig + 4) * WSH + off + n]);
                }
#pragma unroll
                for (int mf = 0; mf < 4; mf++)
#pragma unroll
                    for (int nf = 0; nf < 5; nf++) mma8(acc[mf][nf], a[mf], b[nf]);
            }
        }
        if (phase == 0) {
            CPWAIT0();
            __syncthreads();
        }
    }

    // all h-tile reads done; overwrite tile with z
    __syncthreads();
#pragma unroll
    for (int mf = 0; mf < 4; mf++) {
        int o = mf * 8 + grp;
        float fbv = __ldg(filt_b + layer * 32 + o);
        float gbv = __ldg(gate_b + layer * 32 + o);
        float* zrow = g_z + ((size_t)layer * 32 + o) * BT_ + t0;
#pragma unroll
        for (int nf = 0; nf < 5; nf++) {
            int p = warp * 40 + nf * 8 + 2 * tig;   // 0..318, even
            float2 zv;
            zv.x = act_z(acc[mf][nf][0] + fbv, acc[mf][nf][2] + gbv);
            zv.y = act_z(acc[mf][nf][1] + fbv, acc[mf][nf][3] + gbv);
            if (t0m == 0 && p < 64) { zv.x = 0.f; zv.y = 0.f; }  // causal zero before batch start
            *(float2*)(tile + o * WSZ + p) = zv;
            if (p >= 64) *(float2*)(zrow + p - 64) = zv;
        }
    }
    __syncthreads();

    // ---------- phase B: res mma, M=32, N=256 off smem z ----------
    float acr[2][4][4];
#pragma unroll
    for (int mf = 0; mf < 2; mf++)
#pragma unroll
        for (int nf = 0; nf < 4; nf++)
#pragma unroll
            for (int q = 0; q < 4; q++) acr[mf][nf][q] = 0.f;

#pragma unroll
    for (int tap = 0; tap < 2; tap++) {
#pragma unroll
        for (int kk = 0; kk < 4; kk++) {
            const int cb = kk * 8;
            const int kc = tap * 32 + cb;
            const int off = tap ? 64 : (64 - D);
            unsigned a[2][4];
#pragma unroll
            for (int mf = 0; mf < 2; mf++) {
                int m0 = mf * 16 + grp;
                a[mf][0] = rA[(kc + tig) * 32 + (m0 ^ xkey)];
                a[mf][1] = rA[(kc + tig) * 32 + ((m0 + 8) ^ xkey)];
                a[mf][2] = rA[(kc + tig + 4) * 32 + (m0 ^ xkey)];
                a[mf][3] = rA[(kc + tig + 4) * 32 + ((m0 + 8) ^ xkey)];
            }
            unsigned b[4][2];
#pragma unroll
            for (int nf = 0; nf < 4; nf++) {
                int n = warp * 32 + nf * 8 + grp;
                b[nf][0] = __float_as_uint(tile[(cb + tig) * WSZ + off + n]);
                b[nf][1] = __float_as_uint(tile[(cb + tig + 4) * WSZ + off + n]);
            }
#pragma unroll
            for (int mf = 0; mf < 2; mf++)
#pragma unroll
                for (int nf = 0; nf < 4; nf++) mma8(acr[mf][nf], a[mf], b[nf]);
        }
    }

#pragma unroll
    for (int mf = 0; mf < 2; mf++) {
        int o = mf * 16 + grp;
        float b0 = __ldg(res_b + layer * 32 + o);
        float b1 = __ldg(res_b + layer * 32 + o + 8);
        const float* in0 = hin + (size_t)o * BT_ + t0;
        const float* in1 = hin + (size_t)(o + 8) * BT_ + t0;
        float* out0 = hout + (size_t)o * BT_ + t0;
        float* out1 = hout + (size_t)(o + 8) * BT_ + t0;
#pragma unroll
        for (int nf = 0; nf < 4; nf++) {
            int col = warp * 32 + nf * 8 + 2 * tig;
            float2 h0 = *(const float2*)(in0 + col);
            float2 h1 = *(const float2*)(in1 + col);
            h0.x += acr[mf][nf][0] + b0;
            h0.y += acr[mf][nf][1] + b0;
            h1.x += acr[mf][nf][2] + b1;
            h1.y += acr[mf][nf][3] + b1;
            *(float2*)(out0 + col) = h0;
            *(float2*)(out1 + col) = h1;
        }
    }
}

// ---------------- k_z<D> (mma, unfused; d>=128): TWO-TILE staging -------------
template <int D>
__global__ __launch_bounds__(256, 2) void k_z(const float* __restrict__ filt_b,
                                              const float* __restrict__ gate_b,
                                              int layer, int cur) {
    float* smz = g_smem;
    unsigned* sA = (unsigned*)smz;      // 4096 words
    float* tC = smz + 4096;             // cur tile 32 x 264
    float* tP = smz + 4096 + 32 * WT2;  // prev tile 32 x 264

    int tid = threadIdx.x;
    int t0 = blockIdx.x * 256;
    int t0m = t0 & (T_ - 1);
    const float* hin = cur ? g_hB : g_hA;

    {
        const unsigned* asrc = g_wZ + layer * 4096;
#pragma unroll
        for (int i = 0; i < 4; i++) {
            int q = (tid + i * 256) * 4;
            CP16((uint32_t)__cvta_generic_to_shared(sA + q), asrc + q);
        }
    }
    stage_shift<0, WT2>(tC, hin, t0, t0m, 0, tid);
    stage_shift<D, WT2>(tP, hin, t0, t0m, 0, tid);
    CPCOMMIT();
    stage_shift<0, WT2>(tC, hin, t0, t0m, 16, tid);
    stage_shift<D, WT2>(tP, hin, t0, t0m, 16, tid);
    CPCOMMIT();

    int warp = tid >> 5, lane = tid & 31;
    int grp = lane >> 2, tig = lane & 3;
    int n_off = warp * 32;
    int xkey = tig << 3;

    float acc[4][4][4];
#pragma unroll
    for (int mf = 0; mf < 4; mf++)
#pragma unroll
        for (int nf = 0; nf < 4; nf++)
#pragma unroll
            for (int q = 0; q < 4; q++) acc[mf][nf][q] = 0.f;

    CPWAIT1();
    __syncthreads();

#pragma unroll
    for (int phase = 0; phase < 2; phase++) {
#pragma unroll
        for (int tap = 0; tap < 2; tap++) {
#pragma unroll
            for (int kk = 0; kk < 2; kk++) {
                const int cb = phase * 16 + kk * 8;
                const int kc = tap * 32 + cb;
                const float* tp = tap ? tC : tP;
                unsigned a[4][4];
#pragma unroll
                for (int mf = 0; mf < 4; mf++) {
                    int m0 = mf * 16 + grp;
                    a[mf][0] = sA[(kc + tig) * 64 + (m0 ^ xkey)];
                    a[mf][1] = sA[(kc + tig) * 64 + ((m0 + 8) ^ xkey)];
                    a[mf][2] = sA[(kc + tig + 4) * 64 + (m0 ^ xkey)];
                    a[mf][3] = sA[(kc + tig + 4) * 64 + ((m0 + 8) ^ xkey)];
                }
                unsigned b[4][2];
#pragma unroll
                for (int nf = 0; nf < 4; nf++) {
                    int n = n_off + nf * 8 + grp;
                    b[nf][0] = f2tf(tp[(cb + tig) * WT2 + n]);
                    b[nf][1] = f2tf(tp[(cb + tig + 4) * WT2 + n]);
                }
#pragma unroll
                for (int mf = 0; mf < 4; mf++)
#pragma unroll
                    for (int nf = 0; nf < 4; nf++) mma8(acc[mf][nf], a[mf], b[nf]);
            }
        }
        if (phase == 0) {
            CPWAIT0();
            __syncthreads();
        }
    }

#pragma unroll
    for (int mf = 0; mf < 4; mf++) {
        int o = mf * 8 + grp;
        float fbv = __ldg(filt_b + layer * 32 + o);
        float gbv = __ldg(gate_b + layer * 32 + o);
        float* zrow = g_z + ((size_t)layer * 32 + o) * BT_ + t0;
#pragma unroll
        for (int nf = 0; nf < 4; nf++) {
            int col = n_off + nf * 8 + 2 * tig;
            float2 zv;
            zv.x = act_z(acc[mf][nf][0] + fbv, acc[mf][nf][2] + gbv);
            zv.y = act_z(acc[mf][nf][1] + fbv, acc[mf][nf][3] + gbv);
            *(float2*)(zrow + col) = zv;
        }
    }
}

// ---------------- k_res<D> (mma, unfused; d>=128): TWO-TILE, hout=hin+conv(z) -
template <int D>
__global__ __launch_bounds__(256, 2) void k_res(const float* __restrict__ res_b,
                                                int layer, int cur) {
    float* smr = g_smem;
    unsigned* sR = (unsigned*)smr;      // 2048 words
    float* tC = smr + 2048;             // cur z tile 32 x 264
    float* tP = smr + 2048 + 32 * WT2;  // prev z tile 32 x 264

    int tid = threadIdx.x;
    int t0 = blockIdx.x * 256;
    int t0m = t0 & (T_ - 1);
    const float* zL = g_z + (size_t)layer * 32 * BT_;
    const float* hin = cur ? g_hB : g_hA;
    float* hout = cur ? g_hA : g_hB;

    {
        const unsigned* asrc = g_wR + layer * 2048;
#pragma unroll
        for (int i = 0; i < 2; i++) {
            int q = (tid + i * 256) * 4;
            CP16((uint32_t)__cvta_generic_to_shared(sR + q), asrc + q);
        }
    }
    stage_shift<0, WT2>(tC, zL, t0, t0m, 0, tid);
    stage_shift<D, WT2>(tP, zL, t0, t0m, 0, tid);
    CPCOMMIT();
    stage_shift<0, WT2>(tC, zL, t0, t0m, 16, tid);
    stage_shift<D, WT2>(tP, zL, t0, t0m, 16, tid);
    CPCOMMIT();

    int warp = tid >> 5, lane = tid & 31;
    int grp = lane >> 2, tig = lane & 3;
    int n_off = warp * 32;
    int xkey = tig << 3;

    float acc[2][4][4];
#pragma unroll
    for (int mf = 0; mf < 2; mf++)
#pragma unroll
        for (int nf = 0; nf < 4; nf++)
#pragma unroll
            for (int q = 0; q < 4; q++) acc[mf][nf][q] = 0.f;

    CPWAIT1();
    __syncthreads();

#pragma unroll
    for (int phase = 0; phase < 2; phase++) {
#pragma unroll
        for (int tap = 0; tap < 2; tap++) {
#pragma unroll
            for (int kk = 0; kk < 2; kk++) {
                const int cb = phase * 16 + kk * 8;
                const int kc = tap * 32 + cb;
                const float* tp = tap ? tC : tP;
                unsigned a[2][4];
#pragma unroll
                for (int mf = 0; mf < 2; mf++) {
                    int m0 = mf * 16 + grp;
                    a[mf][0] = sR[(kc + tig) * 32 + (m0 ^ xkey)];
                    a[mf][1] = sR[(kc + tig) * 32 + ((m0 + 8) ^ xkey)];
                    a[mf][2] = sR[(kc + tig + 4) * 32 + (m0 ^ xkey)];
                    a[mf][3] = sR[(kc + tig + 4) * 32 + ((m0 + 8) ^ xkey)];
                }
                unsigned b[4][2];
#pragma unroll
                for (int nf = 0; nf < 4; nf++) {
                    int n = n_off + nf * 8 + grp;
                    b[nf][0] = __float_as_uint(tp[(cb + tig) * WT2 + n]);
                    b[nf][1] = __float_as_uint(tp[(cb + tig + 4) * WT2 + n]);
                }
#pragma unroll
                for (int mf = 0; mf < 2; mf++)
#pragma unroll
                    for (int nf = 0; nf < 4; nf++) mma8(acc[mf][nf], a[mf], b[nf]);
            }
        }
        if (phase == 0) {
            CPWAIT0();
            __syncthreads();
        }
    }

#pragma unroll
    for (int mf = 0; mf < 2; mf++) {
        int o = mf * 16 + grp;
        float b0 = __ldg(res_b + layer * 32 + o);
        float b1 = __ldg(res_b + layer * 32 + o + 8);
        const float* in0 = hin + (size_t)o * BT_ + t0;
        const float* in1 = hin + (size_t)(o + 8) * BT_ + t0;
        float* out0 = hout + (size_t)o * BT_ + t0;
        float* out1 = hout + (size_t)(o + 8) * BT_ + t0;
#pragma unroll
        for (int nf = 0; nf < 4; nf++) {
            int col = n_off + nf * 8 + 2 * tig;
            float2 h0 = *(const float2*)(in0 + col);
            float2 h1 = *(const float2*)(in1 + col);
            h0.x += acc[mf][nf][0] + b0;
            h0.y += acc[mf][nf][1] + b0;
            h1.x += acc[mf][nf][2] + b1;
            h1.y += acc[mf][nf][3] + b1;
            *(float2*)(out0 + col) = h0;
            *(float2*)(out1 + col) = h1;
        }
    }
}

// ================== unified tf32 GEMM (cp.async staged, double buffered) =====
#define SAS 264
#define SBS 136
#define BUFW 12800

template <int MODE>
__device__ __forceinline__ void stage_step(unsigned* sm, int buf, int s, int t0, int tid) {
    unsigned* sA = sm + buf * BUFW;
    unsigned* sB = sm + buf * BUFW + 32 * SAS;
    const unsigned* asrc = g_wA + (MODE == 0 ? WOFF_SKIP : (MODE == 1 ? WOFF_E1 : WOFF_E2))
                         + (size_t)s * 32 * 256;
#pragma unroll
    for (int i = 0; i < 8; i++) {
        int q = tid + i * 256;
        int row = q >> 6, col = (q & 63) * 4;
        uint32_t dst = (uint32_t)__cvta_generic_to_shared(sA + row * SAS + col);
        CP16(dst, asrc + row * 256 + col);
    }
    if (MODE != 0) {
        const float* gB = (MODE == 1) ? g_skip : g_out1;
#pragma unroll
        for (int i = 0; i < 4; i++) {
            int q = tid + i * 256;
            int row = q >> 5, col = (q & 31) * 4;
            uint32_t dst = (uint32_t)__cvta_generic_to_shared(sB + row * SBS + col);
            CP16(dst, gB + (size_t)(s * 32 + row) * BT_ + t0 + col);
        }
    } else {
        int li = s >> 1, tap = s & 1;
        int d = 1 << (li % LAYERS_);
        int j = tid >> 3, l8 = tid & 7;
        const float* zrow = g_z + ((size_t)li * 32 + j) * BT_;
        if (tap == 1) {
#pragma unroll
            for (int i = 0; i < 4; i++) {
                int q = l8 + i * 8;
                uint32_t dst = (uint32_t)__cvta_generic_to_shared(sB + j * SBS + q * 4);
                CP16(dst, zrow + t0 + q * 4);
            }
        } else {
            int r = (4 - (d & 3)) & 3;
            int t0m = t0 & (T_ - 1);
            if (t0m >= d + 4) {
                const float* src = zrow + t0 - d - r;
#pragma unroll
                for (int i = 0; i < 4; i++) {
                    int q = l8 + i * 8;
                    uint32_t dst = (uint32_t)__cvta_generic_to_shared(sB + j * SBS + q * 4);
                    CP16(dst, src + q * 4);
                }
                if (l8 == 0) {
                    uint32_t dst = (uint32_t)__cvta_generic_to_shared(sB + j * SBS + 128);
                    CP16(dst, src + 128);
                }
            } else {
                for (int t = l8; t < 128; t += 8) {
                    int gm = t0 + t;
                    float v = ((gm & (T_ - 1)) >= d) ? zrow[gm - d] : 0.f;
                    sB[j * SBS + r + t] = __float_as_uint(v);
                }
            }
        }
    }
}

template <int MODE>
__global__ __launch_bounds__(256) void k_gemm(const float* __restrict__ bias,
                                              float* __restrict__ dout) {
    unsigned* sm = (unsigned*)g_smem;
    constexpr int KS = (MODE == 0) ? 80 : 8;
    int tid = threadIdx.x, warp = tid >> 5, lane = tid & 31;
    int grp = lane >> 2, tig = lane & 3;
    int t0 = blockIdx.x * 128;
    int m_off = (warp >> 1) * 64;
    int n_off = (warp & 1) * 64;

    float acc[4][8][4];
#pragma unroll
    for (int mf = 0; mf < 4; mf++)
#pragma unroll
        for (int nf = 0; nf < 8; nf++)
#pragma unroll
            for (int q = 0; q < 4; q++) acc[mf][nf][q] = 0.f;

    stage_step<MODE>(sm, 0, 0, t0, tid);
    CPCOMMIT();

    int buf = 0;
#pragma unroll 1
    for (int s = 0; s < KS; s++) {
        if (s + 1 < KS) {
            stage_step<MODE>(sm, buf ^ 1, s + 1, t0, tid);
            CPCOMMIT();
            CPWAIT1();
        } else {
            CPWAIT0();
        }
        __syncthreads();

        unsigned* sA = sm + buf * BUFW;
        unsigned* sB = sm + buf * BUFW + 32 * SAS;
        int roff = 0;
        if (MODE == 0 && !(s & 1)) {
            int d = 1 << ((s >> 1) % LAYERS_);
            roff = (4 - (d & 3)) & 3;
        }
#pragma unroll
        for (int kc = 0; kc < 32; kc += 8) {
            unsigned a[4][4], b[8][2];
#pragma unroll
            for (int mf = 0; mf < 4; mf++) {
                int r0 = m_off + mf * 16 + grp;
                a[mf][0] = sA[(kc + tig) * SAS + r0];
                a[mf][1] = sA[(kc + tig) * SAS + r0 + 8];
                a[mf][2] = sA[(kc + tig + 4) * SAS + r0];
                a[mf][3] = sA[(kc + tig + 4) * SAS + r0 + 8];
            }
#pragma unroll
            for (int nf = 0; nf < 8; nf++) {
                int ci = n_off + nf * 8 + grp + roff;
                b[nf][0] = sB[(kc + tig) * SBS + ci];
                b[nf][1] = sB[(kc + tig + 4) * SBS + ci];
            }
#pragma unroll
            for (int mf = 0; mf < 4; mf++)
#pragma unroll
                for (int nf = 0; nf < 8; nf++) mma8(acc[mf][nf], a[mf], b[nf]);
        }
        __syncthreads();
        buf ^= 1;
    }

    const float* bp = (MODE == 0) ? g_skipb : bias;

    if (MODE != 2) {
        float* out = (MODE == 0) ? g_skip : g_out1;
#pragma unroll
        for (int mf = 0; mf < 4; mf++)
#pragma unroll
            for (int nf = 0; nf < 8; nf++) {
                int row0 = m_off + mf * 16 + grp;
                int col = t0 + n_off + nf * 8 + 2 * tig;
                float b0 = bp[row0];
                float b1 = bp[row0 + 8];
                float2 v0 = make_float2(rtf(fmaxf(acc[mf][nf][0] + b0, 0.f)),
                                        rtf(fmaxf(acc[mf][nf][1] + b0, 0.f)));
                float2 v1 = make_float2(rtf(fmaxf(acc[mf][nf][2] + b1, 0.f)),
                                        rtf(fmaxf(acc[mf][nf][3] + b1, 0.f)));
                *(float2*)&out[(size_t)row0 * BT_ + col] = v0;
                *(float2*)&out[(size_t)(row0 + 8) * BT_ + col] = v1;
            }
    } else {
        float* ts = (float*)sm;  // [64 tok][260]
#pragma unroll 1
        for (int h = 0; h < 2; h++) {
            __syncthreads();
            if ((warp & 1) == h) {
#pragma unroll
                for (int mf = 0; mf < 4; mf++)
#pragma unroll
                    for (int nf = 0; nf < 8; nf++) {
                        int rowL = m_off + mf * 16 + grp;
                        int colL = nf * 8 + 2 * tig;  // 0..63
                        float b0 = bp[rowL];
                        float b1 = bp[rowL + 8];
                        ts[colL * 260 + rowL] = acc[mf][nf][0] + b0;
                        ts[(colL + 1) * 260 + rowL] = acc[mf][nf][1] + b0;
                        ts[colL * 260 + rowL + 8] = acc[mf][nf][2] + b1;
                        ts[(colL + 1) * 260 + rowL + 8] = acc[mf][nf][3] + b1;
                    }
            }
            __syncthreads();
#pragma unroll
            for (int i = 0; i < 16; i++) {
                int q = tid + i * 256;
                int tk = q >> 6, c4 = (q & 63) * 4;
                float4 v = *(const float4*)&ts[tk * 260 + c4];
                *(float4*)&dout[(size_t)(t0 + h * 64 + tk) * 256 + c4] = v;
            }
        }
    }
}

// ---------------- host launcher ----------------
extern "C" void kernel_launch(void* const* d_in, const int* in_sizes, int n_in,
                              void* d_out, int out_size) {
    const float* x      = (const float*)d_in[0];
    const float* w_in   = (const float*)d_in[1];
    const float* b_in   = (const float*)d_in[2];
    const float* filt_w = (const float*)d_in[3];
    const float* filt_b = (const float*)d_in[4];
    const float* gate_w = (const float*)d_in[5];
    const float* gate_b = (const float*)d_in[6];
    const float* res_w  = (const float*)d_in[7];
    const float* res_b  = (const float*)d_in[8];
    const float* skip_w = (const float*)d_in[9];
    const float* skip_b = (const float*)d_in[10];
    const float* end1_w = (const float*)d_in[11];
    const float* end1_b = (const float*)d_in[12];
    const float* end2_w = (const float*)d_in[13];
    const float* end2_b = (const float*)d_in[14];
    float* out = (float*)d_out;

    const int SMEM = 25600 * 4;   // GEMM: 102,400 B dynamic
    const int SMZ2 = (4096 + 2 * 32 * WT2) * 4;   // 83,968 B
    const int SMR2 = (2048 + 2 * 32 * WT2) * 4;   // 75,776 B
    cudaFuncSetAttribute(k_gemm<0>, cudaFuncAttributeMaxDynamicSharedMemorySize, SMEM);
    cudaFuncSetAttribute(k_gemm<1>, cudaFuncAttributeMaxDynamicSharedMemorySize, SMEM);
    cudaFuncSetAttribute(k_gemm<2>, cudaFuncAttributeMaxDynamicSharedMemorySize, SMEM);

#define SETF(D) \
    cudaFuncSetAttribute(k_zr<D>, cudaFuncAttributeMaxDynamicSharedMemorySize, (6144 + 32 * wshof(D)) * 4);
    SETF(1) SETF(2) SETF(4) SETF(8) SETF(16) SETF(32) SETF(64)
#undef SETF
#define SETU(D) \
    cudaFuncSetAttribute(k_z<D>,   cudaFuncAttributeMaxDynamicSharedMemorySize, SMZ2); \
    cudaFuncSetAttribute(k_res<D>, cudaFuncAttributeMaxDynamicSharedMemorySize, SMR2);
    SETU(128) SETU(256) SETU(512)
#undef SETU

    k_bias<<<1, 256>>>(skip_b);
    k_pack<<<4032, 256>>>(skip_w, end1_w, end2_w, filt_w, gate_w, res_w);
    k_input<<<BT_ / 512, 256>>>(x, w_in, b_in);

#define LAYERF(D) { \
        k_zr<D><<<BT_ / 256, 256, (6144 + 32 * wshof(D)) * 4>>>(filt_b, gate_b, res_b, i, cur); }
#define LAYERU(D) { \
        k_z<D><<<BT_ / 256, 256, SMZ2>>>(filt_b, gate_b, i, cur); \
        k_res<D><<<BT_ / 256, 256, SMR2>>>(res_b, i, cur); }

    int cur = 0;
    for (int i = 0; i < NL_; i++) {
        switch (i % LAYERS_) {
            case 0: LAYERF(1)   break;
            case 1: LAYERF(2)   break;
            case 2: LAYERF(4)   break;
            case 3: LAYERF(8)   break;
            case 4: LAYERF(16)  break;
            case 5: LAYERF(32)  break;
            case 6: LAYERF(64)  break;
            case 7: LAYERU(128) break;
            case 8: LAYERU(256) break;
            case 9: LAYERU(512) break;
        }
        cur ^= 1;
    }
#undef LAYERF
#undef LAYERU

    k_gemm<0><<<BT_ / 128, 256, SMEM>>>(nullptr, nullptr);
    k_gemm<1><<<BT_ / 128, 256, SMEM>>>(end1_b, nullptr);
    k_gemm<2><<<BT_ / 128, 256, SMEM>>>(end2_b, out);
}

// round 15
// speedup vs baseline: 1.8761x; 1.0094x over previous
#include <cuda_runtime.h>
#include <cuda_bf16.h>
#include <stdint.h>
#include <math.h>

#define LAYERS_   10
#define NL_       40
#define RC_       32
#define DC_       32
#define SC_       256
#define EC_       256
#define CL_       256
#define B_        8
#define T_        16384
#define BT_       131072   /* B_*T_ */

typedef unsigned long long u64;

// ---------------- scratch (static device globals; no allocations) -------------
__device__ float g_hA[32 * BT_];                      // residual state ping
__device__ float g_hB[32 * BT_];                      // residual state pong
__device__ float g_z[167772160];                      // 40*32*BT, [layer][c][BT] (tf32-rounded)
__device__ float g_skip[SC_ * BT_];                   // [c][BT]  relu(skip), tf32-rounded
__device__ float g_out1[EC_ * BT_];                   // [c][BT]  relu(out1), tf32-rounded
__device__ float g_skipb[SC_];
__device__ unsigned g_wA[786432];                     // packed tf32 weights, K-major (GEMMs)
__device__ unsigned g_wZ[163840];                     // k_z mma weights [layer][64k][64m] xor-swizzled
__device__ unsigned g_wR[81920];                      // k_res mma weights [layer][64k][32m] xor-swizzled

#define WOFF_SKIP 0
#define WOFF_E1   655360
#define WOFF_E2   720896

// ---------------- small helpers ----------------
__device__ __forceinline__ unsigned f2tf(float x) {
    unsigned r;
    asm("cvt.rna.tf32.f32 %0, %1;" : "=r"(r) : "f"(x));
    return r;
}
__device__ __forceinline__ float rtf(float x) {      // RN-round to tf32, as float
    return __uint_as_float(f2tf(x));
}
__device__ __forceinline__ void mma8(float* d, const unsigned* a, const unsigned* b) {
    asm volatile(
        "mma.sync.aligned.m16n8k8.row.col.f32.tf32.tf32.f32 "
        "{%0,%1,%2,%3},{%4,%5,%6,%7},{%8,%9},{%0,%1,%2,%3};\n"
        : "+f"(d[0]), "+f"(d[1]), "+f"(d[2]), "+f"(d[3])
        : "r"(a[0]), "r"(a[1]), "r"(a[2]), "r"(a[3]), "r"(b[0]), "r"(b[1]));
}
__device__ __forceinline__ void fma2(u64& d, u64 a, u64 b) {
    asm("fma.rn.f32x2 %0, %1, %2, %0;" : "+l"(d) : "l"(a), "l"(b));
}
__device__ __forceinline__ u64 dup2(float x) {
    u64 r; unsigned xi = __float_as_uint(x);
    asm("mov.b64 %0, {%1, %1};" : "=l"(r) : "r"(xi));
    return r;
}
__device__ __forceinline__ float2 unpk(u64 v) {
    unsigned lo, hi;
    asm("mov.b64 {%0, %1}, %2;" : "=r"(lo), "=r"(hi) : "l"(v));
    return make_float2(__uint_as_float(lo), __uint_as_float(hi));
}
// 3-MUFU activation: tanh(f)*sigmoid(g), tf32-rounded
__device__ __forceinline__ float act_z(float fx, float gx) {
    float a = __expf(-2.f * fabsf(fx));
    float b = __expf(-gx);
    float den = (1.f + a) * (1.f + b);
    float r;
    asm("rcp.approx.f32 %0, %1;" : "=f"(r) : "f"(den));
    return rtf(copysignf((1.f - a) * r, fx));
}
// PDL primitives
__device__ __forceinline__ void pdl_trigger() {
    asm volatile("griddepcontrol.launch_dependents;" ::: "memory");
}
__device__ __forceinline__ void pdl_wait() {
    asm volatile("griddepcontrol.wait;" ::: "memory");
}

#define CP16(dst, src) asm volatile("cp.async.cg.shared.global [%0], [%1], 16;\n" :: "r"(dst), "l"(src))
#define CP16Z(dst, src, n) asm volatile("cp.async.cg.shared.global [%0], [%1], 16, %2;\n" :: "r"(dst), "l"(src), "r"(n))
#define CPCOMMIT()     asm volatile("cp.async.commit_group;\n")
#define CPWAIT1()      asm volatile("cp.async.wait_group 1;\n" ::: "memory")
#define CPWAIT0()      asm volatile("cp.async.wait_group 0;\n" ::: "memory")

// single extern-shared symbol for the whole TU (consistent type everywhere)
extern __shared__ float g_smem[];

// ---------------- bias reduction for skip ----------------
__global__ void k_bias(const float* __restrict__ skip_b) {
    int o = threadIdx.x;
    float s = 0.f;
#pragma unroll 1
    for (int i = 0; i < NL_; i++) s += skip_b[i * SC_ + o];
    g_skipb[o] = s;
}

// ---------------- pack all weights as tf32 ----------------
__global__ void k_pack(const float* __restrict__ skip_w,
                       const float* __restrict__ e1w,
                       const float* __restrict__ e2w,
                       const float* __restrict__ filt_w,
                       const float* __restrict__ gate_w,
                       const float* __restrict__ res_w) {
    int idx = blockIdx.x * 256 + threadIdx.x;
    if (idx < WOFF_E1) {
        int k = idx >> 8, m = idx & 255;
        int li = k >> 6, tap = (k >> 5) & 1, c = k & 31;
        g_wA[idx] = f2tf(skip_w[((size_t)(li * 256 + m) * 32 + c) * 2 + tap]);
    } else if (idx < WOFF_E2) {
        int local = idx - WOFF_E1;
        int k = local >> 8, m = local & 255;
        g_wA[idx] = f2tf(e1w[m * 256 + k]);
    } else if (idx < 786432) {
        int local = idx - WOFF_E2;
        int k = local >> 8, m = local & 255;
        g_wA[idx] = f2tf(e2w[m * 256 + k]);
    } else if (idx < 786432 + 163840) {
        int local = idx - 786432;
        int layer = local >> 12;
        int rem = local & 4095;
        int k = rem >> 6, mx = rem & 63;
        int m = mx ^ ((k & 3) << 3);
        int c = k & 31, tap = k >> 5;
        int o = ((m >> 4) << 3) + (m & 7);
        int isg = (m >> 3) & 1;
        const float* w = isg ? gate_w : filt_w;
        g_wZ[local] = f2tf(w[layer * 2048 + o * 64 + c * 2 + tap]);
    } else if (idx < 786432 + 163840 + 81920) {
        int local = idx - 786432 - 163840;
        int layer = local >> 11;
        int rem = local & 2047;
        int k = rem >> 5, mx = rem & 31;
        int m = mx ^ ((k & 3) << 3);
        int c = k & 31, tap = k >> 5;
        g_wR[local] = f2tf(res_w[layer * 2048 + m * 64 + c * 2 + tap]);
    }
}

// ---------------- input 1x1 conv (fma2): x[8,256,16384] -> g_hA ---------------
__global__ __launch_bounds__(256, 2) void k_input(const float* __restrict__ x,
                                                  const float* __restrict__ w_in,
                                                  const float* __restrict__ b_in) {
    __shared__ __align__(16) float ws[256 * 32];   // [c][o]
    __shared__ float bs[32];
    int tid = threadIdx.x;
    for (int e = tid; e < 256 * 32; e += 256) {
        int c = e >> 5, rc = e & 31;
        ws[e] = w_in[rc * 256 + c];
    }
    if (tid < 32) bs[tid] = b_in[tid];
    __syncthreads();

    int i0 = blockIdx.x * 512 + tid * 2;
    int b0 = i0 >> 14, t0 = i0 & (T_ - 1);
    const float* xb = x + (size_t)b0 * 256 * T_ + t0;

    u64 a0[16], a1[16];
#pragma unroll
    for (int p = 0; p < 16; p++) { a0[p] = 0; a1[p] = 0; }

    float2 xv = *(const float2*)xb;
#pragma unroll 4
    for (int c = 0; c < 256; c++) {
        int cn = (c < 255) ? c + 1 : 255;
        float2 nxv = *(const float2*)(xb + (size_t)cn * T_);
        u64 xl = dup2(xv.x), xh = dup2(xv.y);
        const ulonglong2* w = (const ulonglong2*)&ws[c * 32];
#pragma unroll
        for (int q = 0; q < 8; q++) {
            ulonglong2 wp = w[q];
            fma2(a0[2 * q], wp.x, xl);     fma2(a0[2 * q + 1], wp.y, xl);
            fma2(a1[2 * q], wp.x, xh);     fma2(a1[2 * q + 1], wp.y, xh);
        }
        xv = nxv;
    }
#pragma unroll
    for (int p = 0; p < 16; p++) {
        int o0 = 2 * p, o1 = o0 + 1;
        float2 vl = unpk(a0[p]);
        float2 vh = unpk(a1[p]);
        float bb0 = bs[o0], bb1 = bs[o1];
        *(float2*)(g_hA + (size_t)o0 * BT_ + i0) = make_float2(vl.x + bb0, vh.x + bb0);
        *(float2*)(g_hA + (size_t)o1 * BT_ + i0) = make_float2(vl.y + bb1, vh.y + bb1);
    }
}

// host/device constexpr geometry (fused kernels)
__host__ __device__ constexpr int padof(int d) { return (d + 3) & ~3; }
__host__ __device__ constexpr int hoffof(int d) { return padof(64 + d); }
__host__ __device__ constexpr int wshof(int d) {
    int w = 256 + hoffof(d);
    return w + ((8 - (w & 31)) & 31);
}
#define WSZ 328   /* z smem tile row stride: 320 tokens + 8 pad */
#define WT2 264   /* two-tile row stride: 256 tokens + 8 pad */

// ---------------- stage channels [c0,c0+16) of halo tile (compile-time PAD/WS)
template <int PAD, int WS>
__device__ __forceinline__ void stage_halo(float* tile, const float* __restrict__ base,
                                           int t0, int t0m, int c0, int tid) {
    constexpr int NCH = (256 + PAD) >> 2;     // 16B chunks per row
    int c = c0 + (tid >> 4);                   // 16 threads per channel, 16 channels
    int j0 = tid & 15;
    const float* rowp = base + (size_t)c * BT_;
    float* srow = tile + c * WS;
#pragma unroll 1
    for (int j = j0; j < NCH; j += 16) {
        bool v = (t0m + 4 * j) >= PAD;
        const float* src = v ? (rowp + (t0 - PAD + 4 * j)) : rowp;
        uint32_t dst = (uint32_t)__cvta_generic_to_shared(srow + 4 * j);
        CP16Z(dst, src, v ? 16u : 0u);
    }
}

// ---------------- stage a plain 256-token tile shifted by -D (D%4==0) --------
template <int D, int WS>
__device__ __forceinline__ void stage_shift(float* tile, const float* __restrict__ base,
                                            int t0, int t0m, int c0, int tid) {
    int c = c0 + (tid >> 4);                   // 16 threads per channel, 16 channels
    int j0 = tid & 15;
    const float* rowp = base + (size_t)c * BT_;
    float* srow = tile + c * WS;
#pragma unroll
    for (int j = j0; j < 64; j += 16) {
        bool v = (t0m + 4 * j) >= D;
        const float* src = v ? (rowp + (t0 - D + 4 * j)) : rowp;
        uint32_t dst = (uint32_t)__cvta_generic_to_shared(srow + 4 * j);
        CP16Z(dst, src, v ? 16u : 0u);
    }
}

// ============ FUSED k_zr<D> (D<=64): z=tanh*sig over halo, then h+=conv(z) ====
template <int D>
__global__ __launch_bounds__(256, 2) void k_zr(const float* __restrict__ filt_b,
                                               const float* __restrict__ gate_b,
                                               const float* __restrict__ res_b,
                                               int layer, int cur) {
    constexpr int HOFF = hoffof(D);
    constexpr int WSH = wshof(D);
    float* smf = g_smem;
    unsigned* zA = (unsigned*)smf;            // 4096 words
    unsigned* rA = (unsigned*)smf + 4096;     // 2048 words
    float* tile = smf + 6144;                 // h tile 32 x WSH; later z tile 32 x WSZ

    int tid = threadIdx.x;
    int t0 = blockIdx.x * 256;
    int t0m = t0 & (T_ - 1);
    const float* hin = cur ? g_hB : g_hA;
    float* hout = cur ? g_hA : g_hB;

    pdl_trigger();

    // stage weights (independent of prior layer)
    {
        const unsigned* za = g_wZ + layer * 4096;
#pragma unroll
        for (int i = 0; i < 4; i++) {
            int q = (tid + i * 256) * 4;
            CP16((uint32_t)__cvta_generic_to_shared(zA + q), za + q);
        }
        const unsigned* ra = g_wR + layer * 2048;
#pragma unroll
        for (int i = 0; i < 2; i++) {
            int q = (tid + i * 256) * 4;
            CP16((uint32_t)__cvta_generic_to_shared(rA + q), ra + q);
        }
    }
    pdl_wait();   // prior layer's h writes must be complete before staging h
    stage_halo<HOFF, WSH>(tile, hin, t0, t0m, 0, tid);
    CPCOMMIT();
    stage_halo<HOFF, WSH>(tile, hin, t0, t0m, 16, tid);
    CPCOMMIT();

    int warp = tid >> 5, lane = tid & 31;
    int grp = lane >> 2, tig = lane & 3;
    int xkey = tig << 3;

    // ---------- phase A: z mma, N=320, warp n-tile 40 ----------
    float acc[4][5][4];
#pragma unroll
    for (int mf = 0; mf < 4; mf++)
#pragma unroll
        for (int nf = 0; nf < 5; nf++)
#pragma unroll
            for (int q = 0; q < 4; q++) acc[mf][nf][q] = 0.f;

    CPWAIT1();
    __syncthreads();

#pragma unroll
    for (int phase = 0; phase < 2; phase++) {
#pragma unroll
        for (int tap = 0; tap < 2; tap++) {
#pragma unroll
            for (int kk = 0; kk < 2; kk++) {
                const int cb = phase * 16 + kk * 8;
                const int kc = tap * 32 + cb;
                const int off = tap ? (HOFF - 64) : (HOFF - 64 - D);
                unsigned a[4][4];
#pragma unroll
                for (int mf = 0; mf < 4; mf++) {
                    int m0 = mf * 16 + grp;
                    a[mf][0] = zA[(kc + tig) * 64 + (m0 ^ xkey)];
                    a[mf][1] = zA[(kc + tig) * 64 + ((m0 + 8) ^ xkey)];
                    a[mf][2] = zA[(kc + tig + 4) * 64 + (m0 ^ xkey)];
                    a[mf][3] = zA[(kc + tig + 4) * 64 + ((m0 + 8) ^ xkey)];
                }
                unsigned b[5][2];
#pragma unroll
                for (int nf = 0; nf < 5; nf++) {
                    int n = warp * 40 + nf * 8 + grp;
                    b[nf][0] = f2tf(tile[(cb + tig) * WSH + off + n]);
                    b[nf][1] = f2tf(tile[(cb + tig + 4) * WSH + off + n]);
                }
#pragma unroll
                for (int mf = 0; mf < 4; mf++)
#pragma unroll
                    for (int nf = 0; nf < 5; nf++) mma8(acc[mf][nf], a[mf], b[nf]);
            }
        }
        if (phase == 0) {
            CPWAIT0();
            __syncthreads();
        }
    }

    // all h-tile reads done; overwrite tile with z
    __syncthreads();
#pragma unroll
    for (int mf = 0; mf < 4; mf++) {
        int o = mf * 8 + grp;
        float fbv = __ldg(filt_b + layer * 32 + o);
        float gbv = __ldg(gate_b + layer * 32 + o);
        float* zrow = g_z + ((size_t)layer * 32 + o) * BT_ + t0;
#pragma unroll
        for (int nf = 0; nf < 5; nf++) {
            int p = warp * 40 + nf * 8 + 2 * tig;   // 0..318, even
            float2 zv;
            zv.x = act_z(acc[mf][nf][0] + fbv, acc[mf][nf][2] + gbv);
            zv.y = act_z(acc[mf][nf][1] + fbv, acc[mf][nf][3] + gbv);
            if (t0m == 0 && p < 64) { zv.x = 0.f; zv.y = 0.f; }  // causal zero before batch start
            *(float2*)(tile + o * WSZ + p) = zv;
            if (p >= 64) *(float2*)(zrow + p - 64) = zv;
        }
    }
    __syncthreads();

    // ---------- phase B: res mma, M=32, N=256 off smem z ----------
    float acr[2][4][4];
#pragma unroll
    for (int mf = 0; mf < 2; mf++)
#pragma unroll
        for (int nf = 0; nf < 4; nf++)
#pragma unroll
            for (int q = 0; q < 4; q++) acr[mf][nf][q] = 0.f;

#pragma unroll
    for (int tap = 0; tap < 2; tap++) {
#pragma unroll
        for (int kk = 0; kk < 4; kk++) {
            const int cb = kk * 8;
            const int kc = tap * 32 + cb;
            const int off = tap ? 64 : (64 - D);
            unsigned a[2][4];
#pragma unroll
            for (int mf = 0; mf < 2; mf++) {
                int m0 = mf * 16 + grp;
                a[mf][0] = rA[(kc + tig) * 32 + (m0 ^ xkey)];
                a[mf][1] = rA[(kc + tig) * 32 + ((m0 + 8) ^ xkey)];
                a[mf][2] = rA[(kc + tig + 4) * 32 + (m0 ^ xkey)];
                a[mf][3] = rA[(kc + tig + 4) * 32 + ((m0 + 8) ^ xkey)];
            }
            unsigned b[4][2];
#pragma unroll
            for (int nf = 0; nf < 4; nf++) {
                int n = warp * 32 + nf * 8 + grp;
                b[nf][0] = __float_as_uint(tile[(cb + tig) * WSZ + off + n]);
                b[nf][1] = __float_as_uint(tile[(cb + tig + 4) * WSZ + off + n]);
            }
#pragma unroll
            for (int mf = 0; mf < 2; mf++)
#pragma unroll
                for (int nf = 0; nf < 4; nf++) mma8(acr[mf][nf], a[mf], b[nf]);
        }
    }

#pragma unroll
    for (int mf = 0; mf < 2; mf++) {
        int o = mf * 16 + grp;
        float b0 = __ldg(res_b + layer * 32 + o);
        float b1 = __ldg(res_b + layer * 32 + o + 8);
        const float* in0 = hin + (size_t)o * BT_ + t0;
        const float* in1 = hin + (size_t)(o + 8) * BT_ + t0;
        float* out0 = hout + (size_t)o * BT_ + t0;
        float* out1 = hout + (size_t)(o + 8) * BT_ + t0;
#pragma unroll
        for (int nf = 0; nf < 4; nf++) {
            int col = warp * 32 + nf * 8 + 2 * tig;
            float2 h0 = *(const float2*)(in0 + col);
            float2 h1 = *(const float2*)(in1 + col);
            h0.x += acr[mf][nf][0] + b0;
            h0.y += acr[mf][nf][1] + b0;
            h1.x += acr[mf][nf][2] + b1;
            h1.y += acr[mf][nf][3] + b1;
            *(float2*)(out0 + col) = h0;
            *(float2*)(out1 + col) = h1;
        }
    }
}

// ---------------- k_z<D> (mma, unfused; d>=128): TWO-TILE staging -------------
template <int D>
__global__ __launch_bounds__(256, 2) void k_z(const float* __restrict__ filt_b,
                                              const float* __restrict__ gate_b,
                                              int layer, int cur) {
    float* smz = g_smem;
    unsigned* sA = (unsigned*)smz;      // 4096 words
    float* tC = smz + 4096;             // cur tile 32 x 264
    float* tP = smz + 4096 + 32 * WT2;  // prev tile 32 x 264

    int tid = threadIdx.x;
    int t0 = blockIdx.x * 256;
    int t0m = t0 & (T_ - 1);
    const float* hin = cur ? g_hB : g_hA;

    pdl_trigger();
    {
        const unsigned* asrc = g_wZ + layer * 4096;
#pragma unroll
        for (int i = 0; i < 4; i++) {
            int q = (tid + i * 256) * 4;
            CP16((uint32_t)__cvta_generic_to_shared(sA + q), asrc + q);
        }
    }
    pdl_wait();
    stage_shift<0, WT2>(tC, hin, t0, t0m, 0, tid);
    stage_shift<D, WT2>(tP, hin, t0, t0m, 0, tid);
    CPCOMMIT();
    stage_shift<0, WT2>(tC, hin, t0, t0m, 16, tid);
    stage_shift<D, WT2>(tP, hin, t0, t0m, 16, tid);
    CPCOMMIT();

    int warp = tid >> 5, lane = tid & 31;
    int grp = lane >> 2, tig = lane & 3;
    int n_off = warp * 32;
    int xkey = tig << 3;

    float acc[4][4][4];
#pragma unroll
    for (int mf = 0; mf < 4; mf++)
#pragma unroll
        for (int nf = 0; nf < 4; nf++)
#pragma unroll
            for (int q = 0; q < 4; q++) acc[mf][nf][q] = 0.f;

    CPWAIT1();
    __syncthreads();

#pragma unroll
    for (int phase = 0; phase < 2; phase++) {
#pragma unroll
        for (int tap = 0; tap < 2; tap++) {
#pragma unroll
            for (int kk = 0; kk < 2; kk++) {
                const int cb = phase * 16 + kk * 8;
                const int kc = tap * 32 + cb;
                const float* tp = tap ? tC : tP;
                unsigned a[4][4];
#pragma unroll
                for (int mf = 0; mf < 4; mf++) {
                    int m0 = mf * 16 + grp;
                    a[mf][0] = sA[(kc + tig) * 64 + (m0 ^ xkey)];
                    a[mf][1] = sA[(kc + tig) * 64 + ((m0 + 8) ^ xkey)];
                    a[mf][2] = sA[(kc + tig + 4) * 64 + (m0 ^ xkey)];
                    a[mf][3] = sA[(kc + tig + 4) * 64 + ((m0 + 8) ^ xkey)];
                }
                unsigned b[4][2];
#pragma unroll
                for (int nf = 0; nf < 4; nf++) {
                    int n = n_off + nf * 8 + grp;
                    b[nf][0] = f2tf(tp[(cb + tig) * WT2 + n]);
                    b[nf][1] = f2tf(tp[(cb + tig + 4) * WT2 + n]);
                }
#pragma unroll
                for (int mf = 0; mf < 4; mf++)
#pragma unroll
                    for (int nf = 0; nf < 4; nf++) mma8(acc[mf][nf], a[mf], b[nf]);
            }
        }
        if (phase == 0) {
            CPWAIT0();
            __syncthreads();
        }
    }

#pragma unroll
    for (int mf = 0; mf < 4; mf++) {
        int o = mf * 8 + grp;
        float fbv = __ldg(filt_b + layer * 32 + o);
        float gbv = __ldg(gate_b + layer * 32 + o);
        float* zrow = g_z + ((size_t)layer * 32 + o) * BT_ + t0;
#pragma unroll
        for (int nf = 0; nf < 4; nf++) {
            int col = n_off + nf * 8 + 2 * tig;
            float2 zv;
            zv.x = act_z(acc[mf][nf][0] + fbv, acc[mf][nf][2] + gbv);
            zv.y = act_z(acc[mf][nf][1] + fbv, acc[mf][nf][3] + gbv);
            *(float2*)(zrow + col) = zv;
        }
    }
}

// ---------------- k_res<D> (mma, unfused; d>=128): TWO-TILE, hout=hin+conv(z) -
template <int D>
__global__ __launch_bounds__(256, 2) void k_res(const float* __restrict__ res_b,
                                                int layer, int cur) {
    float* smr = g_smem;
    unsigned* sR = (unsigned*)smr;      // 2048 words
    float* tC = smr + 2048;             // cur z tile 32 x 264
    float* tP = smr + 2048 + 32 * WT2;  // prev z tile 32 x 264

    int tid = threadIdx.x;
    int t0 = blockIdx.x * 256;
    int t0m = t0 & (T_ - 1);
    const float* zL = g_z + (size_t)layer * 32 * BT_;
    const float* hin = cur ? g_hB : g_hA;
    float* hout = cur ? g_hA : g_hB;

    pdl_trigger();
    {
        const unsigned* asrc = g_wR + layer * 2048;
#pragma unroll
        for (int i = 0; i < 2; i++) {
            int q = (tid + i * 256) * 4;
            CP16((uint32_t)__cvta_generic_to_shared(sR + q), asrc + q);
        }
    }
    pdl_wait();
    stage_shift<0, WT2>(tC, zL, t0, t0m, 0, tid);
    stage_shift<D, WT2>(tP, zL, t0, t0m, 0, tid);
    CPCOMMIT();
    stage_shift<0, WT2>(tC, zL, t0, t0m, 16, tid);
    stage_shift<D, WT2>(tP, zL, t0, t0m, 16, tid);
    CPCOMMIT();

    int warp = tid >> 5, lane = tid & 31;
    int grp = lane >> 2, tig = lane & 3;
    int n_off = warp * 32;
    int xkey = tig << 3;

    float acc[2][4][4];
#pragma unroll
    for (int mf = 0; mf < 2; mf++)
#pragma unroll
        for (int nf = 0; nf < 4; nf++)
#pragma unroll
            for (int q = 0; q < 4; q++) acc[mf][nf][q] = 0.f;

    CPWAIT1();
    __syncthreads();

#pragma unroll
    for (int phase = 0; phase < 2; phase++) {
#pragma unroll
        for (int tap = 0; tap < 2; tap++) {
#pragma unroll
            for (int kk = 0; kk < 2; kk++) {
                const int cb = phase * 16 + kk * 8;
                const int kc = tap * 32 + cb;
                const float* tp = tap ? tC : tP;
                unsigned a[2][4];
#pragma unroll
                for (int mf = 0; mf < 2; mf++) {
                    int m0 = mf * 16 + grp;
                    a[mf][0] = sR[(kc + tig) * 32 + (m0 ^ xkey)];
                    a[mf][1] = sR[(kc + tig) * 32 + ((m0 + 8) ^ xkey)];
                    a[mf][2] = sR[(kc + tig + 4) * 32 + (m0 ^ xkey)];
                    a[mf][3] = sR[(kc + tig + 4) * 32 + ((m0 + 8) ^ xkey)];
                }
                unsigned b[4][2];
#pragma unroll
                for (int nf = 0; nf < 4; nf++) {
                    int n = n_off + nf * 8 + grp;
                    b[nf][0] = __float_as_uint(tp[(cb + tig) * WT2 + n]);
                    b[nf][1] = __float_as_uint(tp[(cb + tig + 4) * WT2 + n]);
                }
#pragma unroll
                for (int mf = 0; mf < 2; mf++)
#pragma unroll
                    for (int nf = 0; nf < 4; nf++) mma8(acc[mf][nf], a[mf], b[nf]);
            }
        }
        if (phase == 0) {
            CPWAIT0();
            __syncthreads();
        }
    }

#pragma unroll
    for (int mf = 0; mf < 2; mf++) {
        int o = mf * 16 + grp;
        float b0 = __ldg(res_b + layer * 32 + o);
        float b1 = __ldg(res_b + layer * 32 + o + 8);
        const float* in0 = hin + (size_t)o * BT_ + t0;
        const float* in1 = hin + (size_t)(o + 8) * BT_ + t0;
        float* out0 = hout + (size_t)o * BT_ + t0;
        float* out1 = hout + (size_t)(o + 8) * BT_ + t0;
#pragma unroll
        for (int nf = 0; nf < 4; nf++) {
            int col = n_off + nf * 8 + 2 * tig;
            float2 h0 = *(const float2*)(in0 + col);
            float2 h1 = *(const float2*)(in1 + col);
            h0.x += acc[mf][nf][0] + b0;
            h0.y += acc[mf][nf][1] + b0;
            h1.x += acc[mf][nf][2] + b1;
            h1.y += acc[mf][nf][3] + b1;
            *(float2*)(out0 + col) = h0;
            *(float2*)(out1 + col) = h1;
        }
    }
}

// ================== unified tf32 GEMM (cp.async staged, double buffered) =====
#define SAS 264
#define SBS 136
#define BUFW 12800

template <int MODE>
__device__ __forceinline__ void stage_step(unsigned* sm, int buf, int s, int t0, int tid) {
    unsigned* sA = sm + buf * BUFW;
    unsigned* sB = sm + buf * BUFW + 32 * SAS;
    const unsigned* asrc = g_wA + (MODE == 0 ? WOFF_SKIP : (MODE == 1 ? WOFF_E1 : WOFF_E2))
                         + (size_t)s * 32 * 256;
#pragma unroll
    for (int i = 0; i < 8; i++) {
        int q = tid + i * 256;
        int row = q >> 6, col = (q & 63) * 4;
        uint32_t dst = (uint32_t)__cvta_generic_to_shared(sA + row * SAS + col);
        CP16(dst, asrc + row * 256 + col);
    }
    if (MODE != 0) {
        const float* gB = (MODE == 1) ? g_skip : g_out1;
#pragma unroll
        for (int i = 0; i < 4; i++) {
            int q = tid + i * 256;
            int row = q >> 5, col = (q & 31) * 4;
            uint32_t dst = (uint32_t)__cvta_generic_to_shared(sB + row * SBS + col);
            CP16(dst, gB + (size_t)(s * 32 + row) * BT_ + t0 + col);
        }
    } else {
        int li = s >> 1, tap = s & 1;
        int d = 1 << (li % LAYERS_);
        int j = tid >> 3, l8 = tid & 7;
        const float* zrow = g_z + ((size_t)li * 32 + j) * BT_;
        if (tap == 1) {
#pragma unroll
            for (int i = 0; i < 4; i++) {
                int q = l8 + i * 8;
                uint32_t dst = (uint32_t)__cvta_generic_to_shared(sB + j * SBS + q * 4);
                CP16(dst, zrow + t0 + q * 4);
            }
        } else {
            int r = (4 - (d & 3)) & 3;
            int t0m = t0 & (T_ - 1);
            if (t0m >= d + 4) {
                const float* src = zrow + t0 - d - r;
#pragma unroll
                for (int i = 0; i < 4; i++) {
                    int q = l8 + i * 8;
                    uint32_t dst = (uint32_t)__cvta_generic_to_shared(sB + j * SBS + q * 4);
                    CP16(dst, src + q * 4);
                }
                if (l8 == 0) {
                    uint32_t dst = (uint32_t)__cvta_generic_to_shared(sB + j * SBS + 128);
                    CP16(dst, src + 128);
                }
            } else {
                for (int t = l8; t < 128; t += 8) {
                    int gm = t0 + t;
                    float v = ((gm & (T_ - 1)) >= d) ? zrow[gm - d] : 0.f;
                    sB[j * SBS + r + t] = __float_as_uint(v);
                }
            }
        }
    }
}

template <int MODE>
__global__ __launch_bounds__(256) void k_gemm(const float* __restrict__ bias,
                                              float* __restrict__ dout) {
    unsigned* sm = (unsigned*)g_smem;
    constexpr int KS = (MODE == 0) ? 80 : 8;
    int tid = threadIdx.x, warp = tid >> 5, lane = tid & 31;
    int grp = lane >> 2, tig = lane & 3;
    int t0 = blockIdx.x * 128;
    int m_off = (warp >> 1) * 64;
    int n_off = (warp & 1) * 64;

    pdl_trigger();
    pdl_wait();

    float acc[4][8][4];
#pragma unroll
    for (int mf = 0; mf < 4; mf++)
#pragma unroll
        for (int nf = 0; nf < 8; nf++)
#pragma unroll
            for (int q = 0; q < 4; q++) acc[mf][nf][q] = 0.f;

    stage_step<MODE>(sm, 0, 0, t0, tid);
    CPCOMMIT();

    int buf = 0;
#pragma unroll 1
    for (int s = 0; s < KS; s++) {
        if (s + 1 < KS) {
            stage_step<MODE>(sm, buf ^ 1, s + 1, t0, tid);
            CPCOMMIT();
            CPWAIT1();
        } else {
            CPWAIT0();
        }
        __syncthreads();

        unsigned* sA = sm + buf * BUFW;
        unsigned* sB = sm + buf * BUFW + 32 * SAS;
        int roff = 0;
        if (MODE == 0 && !(s & 1)) {
            int d = 1 << ((s >> 1) % LAYERS_);
            roff = (4 - (d & 3)) & 3;
        }
#pragma unroll
        for (int kc = 0; kc < 32; kc += 8) {
            unsigned a[4][4], b[8][2];
#pragma unroll
            for (int mf = 0; mf < 4; mf++) {
                int r0 = m_off + mf * 16 + grp;
                a[mf][0] = sA[(kc + tig) * SAS + r0];
                a[mf][1] = sA[(kc + tig) * SAS + r0 + 8];
                a[mf][2] = sA[(kc + tig + 4) * SAS + r0];
                a[mf][3] = sA[(kc + tig + 4) * SAS + r0 + 8];
            }
#pragma unroll
            for (int nf = 0; nf < 8; nf++) {
                int ci = n_off + nf * 8 + grp + roff;
                b[nf][0] = sB[(kc + tig) * SBS + ci];
                b[nf][1] = sB[(kc + tig + 4) * SBS + ci];
            }
#pragma unroll
            for (int mf = 0; mf < 4; mf++)
#pragma unroll
                for (int nf = 0; nf < 8; nf++) mma8(acc[mf][nf], a[mf], b[nf]);
        }
        __syncthreads();
        buf ^= 1;
    }

    const float* bp = (MODE == 0) ? g_skipb : bias;

    if (MODE != 2) {
        float* out = (MODE == 0) ? g_skip : g_out1;
#pragma unroll
        for (int mf = 0; mf < 4; mf++)
#pragma unroll
            for (int nf = 0; nf < 8; nf++) {
                int row0 = m_off + mf * 16 + grp;
                int col = t0 + n_off + nf * 8 + 2 * tig;
                float b0 = bp[row0];
                float b1 = bp[row0 + 8];
                float2 v0 = make_float2(rtf(fmaxf(acc[mf][nf][0] + b0, 0.f)),
                                        rtf(fmaxf(acc[mf][nf][1] + b0, 0.f)));
                float2 v1 = make_float2(rtf(fmaxf(acc[mf][nf][2] + b1, 0.f)),
                                        rtf(fmaxf(acc[mf][nf][3] + b1, 0.f)));
                *(float2*)&out[(size_t)row0 * BT_ + col] = v0;
                *(float2*)&out[(size_t)(row0 + 8) * BT_ + col] = v1;
            }
    } else {
        float* ts = (float*)sm;  // [64 tok][260]
#pragma unroll 1
        for (int h = 0; h < 2; h++) {
            __syncthreads();
            if ((warp & 1) == h) {
#pragma unroll
                for (int mf = 0; mf < 4; mf++)
#pragma unroll
                    for (int nf = 0; nf < 8; nf++) {
                        int rowL = m_off + mf * 16 + grp;
                        int colL = nf * 8 + 2 * tig;  // 0..63
                        float b0 = bp[rowL];
                        float b1 = bp[rowL + 8];
                        ts[colL * 260 + rowL] = acc[mf][nf][0] + b0;
                        ts[(colL + 1) * 260 + rowL] = acc[mf][nf][1] + b0;
                        ts[colL * 260 + rowL + 8] = acc[mf][nf][2] + b1;
                        ts[(colL + 1) * 260 + rowL + 8] = acc[mf][nf][3] + b1;
                    }
            }
            __syncthreads();
#pragma unroll
            for (int i = 0; i < 16; i++) {
                int q = tid + i * 256;
                int tk = q >> 6, c4 = (q & 63) * 4;
                float4 v = *(const float4*)&ts[tk * 260 + c4];
                *(float4*)&dout[(size_t)(t0 + h * 64 + tk) * 256 + c4] = v;
            }
        }
    }
}

// ---------------- PDL launch helper ----------------
template <typename... Args>
static void pdl_launch(void (*kern)(Args...), int grid, int block, size_t smem,
                       Args... args) {
    cudaLaunchConfig_t cfg = {};
    cfg.gridDim = dim3(grid, 1, 1);
    cfg.blockDim = dim3(block, 1, 1);
    cfg.dynamicSmemBytes = smem;
    cudaLaunchAttribute attr[1];
    attr[0].id = cudaLaunchAttributeProgrammaticStreamSerialization;
    attr[0].val.programmaticStreamSerializationAllowed = 1;
    cfg.attrs = attr;
    cfg.numAttrs = 1;
    cudaLaunchKernelEx(&cfg, kern, args...);
}

// ---------------- host launcher ----------------
extern "C" void kernel_launch(void* const* d_in, const int* in_sizes, int n_in,
                              void* d_out, int out_size) {
    const float* x      = (const float*)d_in[0];
    const float* w_in   = (const float*)d_in[1];
    const float* b_in   = (const float*)d_in[2];
    const float* filt_w = (const float*)d_in[3];
    const float* filt_b = (const float*)d_in[4];
    const float* gate_w = (const float*)d_in[5];
    const float* gate_b = (const float*)d_in[6];
    const float* res_w  = (const float*)d_in[7];
    const float* res_b  = (const float*)d_in[8];
    const float* skip_w = (const float*)d_in[9];
    const float* skip_b = (const float*)d_in[10];
    const float* end1_w = (const float*)d_in[11];
    const float* end1_b = (const float*)d_in[12];
    const float* end2_w = (const float*)d_in[13];
    const float* end2_b = (const float*)d_in[14];
    float* out = (float*)d_out;

    const int SMEM = 25600 * 4;   // GEMM: 102,400 B dynamic
    const int SMZ2 = (4096 + 2 * 32 * WT2) * 4;   // 83,968 B
    const int SMR2 = (2048 + 2 * 32 * WT2) * 4;   // 75,776 B
    cudaFuncSetAttribute(k_gemm<0>, cudaFuncAttributeMaxDynamicSharedMemorySize, SMEM);
    cudaFuncSetAttribute(k_gemm<1>, cudaFuncAttributeMaxDynamicSharedMemorySize, SMEM);
    cudaFuncSetAttribute(k_gemm<2>, cudaFuncAttributeMaxDynamicSharedMemorySize, SMEM);

#define SETF(D) \
    cudaFuncSetAttribute(k_zr<D>, cudaFuncAttributeMaxDynamicSharedMemorySize, (6144 + 32 * wshof(D)) * 4);
    SETF(1) SETF(2) SETF(4) SETF(8) SETF(16) SETF(32) SETF(64)
#undef SETF
#define SETU(D) \
    cudaFuncSetAttribute(k_z<D>,   cudaFuncAttributeMaxDynamicSharedMemorySize, SMZ2); \
    cudaFuncSetAttribute(k_res<D>, cudaFuncAttributeMaxDynamicSharedMemorySize, SMR2);
    SETU(128) SETU(256) SETU(512)
#undef SETU

    k_bias<<<1, 256>>>(skip_b);
    k_pack<<<4032, 256>>>(skip_w, end1_w, end2_w, filt_w, gate_w, res_w);
    k_input<<<BT_ / 512, 256>>>(x, w_in, b_in);

#define LAYERF(D) { \
        pdl_launch(k_zr<D>, BT_ / 256, 256, (size_t)(6144 + 32 * wshof(D)) * 4, \
                   filt_b, gate_b, res_b, i, cur); }
#define LAYERU(D) { \
        pdl_launch(k_z<D>, BT_ / 256, 256, (size_t)SMZ2, filt_b, gate_b, i, cur); \
        pdl_launch(k_res<D>, BT_ / 256, 256, (size_t)SMR2, res_b, i, cur); }

    int cur = 0;
    for (int i = 0; i < NL_; i++) {
        switch (i % LAYERS_) {
            case 0: LAYERF(1)   break;
            case 1: LAYERF(2)   break;
            case 2: LAYERF(4)   break;
            case 3: LAYERF(8)   break;
            case 4: LAYERF(16)  break;
            case 5: LAYERF(32)  break;
            case 6: LAYERF(64)  break;
            case 7: LAYERU(128) break;
            case 8: LAYERU(256) break;
            case 9: LAYERU(512) break;
        }
        cur ^= 1;
    }
#undef LAYERF
#undef LAYERU

    pdl_launch(k_gemm<0>, BT_ / 128, 256, (size_t)SMEM, (const float*)nullptr, (float*)nullptr);
    pdl_launch(k_gemm<1>, BT_ / 128, 256, (size_t)SMEM, end1_b, (float*)nullptr);
    pdl_launch(k_gemm<2>, BT_ / 128, 256, (size_t)SMEM, end2_b, out);
}

// round 16
// speedup vs baseline: 2.0191x; 1.0762x over previous
#include <cuda_runtime.h>
#include <cuda_bf16.h>
#include <stdint.h>
#include <math.h>

#define LAYERS_   10
#define NL_       40
#define RC_       32
#define DC_       32
#define SC_       256
#define EC_       256
#define CL_       256
#define B_        8
#define T_        16384
#define BT_       131072   /* B_*T_ */

typedef unsigned long long u64;

// ---------------- scratch (static device globals; no allocations) -------------
__device__ float g_hA[32 * BT_];                      // residual state ping
__device__ float g_hB[32 * BT_];                      // residual state pong
__device__ float g_z[167772160];                      // 40*32*BT, [layer][c][BT] (tf32-rounded)
__device__ float g_skip[SC_ * BT_];                   // [c][BT]  relu(skip), tf32-rounded
__device__ float g_out1[EC_ * BT_];                   // [c][BT]  relu(out1), tf32-rounded
__device__ float g_skipb[SC_];
__device__ unsigned g_wA[786432];                     // packed tf32 weights, K-major (GEMMs)
__device__ unsigned g_wZ[163840];                     // k_z mma weights [layer][64k][64m] xor-swizzled
__device__ unsigned g_wR[81920];                      // k_res mma weights [layer][64k][32m] xor-swizzled
__device__ int g_hflag[NL_][512];                     // h tile ready flags per layer
__device__ int g_zflag[NL_][512];                     // z tile ready flags per layer

#define WOFF_SKIP 0
#define WOFF_E1   655360
#define WOFF_E2   720896

// ---------------- small helpers ----------------
__device__ __forceinline__ unsigned f2tf(float x) {
    unsigned r;
    asm("cvt.rna.tf32.f32 %0, %1;" : "=r"(r) : "f"(x));
    return r;
}
__device__ __forceinline__ float rtf(float x) {      // RN-round to tf32, as float
    return __uint_as_float(f2tf(x));
}
__device__ __forceinline__ void mma8(float* d, const unsigned* a, const unsigned* b) {
    asm volatile(
        "mma.sync.aligned.m16n8k8.row.col.f32.tf32.tf32.f32 "
        "{%0,%1,%2,%3},{%4,%5,%6,%7},{%8,%9},{%0,%1,%2,%3};\n"
        : "+f"(d[0]), "+f"(d[1]), "+f"(d[2]), "+f"(d[3])
        : "r"(a[0]), "r"(a[1]), "r"(a[2]), "r"(a[3]), "r"(b[0]), "r"(b[1]));
}
__device__ __forceinline__ void fma2(u64& d, u64 a, u64 b) {
    asm("fma.rn.f32x2 %0, %1, %2, %0;" : "+l"(d) : "l"(a), "l"(b));
}
__device__ __forceinline__ u64 dup2(float x) {
    u64 r; unsigned xi = __float_as_uint(x);
    asm("mov.b64 %0, {%1, %1};" : "=l"(r) : "r"(xi));
    return r;
}
__device__ __forceinline__ float2 unpk(u64 v) {
    unsigned lo, hi;
    asm("mov.b64 {%0, %1}, %2;" : "=r"(lo), "=r"(hi) : "l"(v));
    return make_float2(__uint_as_float(lo), __uint_as_float(hi));
}
// 3-MUFU activation: tanh(f)*sigmoid(g), tf32-rounded
__device__ __forceinline__ float act_z(float fx, float gx) {
    float a = __expf(-2.f * fabsf(fx));
    float b = __expf(-gx);
    float den = (1.f + a) * (1.f + b);
    float r;
    asm("rcp.approx.f32 %0, %1;" : "=f"(r) : "f"(den));
    return rtf(copysignf((1.f - a) * r, fx));
}
// PDL + flag primitives
__device__ __forceinline__ void pdl_trigger() {
    asm volatile("griddepcontrol.launch_dependents;" ::: "memory");
}
__device__ __forceinline__ void spin_flag(const int* f) {
    int v;
    do {
        asm volatile("ld.acquire.gpu.b32 %0, [%1];" : "=r"(v) : "l"(f) : "memory");
    } while (v == 0);
}
__device__ __forceinline__ void set_flag(int* f) {
    asm volatile("st.release.gpu.b32 [%0], %1;" :: "l"(f), "r"(1) : "memory");
}

#define CP16(dst, src) asm volatile("cp.async.cg.shared.global [%0], [%1], 16;\n" :: "r"(dst), "l"(src))
#define CP16Z(dst, src, n) asm volatile("cp.async.cg.shared.global [%0], [%1], 16, %2;\n" :: "r"(dst), "l"(src), "r"(n))
#define CPCOMMIT()     asm volatile("cp.async.commit_group;\n")
#define CPWAIT1()      asm volatile("cp.async.wait_group 1;\n" ::: "memory")
#define CPWAIT0()      asm volatile("cp.async.wait_group 0;\n" ::: "memory")

// single extern-shared symbol for the whole TU (consistent type everywhere)
extern __shared__ float g_smem[];

// ---------------- flag reset (runs first every call) ----------------
__global__ void k_reset() {
    int idx = blockIdx.x * 512 + threadIdx.x;
    if (idx < NL_ * 512) {
        (&g_hflag[0][0])[idx] = 0;
        (&g_zflag[0][0])[idx] = 0;
    }
}

// ---------------- bias reduction for skip ----------------
__global__ void k_bias(const float* __restrict__ skip_b) {
    int o = threadIdx.x;
    float s = 0.f;
#pragma unroll 1
    for (int i = 0; i < NL_; i++) s += skip_b[i * SC_ + o];
    g_skipb[o] = s;
}

// ---------------- pack all weights as tf32 ----------------
__global__ void k_pack(const float* __restrict__ skip_w,
                       const float* __restrict__ e1w,
                       const float* __restrict__ e2w,
                       const float* __restrict__ filt_w,
                       const float* __restrict__ gate_w,
                       const float* __restrict__ res_w) {
    int idx = blockIdx.x * 256 + threadIdx.x;
    if (idx < WOFF_E1) {
        int k = idx >> 8, m = idx & 255;
        int li = k >> 6, tap = (k >> 5) & 1, c = k & 31;
        g_wA[idx] = f2tf(skip_w[((size_t)(li * 256 + m) * 32 + c) * 2 + tap]);
    } else if (idx < WOFF_E2) {
        int local = idx - WOFF_E1;
        int k = local >> 8, m = local & 255;
        g_wA[idx] = f2tf(e1w[m * 256 + k]);
    } else if (idx < 786432) {
        int local = idx - WOFF_E2;
        int k = local >> 8, m = local & 255;
        g_wA[idx] = f2tf(e2w[m * 256 + k]);
    } else if (idx < 786432 + 163840) {
        int local = idx - 786432;
        int layer = local >> 12;
        int rem = local & 4095;
        int k = rem >> 6, mx = rem & 63;
        int m = mx ^ ((k & 3) << 3);
        int c = k & 31, tap = k >> 5;
        int o = ((m >> 4) << 3) + (m & 7);
        int isg = (m >> 3) & 1;
        const float* w = isg ? gate_w : filt_w;
        g_wZ[local] = f2tf(w[layer * 2048 + o * 64 + c * 2 + tap]);
    } else if (idx < 786432 + 163840 + 81920) {
        int local = idx - 786432 - 163840;
        int layer = local >> 11;
        int rem = local & 2047;
        int k = rem >> 5, mx = rem & 31;
        int m = mx ^ ((k & 3) << 3);
        int c = k & 31, tap = k >> 5;
        g_wR[local] = f2tf(res_w[layer * 2048 + m * 64 + c * 2 + tap]);
    }
}

// ---------------- input 1x1 conv (fma2): x[8,256,16384] -> g_hA ---------------
__global__ __launch_bounds__(256, 2) void k_input(const float* __restrict__ x,
                                                  const float* __restrict__ w_in,
                                                  const float* __restrict__ b_in) {
    __shared__ __align__(16) float ws[256 * 32];   // [c][o]
    __shared__ float bs[32];
    int tid = threadIdx.x;
    for (int e = tid; e < 256 * 32; e += 256) {
        int c = e >> 5, rc = e & 31;
        ws[e] = w_in[rc * 256 + c];
    }
    if (tid < 32) bs[tid] = b_in[tid];
    __syncthreads();

    int i0 = blockIdx.x * 512 + tid * 2;
    int b0 = i0 >> 14, t0 = i0 & (T_ - 1);
    const float* xb = x + (size_t)b0 * 256 * T_ + t0;

    u64 a0[16], a1[16];
#pragma unroll
    for (int p = 0; p < 16; p++) { a0[p] = 0; a1[p] = 0; }

    float2 xv = *(const float2*)xb;
#pragma unroll 4
    for (int c = 0; c < 256; c++) {
        int cn = (c < 255) ? c + 1 : 255;
        float2 nxv = *(const float2*)(xb + (size_t)cn * T_);
        u64 xl = dup2(xv.x), xh = dup2(xv.y);
        const ulonglong2* w = (const ulonglong2*)&ws[c * 32];
#pragma unroll
        for (int q = 0; q < 8; q++) {
            ulonglong2 wp = w[q];
            fma2(a0[2 * q], wp.x, xl);     fma2(a0[2 * q + 1], wp.y, xl);
            fma2(a1[2 * q], wp.x, xh);     fma2(a1[2 * q + 1], wp.y, xh);
        }
        xv = nxv;
    }
#pragma unroll
    for (int p = 0; p < 16; p++) {
        int o0 = 2 * p, o1 = o0 + 1;
        float2 vl = unpk(a0[p]);
        float2 vh = unpk(a1[p]);
        float bb0 = bs[o0], bb1 = bs[o1];
        *(float2*)(g_hA + (size_t)o0 * BT_ + i0) = make_float2(vl.x + bb0, vh.x + bb0);
        *(float2*)(g_hA + (size_t)o1 * BT_ + i0) = make_float2(vl.y + bb1, vh.y + bb1);
    }
}

// host/device constexpr geometry (fused kernels)
__host__ __device__ constexpr int padof(int d) { return (d + 3) & ~3; }
__host__ __device__ constexpr int hoffof(int d) { return padof(64 + d); }
__host__ __device__ constexpr int wshof(int d) {
    int w = 256 + hoffof(d);
    return w + ((8 - (w & 31)) & 31);
}
#define WSZ 328   /* z smem tile row stride: 320 tokens + 8 pad */
#define WT2 264   /* two-tile row stride: 256 tokens + 8 pad */

// ---------------- stage channels [c0,c0+16) of halo tile (compile-time PAD/WS)
template <int PAD, int WS>
__device__ __forceinline__ void stage_halo(float* tile, const float* __restrict__ base,
                                           int t0, int t0m, int c0, int tid) {
    constexpr int NCH = (256 + PAD) >> 2;     // 16B chunks per row
    int c = c0 + (tid >> 4);                   // 16 threads per channel, 16 channels
    int j0 = tid & 15;
    const float* rowp = base + (size_t)c * BT_;
    float* srow = tile + c * WS;
#pragma unroll 1
    for (int j = j0; j < NCH; j += 16) {
        bool v = (t0m + 4 * j) >= PAD;
        const float* src = v ? (rowp + (t0 - PAD + 4 * j)) : rowp;
        uint32_t dst = (uint32_t)__cvta_generic_to_shared(srow + 4 * j);
        CP16Z(dst, src, v ? 16u : 0u);
    }
}

// ---------------- stage a plain 256-token tile shifted by -D (D%4==0) --------
template <int D, int WS>
__device__ __forceinline__ void stage_shift(float* tile, const float* __restrict__ base,
                                            int t0, int t0m, int c0, int tid) {
    int c = c0 + (tid >> 4);                   // 16 threads per channel, 16 channels
    int j0 = tid & 15;
    const float* rowp = base + (size_t)c * BT_;
    float* srow = tile + c * WS;
#pragma unroll
    for (int j = j0; j < 64; j += 16) {
        bool v = (t0m + 4 * j) >= D;
        const float* src = v ? (rowp + (t0 - D + 4 * j)) : rowp;
        uint32_t dst = (uint32_t)__cvta_generic_to_shared(srow + 4 * j);
        CP16Z(dst, src, v ? 16u : 0u);
    }
}

// ============ FUSED k_zr<D> (D<=64): z=tanh*sig over halo, then h+=conv(z) ====
template <int D>
__global__ __launch_bounds__(256, 2) void k_zr(const float* __restrict__ filt_b,
                                               const float* __restrict__ gate_b,
                                               const float* __restrict__ res_b,
                                               int layer, int cur) {
    constexpr int HOFF = hoffof(D);
    constexpr int WSH = wshof(D);
    float* smf = g_smem;
    unsigned* zA = (unsigned*)smf;            // 4096 words
    unsigned* rA = (unsigned*)smf + 4096;     // 2048 words
    float* tile = smf + 6144;                 // h tile 32 x WSH; later z tile 32 x WSZ

    int tid = threadIdx.x;
    int jt = blockIdx.x;
    int t0 = jt * 256;
    int t0m = t0 & (T_ - 1);
    const float* hin = cur ? g_hB : g_hA;
    float* hout = cur ? g_hA : g_hB;

    pdl_trigger();

    // stage weights (independent of prior layer)
    {
        const unsigned* za = g_wZ + layer * 4096;
#pragma unroll
        for (int i = 0; i < 4; i++) {
            int q = (tid + i * 256) * 4;
            CP16((uint32_t)__cvta_generic_to_shared(zA + q), za + q);
        }
        const unsigned* ra = g_wR + layer * 2048;
#pragma unroll
        for (int i = 0; i < 2; i++) {
            int q = (tid + i * 256) * 4;
            CP16((uint32_t)__cvta_generic_to_shared(rA + q), ra + q);
        }
    }
    CPCOMMIT();
    // fine-grained wait: only the producer tiles we actually read
    if (layer > 0 && tid == 0) {
        if (jt > 0) spin_flag(&g_hflag[layer - 1][jt - 1]);
        spin_flag(&g_hflag[layer - 1][jt]);
    }
    __syncthreads();

    stage_halo<HOFF, WSH>(tile, hin, t0, t0m, 0, tid);
    CPCOMMIT();
    stage_halo<HOFF, WSH>(tile, hin, t0, t0m, 16, tid);
    CPCOMMIT();

    int warp = tid >> 5, lane = tid & 31;
    int grp = lane >> 2, tig = lane & 3;
    int xkey = tig << 3;

    // ---------- phase A: z mma, N=320, warp n-tile 40 ----------
    float acc[4][5][4];
#pragma unroll
    for (int mf = 0; mf < 4; mf++)
#pragma unroll
        for (int nf = 0; nf < 5; nf++)
#pragma unroll
            for (int q = 0; q < 4; q++) acc[mf][nf][q] = 0.f;

    CPWAIT1();
    __syncthreads();

#pragma unroll
    for (int phase = 0; phase < 2; phase++) {
#pragma unroll
        for (int tap = 0; tap < 2; tap++) {
#pragma unroll
            for (int kk = 0; kk < 2; kk++) {
                const int cb = phase * 16 + kk * 8;
                const int kc = tap * 32 + cb;
                const int off = tap ? (HOFF - 64) : (HOFF - 64 - D);
                unsigned a[4][4];
#pragma unroll
                for (int mf = 0; mf < 4; mf++) {
                    int m0 = mf * 16 + grp;
                    a[mf][0] = zA[(kc + tig) * 64 + (m0 ^ xkey)];
                    a[mf][1] = zA[(kc + tig) * 64 + ((m0 + 8) ^ xkey)];
                    a[mf][2] = zA[(kc + tig + 4) * 64 + (m0 ^ xkey)];
                    a[mf][3] = zA[(kc + tig + 4) * 64 + ((m0 + 8) ^ xkey)];
                }
                unsigned b[5][2];
#pragma unroll
                for (int nf = 0; nf < 5; nf++) {
                    int n = warp * 40 + nf * 8 + grp;
                    b[nf][0] = f2tf(tile[(cb + tig) * WSH + off + n]);
                    b[nf][1] = f2tf(tile[(cb + tig + 4) * WSH + off + n]);
                }
#pragma unroll
                for (int mf = 0; mf < 4; mf++)
#pragma unroll
                    for (int nf = 0; nf < 5; nf++) mma8(acc[mf][nf], a[mf], b[nf]);
            }
        }
        if (phase == 0) {
            CPWAIT0();
            __syncthreads();
        }
    }

    // all h-tile reads done; overwrite tile with z
    __syncthreads();
#pragma unroll
    for (int mf = 0; mf < 4; mf++) {
        int o = mf * 8 + grp;
        float fbv = __ldg(filt_b + layer * 32 + o);
        float gbv = __ldg(gate_b + layer * 32 + o);
        float* zrow = g_z + ((size_t)layer * 32 + o) * BT_ + t0;
#pragma unroll
        for (int nf = 0; nf < 5; nf++) {
            int p = warp * 40 + nf * 8 + 2 * tig;   // 0..318, even
            float2 zv;
            zv.x = act_z(acc[mf][nf][0] + fbv, acc[mf][nf][2] + gbv);
            zv.y = act_z(acc[mf][nf][1] + fbv, acc[mf][nf][3] + gbv);
            if (t0m == 0 && p < 64) { zv.x = 0.f; zv.y = 0.f; }  // causal zero before batch start
            *(float2*)(tile + o * WSZ + p) = zv;
            if (p >= 64) *(float2*)(zrow + p - 64) = zv;
        }
    }
    __syncthreads();

    // ---------- phase B: res mma, M=32, N=256 off smem z ----------
    float acr[2][4][4];
#pragma unroll
    for (int mf = 0; mf < 2; mf++)
#pragma unroll
        for (int nf = 0; nf < 4; nf++)
#pragma unroll
            for (int q = 0; q < 4; q++) acr[mf][nf][q] = 0.f;

#pragma unroll
    for (int tap = 0; tap < 2; tap++) {
#pragma unroll
        for (int kk = 0; kk < 4; kk++) {
            const int cb = kk * 8;
            const int kc = tap * 32 + cb;
            const int off = tap ? 64 : (64 - D);
            unsigned a[2][4];
#pragma unroll
            for (int mf = 0; mf < 2; mf++) {
                int m0 = mf * 16 + grp;
                a[mf][0] = rA[(kc + tig) * 32 + (m0 ^ xkey)];
                a[mf][1] = rA[(kc + tig) * 32 + ((m0 + 8) ^ xkey)];
                a[mf][2] = rA[(kc + tig + 4) * 32 + (m0 ^ xkey)];
                a[mf][3] = rA[(kc + tig + 4) * 32 + ((m0 + 8) ^ xkey)];
            }
            unsigned b[4][2];
#pragma unroll
            for (int nf = 0; nf < 4; nf++) {
                int n = warp * 32 + nf * 8 + grp;
                b[nf][0] = __float_as_uint(tile[(cb + tig) * WSZ + off + n]);
                b[nf][1] = __float_as_uint(tile[(cb + tig + 4) * WSZ + off + n]);
            }
#pragma unroll
            for (int mf = 0; mf < 2; mf++)
#pragma unroll
                for (int nf = 0; nf < 4; nf++) mma8(acr[mf][nf], a[mf], b[nf]);
        }
    }

#pragma unroll
    for (int mf = 0; mf < 2; mf++) {
        int o = mf * 16 + grp;
        float b0 = __ldg(res_b + layer * 32 + o);
        float b1 = __ldg(res_b + layer * 32 + o + 8);
        const float* in0 = hin + (size_t)o * BT_ + t0;
        const float* in1 = hin + (size_t)(o + 8) * BT_ + t0;
        float* out0 = hout + (size_t)o * BT_ + t0;
        float* out1 = hout + (size_t)(o + 8) * BT_ + t0;
#pragma unroll
        for (int nf = 0; nf < 4; nf++) {
            int col = warp * 32 + nf * 8 + 2 * tig;
            float2 h0 = *(const float2*)(in0 + col);
            float2 h1 = *(const float2*)(in1 + col);
            h0.x += acr[mf][nf][0] + b0;
            h0.y += acr[mf][nf][1] + b0;
            h1.x += acr[mf][nf][2] + b1;
            h1.y += acr[mf][nf][3] + b1;
            *(float2*)(out0 + col) = h0;
            *(float2*)(out1 + col) = h1;
        }
    }

    __threadfence();
    __syncthreads();
    if (tid == 0) set_flag(&g_hflag[layer][jt]);
}

// ---------------- k_z<D> (mma, unfused; d>=128): TWO-TILE staging -------------
template <int D>
__global__ __launch_bounds__(256, 2) void k_z(const float* __restrict__ filt_b,
                                              const float* __restrict__ gate_b,
                                              int layer, int cur) {
    constexpr int NB = (D + 255) >> 8;
    float* smz = g_smem;
    unsigned* sA = (unsigned*)smz;      // 4096 words
    float* tC = smz + 4096;             // cur tile 32 x 264
    float* tP = smz + 4096 + 32 * WT2;  // prev tile 32 x 264

    int tid = threadIdx.x;
    int jt = blockIdx.x;
    int t0 = jt * 256;
    int t0m = t0 & (T_ - 1);
    const float* hin = cur ? g_hB : g_hA;

    pdl_trigger();
    {
        const unsigned* asrc = g_wZ + layer * 4096;
#pragma unroll
        for (int i = 0; i < 4; i++) {
            int q = (tid + i * 256) * 4;
            CP16((uint32_t)__cvta_generic_to_shared(sA + q), asrc + q);
        }
    }
    CPCOMMIT();
    if (tid == 0) {
#pragma unroll
        for (int b = NB; b >= 0; b--)
            if (jt - b >= 0) spin_flag(&g_hflag[layer - 1][jt - b]);
    }
    __syncthreads();

    stage_shift<0, WT2>(tC, hin, t0, t0m, 0, tid);
    stage_shift<D, WT2>(tP, hin, t0, t0m, 0, tid);
    CPCOMMIT();
    stage_shift<0, WT2>(tC, hin, t0, t0m, 16, tid);
    stage_shift<D, WT2>(tP, hin, t0, t0m, 16, tid);
    CPCOMMIT();

    int warp = tid >> 5, lane = tid & 31;
    int grp = lane >> 2, tig = lane & 3;
    int n_off = warp * 32;
    int xkey = tig << 3;

    float acc[4][4][4];
#pragma unroll
    for (int mf = 0; mf < 4; mf++)
#pragma unroll
        for (int nf = 0; nf < 4; nf++)
#pragma unroll
            for (int q = 0; q < 4; q++) acc[mf][nf][q] = 0.f;

    CPWAIT1();
    __syncthreads();

#pragma unroll
    for (int phase = 0; phase < 2; phase++) {
#pragma unroll
        for (int tap = 0; tap < 2; tap++) {
#pragma unroll
            for (int kk = 0; kk < 2; kk++) {
                const int cb = phase * 16 + kk * 8;
                const int kc = tap * 32 + cb;
                const float* tp = tap ? tC : tP;
                unsigned a[4][4];
#pragma unroll
                for (int mf = 0; mf < 4; mf++) {
                    int m0 = mf * 16 + grp;
                    a[mf][0] = sA[(kc + tig) * 64 + (m0 ^ xkey)];
                    a[mf][1] = sA[(kc + tig) * 64 + ((m0 + 8) ^ xkey)];
                    a[mf][2] = sA[(kc + tig + 4) * 64 + (m0 ^ xkey)];
                    a[mf][3] = sA[(kc + tig + 4) * 64 + ((m0 + 8) ^ xkey)];
                }
                unsigned b[4][2];
#pragma unroll
                for (int nf = 0; nf < 4; nf++) {
                    int n = n_off + nf * 8 + grp;
                    b[nf][0] = f2tf(tp[(cb + tig) * WT2 + n]);
                    b[nf][1] = f2tf(tp[(cb + tig + 4) * WT2 + n]);
                }
#pragma unroll
                for (int mf = 0; mf < 4; mf++)
#pragma unroll
                    for (int nf = 0; nf < 4; nf++) mma8(acc[mf][nf], a[mf], b[nf]);
            }
        }
        if (phase == 0) {
            CPWAIT0();
            __syncthreads();
        }
    }

#pragma unroll
    for (int mf = 0; mf < 4; mf++) {
        int o = mf * 8 + grp;
        float fbv = __ldg(filt_b + layer * 32 + o);
        float gbv = __ldg(gate_b + layer * 32 + o);
        float* zrow = g_z + ((size_t)layer * 32 + o) * BT_ + t0;
#pragma unroll
        for (int nf = 0; nf < 4; nf++) {
            int col = n_off + nf * 8 + 2 * tig;
            float2 zv;
            zv.x = act_z(acc[mf][nf][0] + fbv, acc[mf][nf][2] + gbv);
            zv.y = act_z(acc[mf][nf][1] + fbv, acc[mf][nf][3] + gbv);
            *(float2*)(zrow + col) = zv;
        }
    }

    __threadfence();
    __syncthreads();
    if (tid == 0) set_flag(&g_zflag[layer][jt]);
}

// ---------------- k_res<D> (mma, unfused; d>=128): TWO-TILE, hout=hin+conv(z) -
template <int D>
__global__ __launch_bounds__(256, 2) void k_res(const float* __restrict__ res_b,
                                                int layer, int cur) {
    constexpr int NB = (D + 255) >> 8;
    float* smr = g_smem;
    unsigned* sR = (unsigned*)smr;      // 2048 words
    float* tC = smr + 2048;             // cur z tile 32 x 264
    float* tP = smr + 2048 + 32 * WT2;  // prev z tile 32 x 264

    int tid = threadIdx.x;
    int jt = blockIdx.x;
    int t0 = jt * 256;
    int t0m = t0 & (T_ - 1);
    const float* zL = g_z + (size_t)layer * 32 * BT_;
    const float* hin = cur ? g_hB : g_hA;
    float* hout = cur ? g_hA : g_hB;

    pdl_trigger();
    {
        const unsigned* asrc = g_wR + layer * 2048;
#pragma unroll
        for (int i = 0; i < 2; i++) {
            int q = (tid + i * 256) * 4;
            CP16((uint32_t)__cvta_generic_to_shared(sR + q), asrc + q);
        }
    }
    CPCOMMIT();
    if (tid == 0) {
#pragma unroll
        for (int b = NB; b >= 0; b--)
            if (jt - b >= 0) spin_flag(&g_zflag[layer][jt - b]);
    }
    __syncthreads();

    stage_shift<0, WT2>(tC, zL, t0, t0m, 0, tid);
    stage_shift<D, WT2>(tP, zL, t0, t0m, 0, tid);
    CPCOMMIT();
    stage_shift<0, WT2>(tC, zL, t0, t0m, 16, tid);
    stage_shift<D, WT2>(tP, zL, t0, t0m, 16, tid);
    CPCOMMIT();

    int warp = tid >> 5, lane = tid & 31;
    int grp = lane >> 2, tig = lane & 3;
    int n_off = warp * 32;
    int xkey = tig << 3;

    float acc[2][4][4];
#pragma unroll
    for (int mf = 0; mf < 2; mf++)
#pragma unroll
        for (int nf = 0; nf < 4; nf++)
#pragma unroll
            for (int q = 0; q < 4; q++) acc[mf][nf][q] = 0.f;

    CPWAIT1();
    __syncthreads();

#pragma unroll
    for (int phase = 0; phase < 2; phase++) {
#pragma unroll
        for (int tap = 0; tap < 2; tap++) {
#pragma unroll
            for (int kk = 0; kk < 2; kk++) {
                const int cb = phase * 16 + kk * 8;
                const int kc = tap * 32 + cb;
                const float* tp = tap ? tC : tP;
                unsigned a[2][4];
#pragma unroll
                for (int mf = 0; mf < 2; mf++) {
                    int m0 = mf * 16 + grp;
                    a[mf][0] = sR[(kc + tig) * 32 + (m0 ^ xkey)];
                    a[mf][1] = sR[(kc + tig) * 32 + ((m0 + 8) ^ xkey)];
                    a[mf][2] = sR[(kc + tig + 4) * 32 + (m0 ^ xkey)];
                    a[mf][3] = sR[(kc + tig + 4) * 32 + ((m0 + 8) ^ xkey)];
                }
                unsigned b[4][2];
#pragma unroll
                for (int nf = 0; nf < 4; nf++) {
                    int n = n_off + nf * 8 + grp;
                    b[nf][0] = __float_as_uint(tp[(cb + tig) * WT2 + n]);
                    b[nf][1] = __float_as_uint(tp[(cb + tig + 4) * WT2 + n]);
                }
#pragma unroll
                for (int mf = 0; mf < 2; mf++)
#pragma unroll
                    for (int nf = 0; nf < 4; nf++) mma8(acc[mf][nf], a[mf], b[nf]);
            }
        }
        if (phase == 0) {
            CPWAIT0();
            __syncthreads();
        }
    }

#pragma unroll
    for (int mf = 0; mf < 2; mf++) {
        int o = mf * 16 + grp;
        float b0 = __ldg(res_b + layer * 32 + o);
        float b1 = __ldg(res_b + layer * 32 + o + 8);
        const float* in0 = hin + (size_t)o * BT_ + t0;
        const float* in1 = hin + (size_t)(o + 8) * BT_ + t0;
        float* out0 = hout + (size_t)o * BT_ + t0;
        float* out1 = hout + (size_t)(o + 8) * BT_ + t0;
#pragma unroll
        for (int nf = 0; nf < 4; nf++) {
            int col = n_off + nf * 8 + 2 * tig;
            float2 h0 = *(const float2*)(in0 + col);
            float2 h1 = *(const float2*)(in1 + col);
            h0.x += acc[mf][nf][0] + b0;
            h0.y += acc[mf][nf][1] + b0;
            h1.x += acc[mf][nf][2] + b1;
            h1.y += acc[mf][nf][3] + b1;
            *(float2*)(out0 + col) = h0;
            *(float2*)(out1 + col) = h1;
        }
    }

    __threadfence();
    __syncthreads();
    if (tid == 0) set_flag(&g_hflag[layer][jt]);
}

// ================== unified tf32 GEMM (cp.async staged, double buffered) =====
#define SAS 264
#define SBS 136
#define BUFW 12800

template <int MODE>
__device__ __forceinline__ void stage_step(unsigned* sm, int buf, int s, int t0, int tid) {
    unsigned* sA = sm + buf * BUFW;
    unsigned* sB = sm + buf * BUFW + 32 * SAS;
    const unsigned* asrc = g_wA + (MODE == 0 ? WOFF_SKIP : (MODE == 1 ? WOFF_E1 : WOFF_E2))
                         + (size_t)s * 32 * 256;
#pragma unroll
    for (int i = 0; i < 8; i++) {
        int q = tid + i * 256;
        int row = q >> 6, col = (q & 63) * 4;
        uint32_t dst = (uint32_t)__cvta_generic_to_shared(sA + row * SAS + col);
        CP16(dst, asrc + row * 256 + col);
    }
    if (MODE != 0) {
        const float* gB = (MODE == 1) ? g_skip : g_out1;
#pragma unroll
        for (int i = 0; i < 4; i++) {
            int q = tid + i * 256;
            int row = q >> 5, col = (q & 31) * 4;
            uint32_t dst = (uint32_t)__cvta_generic_to_shared(sB + row * SBS + col);
            CP16(dst, gB + (size_t)(s * 32 + row) * BT_ + t0 + col);
        }
    } else {
        int li = s >> 1, tap = s & 1;
        int d = 1 << (li % LAYERS_);
        int j = tid >> 3, l8 = tid & 7;
        const float* zrow = g_z + ((size_t)li * 32 + j) * BT_;
        if (tap == 1) {
#pragma unroll
            for (int i = 0; i < 4; i++) {
                int q = l8 + i * 8;
                uint32_t dst = (uint32_t)__cvta_generic_to_shared(sB + j * SBS + q * 4);
                CP16(dst, zrow + t0 + q * 4);
            }
        } else {
            int r = (4 - (d & 3)) & 3;
            int t0m = t0 & (T_ - 1);
            if (t0m >= d + 4) {
                const float* src = zrow + t0 - d - r;
#pragma unroll
                for (int i = 0; i < 4; i++) {
                    int q = l8 + i * 8;
                    uint32_t dst = (uint32_t)__cvta_generic_to_shared(sB + j * SBS + q * 4);
                    CP16(dst, src + q * 4);
                }
                if (l8 == 0) {
                    uint32_t dst = (uint32_t)__cvta_generic_to_shared(sB + j * SBS + 128);
                    CP16(dst, src + 128);
                }
            } else {
                for (int t = l8; t < 128; t += 8) {
                    int gm = t0 + t;
                    float v = ((gm & (T_ - 1)) >= d) ? zrow[gm - d] : 0.f;
                    sB[j * SBS + r + t] = __float_as_uint(v);
                }
            }
        }
    }
}

template <int MODE>
__global__ __launch_bounds__(256) void k_gemm(const float* __restrict__ bias,
                                              float* __restrict__ dout) {
    unsigned* sm = (unsigned*)g_smem;
    constexpr int KS = (MODE == 0) ? 80 : 8;
    int tid = threadIdx.x, warp = tid >> 5, lane = tid & 31;
    int grp = lane >> 2, tig = lane & 3;
    int t0 = blockIdx.x * 128;
    int m_off = (warp >> 1) * 64;
    int n_off = (warp & 1) * 64;

    float acc[4][8][4];
#pragma unroll
    for (int mf = 0; mf < 4; mf++)
#pragma unroll
        for (int nf = 0; nf < 8; nf++)
#pragma unroll
            for (int q = 0; q < 4; q++) acc[mf][nf][q] = 0.f;

    stage_step<MODE>(sm, 0, 0, t0, tid);
    CPCOMMIT();

    int buf = 0;
#pragma unroll 1
    for (int s = 0; s < KS; s++) {
        if (s + 1 < KS) {
            stage_step<MODE>(sm, buf ^ 1, s + 1, t0, tid);
            CPCOMMIT();
            CPWAIT1();
        } else {
            CPWAIT0();
        }
        __syncthreads();

        unsigned* sA = sm + buf * BUFW;
        unsigned* sB = sm + buf * BUFW + 32 * SAS;
        int roff = 0;
        if (MODE == 0 && !(s & 1)) {
            int d = 1 << ((s >> 1) % LAYERS_);
            roff = (4 - (d & 3)) & 3;
        }
#pragma unroll
        for (int kc = 0; kc < 32; kc += 8) {
            unsigned a[4][4], b[8][2];
#pragma unroll
            for (int mf = 0; mf < 4; mf++) {
                int r0 = m_off + mf * 16 + grp;
                a[mf][0] = sA[(kc + tig) * SAS + r0];
                a[mf][1] = sA[(kc + tig) * SAS + r0 + 8];
                a[mf][2] = sA[(kc + tig + 4) * SAS + r0];
                a[mf][3] = sA[(kc + tig + 4) * SAS + r0 + 8];
            }
#pragma unroll
            for (int nf = 0; nf < 8; nf++) {
                int ci = n_off + nf * 8 + grp + roff;
                b[nf][0] = sB[(kc + tig) * SBS + ci];
                b[nf][1] = sB[(kc + tig + 4) * SBS + ci];
            }
#pragma unroll
            for (int mf = 0; mf < 4; mf++)
#pragma unroll
                for (int nf = 0; nf < 8; nf++) mma8(acc[mf][nf], a[mf], b[nf]);
        }
        __syncthreads();
        buf ^= 1;
    }

    const float* bp = (MODE == 0) ? g_skipb : bias;

    if (MODE != 2) {
        float* out = (MODE == 0) ? g_skip : g_out1;
#pragma unroll
        for (int mf = 0; mf < 4; mf++)
#pragma unroll
            for (int nf = 0; nf < 8; nf++) {
                int row0 = m_off + mf * 16 + grp;
                int col = t0 + n_off + nf * 8 + 2 * tig;
                float b0 = bp[row0];
                float b1 = bp[row0 + 8];
                float2 v0 = make_float2(rtf(fmaxf(acc[mf][nf][0] + b0, 0.f)),
                                        rtf(fmaxf(acc[mf][nf][1] + b0, 0.f)));
                float2 v1 = make_float2(rtf(fmaxf(acc[mf][nf][2] + b1, 0.f)),
                                        rtf(fmaxf(acc[mf][nf][3] + b1, 0.f)));
                *(float2*)&out[(size_t)row0 * BT_ + col] = v0;
                *(float2*)&out[(size_t)(row0 + 8) * BT_ + col] = v1;
            }
    } else {
        float* ts = (float*)sm;  // [64 tok][260]
#pragma unroll 1
        for (int h = 0; h < 2; h++) {
            __syncthreads();
            if ((warp & 1) == h) {
#pragma unroll
                for (int mf = 0; mf < 4; mf++)
#pragma unroll
                    for (int nf = 0; nf < 8; nf++) {
                        int rowL = m_off + mf * 16 + grp;
                        int colL = nf * 8 + 2 * tig;  // 0..63
                        float b0 = bp[rowL];
                        float b1 = bp[rowL + 8];
                        ts[colL * 260 + rowL] = acc[mf][nf][0] + b0;
                        ts[(colL + 1) * 260 + rowL] = acc[mf][nf][1] + b0;
                        ts[colL * 260 + rowL + 8] = acc[mf][nf][2] + b1;
                        ts[(colL + 1) * 260 + rowL + 8] = acc[mf][nf][3] + b1;
                    }
            }
            __syncthreads();
#pragma unroll
            for (int i = 0; i < 16; i++) {
                int q = tid + i * 256;
                int tk = q >> 6, c4 = (q & 63) * 4;
                float4 v = *(const float4*)&ts[tk * 260 + c4];
                *(float4*)&dout[(size_t)(t0 + h * 64 + tk) * 256 + c4] = v;
            }
        }
    }
}

// ---------------- PDL launch helper (trigger-based early launch) ----------------
template <typename... Args>
static void pdl_launch(void (*kern)(Args...), int grid, int block, size_t smem,
                       Args... args) {
    cudaLaunchConfig_t cfg = {};
    cfg.gridDim = dim3(grid, 1, 1);
    cfg.blockDim = dim3(block, 1, 1);
    cfg.dynamicSmemBytes = smem;
    cudaLaunchAttribute attr[1];
    attr[0].id = cudaLaunchAttributeProgrammaticStreamSerialization;
    attr[0].val.programmaticStreamSerializationAllowed = 1;
    cfg.attrs = attr;
    cfg.numAttrs = 1;
    cudaLaunchKernelEx(&cfg, kern, args...);
}

// ---------------- host launcher ----------------
extern "C" void kernel_launch(void* const* d_in, const int* in_sizes, int n_in,
                              void* d_out, int out_size) {
    const float* x      = (const float*)d_in[0];
    const float* w_in   = (const float*)d_in[1];
    const float* b_in   = (const float*)d_in[2];
    const float* filt_w = (const float*)d_in[3];
    const float* filt_b = (const float*)d_in[4];
    const float* gate_w = (const float*)d_in[5];
    const float* gate_b = (const float*)d_in[6];
    const float* res_w  = (const float*)d_in[7];
    const float* res_b  = (const float*)d_in[8];
    const float* skip_w = (const float*)d_in[9];
    const float* skip_b = (const float*)d_in[10];
    const float* end1_w = (const float*)d_in[11];
    const float* end1_b = (const float*)d_in[12];
    const float* end2_w = (const float*)d_in[13];
    const float* end2_b = (const float*)d_in[14];
    float* out = (float*)d_out;

    const int SMEM = 25600 * 4;   // GEMM: 102,400 B dynamic
    const int SMZ2 = (4096 + 2 * 32 * WT2) * 4;   // 83,968 B
    const int SMR2 = (2048 + 2 * 32 * WT2) * 4;   // 75,776 B
    cudaFuncSetAttribute(k_gemm<0>, cudaFuncAttributeMaxDynamicSharedMemorySize, SMEM);
    cudaFuncSetAttribute(k_gemm<1>, cudaFuncAttributeMaxDynamicSharedMemorySize, SMEM);
    cudaFuncSetAttribute(k_gemm<2>, cudaFuncAttributeMaxDynamicSharedMemorySize, SMEM);

#define SETF(D) \
    cudaFuncSetAttribute(k_zr<D>, cudaFuncAttributeMaxDynamicSharedMemorySize, (6144 + 32 * wshof(D)) * 4);
    SETF(1) SETF(2) SETF(4) SETF(8) SETF(16) SETF(32) SETF(64)
#undef SETF
#define SETU(D) \
    cudaFuncSetAttribute(k_z<D>,   cudaFuncAttributeMaxDynamicSharedMemorySize, SMZ2); \
    cudaFuncSetAttribute(k_res<D>, cudaFuncAttributeMaxDynamicSharedMemorySize, SMR2);
    SETU(128) SETU(256) SETU(512)
#undef SETU

    k_reset<<<40, 512>>>();
    k_bias<<<1, 256>>>(skip_b);
    k_pack<<<4032, 256>>>(skip_w, end1_w, end2_w, filt_w, gate_w, res_w);
    k_input<<<BT_ / 512, 256>>>(x, w_in, b_in);

#define LAYERF(D) { \
        pdl_launch(k_zr<D>, BT_ / 256, 256, (size_t)(6144 + 32 * wshof(D)) * 4, \
                   filt_b, gate_b, res_b, i, cur); }
#define LAYERU(D) { \
        pdl_launch(k_z<D>, BT_ / 256, 256, (size_t)SMZ2, filt_b, gate_b, i, cur); \
        pdl_launch(k_res<D>, BT_ / 256, 256, (size_t)SMR2, res_b, i, cur); }

    int cur = 0;
    for (int i = 0; i < NL_; i++) {
        switch (i % LAYERS_) {
            case 0: LAYERF(1)   break;
            case 1: LAYERF(2)   break;
            case 2: LAYERF(4)   break;
            case 3: LAYERF(8)   break;
            case 4: LAYERF(16)  break;
            case 5: LAYERF(32)  break;
            case 6: LAYERF(64)  break;
            case 7: LAYERU(128) break;
            case 8: LAYERU(256) break;
            case 9: LAYERU(512) break;
        }
        cur ^= 1;
    }
#undef LAYERF
#undef LAYERU

    // GEMMs: plain launches -> full serialization after the chain
    k_gemm<0><<<BT_ / 128, 256, SMEM>>>(nullptr, nullptr);
    k_gemm<1><<<BT_ / 128, 256, SMEM>>>(end1_b, nullptr);
    k_gemm<2><<<BT_ / 128, 256, SMEM>>>(end2_b, out);
}

// round 17
// speedup vs baseline: 2.0263x; 1.0036x over previous
#include <cuda_runtime.h>
#include <cuda_bf16.h>
#include <stdint.h>
#include <math.h>

#define LAYERS_   10
#define NL_       40
#define RC_       32
#define DC_       32
#define SC_       256
#define EC_       256
#define CL_       256
#define B_        8
#define T_        16384
#define BT_       131072   /* B_*T_ */

typedef unsigned long long u64;

// ---------------- scratch (static device globals; no allocations) -------------
__device__ float g_hA[32 * BT_];                      // residual state ping
__device__ float g_hB[32 * BT_];                      // residual state pong
__device__ float g_z[167772160];                      // 40*32*BT, [layer][c][BT] (tf32-rounded)
__device__ float g_skip[SC_ * BT_];                   // [c][BT]  relu(skip), tf32-rounded
__device__ float g_out1[EC_ * BT_];                   // [c][BT]  relu(out1), tf32-rounded
__device__ float g_skipb[SC_];
__device__ unsigned g_wA[786432];                     // packed tf32 weights, K-major (GEMMs)
__device__ unsigned g_wZ[163840];                     // k_z mma weights [layer][64k][64m] xor-swizzled
__device__ unsigned g_wR[81920];                      // k_res mma weights [layer][64k][32m] xor-swizzled
__device__ int g_hflag[NL_][512];                     // h tile ready flags per layer
__device__ int g_zflag[NL_][512];                     // z tile ready flags per layer
__device__ int g_sflag[1024];                         // skip tile (128 tok) ready
__device__ int g_oflag[1024];                         // out1 tile ready

#define WOFF_SKIP 0
#define WOFF_E1   655360
#define WOFF_E2   720896

// ---------------- small helpers ----------------
__device__ __forceinline__ unsigned f2tf(float x) {
    unsigned r;
    asm("cvt.rna.tf32.f32 %0, %1;" : "=r"(r) : "f"(x));
    return r;
}
__device__ __forceinline__ float rtf(float x) {      // RN-round to tf32, as float
    return __uint_as_float(f2tf(x));
}
__device__ __forceinline__ void mma8(float* d, const unsigned* a, const unsigned* b) {
    asm volatile(
        "mma.sync.aligned.m16n8k8.row.col.f32.tf32.tf32.f32 "
        "{%0,%1,%2,%3},{%4,%5,%6,%7},{%8,%9},{%0,%1,%2,%3};\n"
        : "+f"(d[0]), "+f"(d[1]), "+f"(d[2]), "+f"(d[3])
        : "r"(a[0]), "r"(a[1]), "r"(a[2]), "r"(a[3]), "r"(b[0]), "r"(b[1]));
}
__device__ __forceinline__ void fma2(u64& d, u64 a, u64 b) {
    asm("fma.rn.f32x2 %0, %1, %2, %0;" : "+l"(d) : "l"(a), "l"(b));
}
__device__ __forceinline__ u64 dup2(float x) {
    u64 r; unsigned xi = __float_as_uint(x);
    asm("mov.b64 %0, {%1, %1};" : "=l"(r) : "r"(xi));
    return r;
}
__device__ __forceinline__ float2 unpk(u64 v) {
    unsigned lo, hi;
    asm("mov.b64 {%0, %1}, %2;" : "=r"(lo), "=r"(hi) : "l"(v));
    return make_float2(__uint_as_float(lo), __uint_as_float(hi));
}
// 3-MUFU activation: tanh(f)*sigmoid(g), tf32-rounded
__device__ __forceinline__ float act_z(float fx, float gx) {
    float a = __expf(-2.f * fabsf(fx));
    float b = __expf(-gx);
    float den = (1.f + a) * (1.f + b);
    float r;
    asm("rcp.approx.f32 %0, %1;" : "=f"(r) : "f"(den));
    return rtf(copysignf((1.f - a) * r, fx));
}
// PDL + flag primitives
__device__ __forceinline__ void pdl_trigger() {
    asm volatile("griddepcontrol.launch_dependents;" ::: "memory");
}
__device__ __forceinline__ void spin_flag(const int* f) {
    int v;
    do {
        asm volatile("ld.acquire.gpu.b32 %0, [%1];" : "=r"(v) : "l"(f) : "memory");
    } while (v == 0);
}
__device__ __forceinline__ void set_flag(int* f) {
    asm volatile("st.release.gpu.b32 [%0], %1;" :: "l"(f), "r"(1) : "memory");
}

#define CP16(dst, src) asm volatile("cp.async.cg.shared.global [%0], [%1], 16;\n" :: "r"(dst), "l"(src))
#define CP16Z(dst, src, n) asm volatile("cp.async.cg.shared.global [%0], [%1], 16, %2;\n" :: "r"(dst), "l"(src), "r"(n))
#define CPCOMMIT()     asm volatile("cp.async.commit_group;\n")
#define CPWAIT1()      asm volatile("cp.async.wait_group 1;\n" ::: "memory")
#define CPWAIT0()      asm volatile("cp.async.wait_group 0;\n" ::: "memory")

// single extern-shared symbol for the whole TU (consistent type everywhere)
extern __shared__ float g_smem[];

// ---------------- flag reset (runs first every call) ----------------
__global__ void k_reset() {
    int idx = blockIdx.x * 512 + threadIdx.x;
    if (idx < NL_ * 512) {
        (&g_hflag[0][0])[idx] = 0;
        (&g_zflag[0][0])[idx] = 0;
    }
    if (idx < 1024) {
        g_sflag[idx] = 0;
        g_oflag[idx] = 0;
    }
}

// ---------------- bias reduction for skip ----------------
__global__ void k_bias(const float* __restrict__ skip_b) {
    int o = threadIdx.x;
    float s = 0.f;
#pragma unroll 1
    for (int i = 0; i < NL_; i++) s += skip_b[i * SC_ + o];
    g_skipb[o] = s;
}

// ---------------- pack all weights as tf32 ----------------
__global__ void k_pack(const float* __restrict__ skip_w,
                       const float* __restrict__ e1w,
                       const float* __restrict__ e2w,
                       const float* __restrict__ filt_w,
                       const float* __restrict__ gate_w,
                       const float* __restrict__ res_w) {
    int idx = blockIdx.x * 256 + threadIdx.x;
    if (idx < WOFF_E1) {
        int k = idx >> 8, m = idx & 255;
        int li = k >> 6, tap = (k >> 5) & 1, c = k & 31;
        g_wA[idx] = f2tf(skip_w[((size_t)(li * 256 + m) * 32 + c) * 2 + tap]);
    } else if (idx < WOFF_E2) {
        int local = idx - WOFF_E1;
        int k = local >> 8, m = local & 255;
        g_wA[idx] = f2tf(e1w[m * 256 + k]);
    } else if (idx < 786432) {
        int local = idx - WOFF_E2;
        int k = local >> 8, m = local & 255;
        g_wA[idx] = f2tf(e2w[m * 256 + k]);
    } else if (idx < 786432 + 163840) {
        int local = idx - 786432;
        int layer = local >> 12;
        int rem = local & 4095;
        int k = rem >> 6, mx = rem & 63;
        int m = mx ^ ((k & 3) << 3);
        int c = k & 31, tap = k >> 5;
        int o = ((m >> 4) << 3) + (m & 7);
        int isg = (m >> 3) & 1;
        const float* w = isg ? gate_w : filt_w;
        g_wZ[local] = f2tf(w[layer * 2048 + o * 64 + c * 2 + tap]);
    } else if (idx < 786432 + 163840 + 81920) {
        int local = idx - 786432 - 163840;
        int layer = local >> 11;
        int rem = local & 2047;
        int k = rem >> 5, mx = rem & 31;
        int m = mx ^ ((k & 3) << 3);
        int c = k & 31, tap = k >> 5;
        g_wR[local] = f2tf(res_w[layer * 2048 + m * 64 + c * 2 + tap]);
    }
}

// ---------------- input 1x1 conv (fma2): x[8,256,16384] -> g_hA ---------------
__global__ __launch_bounds__(256, 2) void k_input(const float* __restrict__ x,
                                                  const float* __restrict__ w_in,
                                                  const float* __restrict__ b_in) {
    __shared__ __align__(16) float ws[256 * 32];   // [c][o]
    __shared__ float bs[32];
    int tid = threadIdx.x;
    for (int e = tid; e < 256 * 32; e += 256) {
        int c = e >> 5, rc = e & 31;
        ws[e] = w_in[rc * 256 + c];
    }
    if (tid < 32) bs[tid] = b_in[tid];
    __syncthreads();

    int i0 = blockIdx.x * 512 + tid * 2;
    int b0 = i0 >> 14, t0 = i0 & (T_ - 1);
    const float* xb = x + (size_t)b0 * 256 * T_ + t0;

    u64 a0[16], a1[16];
#pragma unroll
    for (int p = 0; p < 16; p++) { a0[p] = 0; a1[p] = 0; }

    float2 xv = *(const float2*)xb;
#pragma unroll 4
    for (int c = 0; c < 256; c++) {
        int cn = (c < 255) ? c + 1 : 255;
        float2 nxv = *(const float2*)(xb + (size_t)cn * T_);
        u64 xl = dup2(xv.x), xh = dup2(xv.y);
        const ulonglong2* w = (const ulonglong2*)&ws[c * 32];
#pragma unroll
        for (int q = 0; q < 8; q++) {
            ulonglong2 wp = w[q];
            fma2(a0[2 * q], wp.x, xl);     fma2(a0[2 * q + 1], wp.y, xl);
            fma2(a1[2 * q], wp.x, xh);     fma2(a1[2 * q + 1], wp.y, xh);
        }
        xv = nxv;
    }
#pragma unroll
    for (int p = 0; p < 16; p++) {
        int o0 = 2 * p, o1 = o0 + 1;
        float2 vl = unpk(a0[p]);
        float2 vh = unpk(a1[p]);
        float bb0 = bs[o0], bb1 = bs[o1];
        *(float2*)(g_hA + (size_t)o0 * BT_ + i0) = make_float2(vl.x + bb0, vh.x + bb0);
        *(float2*)(g_hA + (size_t)o1 * BT_ + i0) = make_float2(vl.y + bb1, vh.y + bb1);
    }
}

// host/device constexpr geometry (fused kernels)
__host__ __device__ constexpr int padof(int d) { return (d + 3) & ~3; }
__host__ __device__ constexpr int hoffof(int d) { return padof(64 + d); }
__host__ __device__ constexpr int wshof(int d) {
    int w = 256 + hoffof(d);
    return w + ((8 - (w & 31)) & 31);
}
#define WSZ 328   /* z smem tile row stride: 320 tokens + 8 pad */
#define WT2 264   /* two-tile row stride: 256 tokens + 8 pad */

// ---------------- stage channels [c0,c0+16) of halo tile (compile-time PAD/WS)
template <int PAD, int WS>
__device__ __forceinline__ void stage_halo(float* tile, const float* __restrict__ base,
                                           int t0, int t0m, int c0, int tid) {
    constexpr int NCH = (256 + PAD) >> 2;     // 16B chunks per row
    int c = c0 + (tid >> 4);                   // 16 threads per channel, 16 channels
    int j0 = tid & 15;
    const float* rowp = base + (size_t)c * BT_;
    float* srow = tile + c * WS;
#pragma unroll 1
    for (int j = j0; j < NCH; j += 16) {
        bool v = (t0m + 4 * j) >= PAD;
        const float* src = v ? (rowp + (t0 - PAD + 4 * j)) : rowp;
        uint32_t dst = (uint32_t)__cvta_generic_to_shared(srow + 4 * j);
        CP16Z(dst, src, v ? 16u : 0u);
    }
}

// ---------------- stage a plain 256-token tile shifted by -D (D%4==0) --------
template <int D, int WS>
__device__ __forceinline__ void stage_shift(float* tile, const float* __restrict__ base,
                                            int t0, int t0m, int c0, int tid) {
    int c = c0 + (tid >> 4);                   // 16 threads per channel, 16 channels
    int j0 = tid & 15;
    const float* rowp = base + (size_t)c * BT_;
    float* srow = tile + c * WS;
#pragma unroll
    for (int j = j0; j < 64; j += 16) {
        bool v = (t0m + 4 * j) >= D;
        const float* src = v ? (rowp + (t0 - D + 4 * j)) : rowp;
        uint32_t dst = (uint32_t)__cvta_generic_to_shared(srow + 4 * j);
        CP16Z(dst, src, v ? 16u : 0u);
    }
}

// ============ FUSED k_zr<D> (D<=64): z=tanh*sig over halo, then h+=conv(z) ====
template <int D>
__global__ __launch_bounds__(256, 2) void k_zr(const float* __restrict__ filt_b,
                                               const float* __restrict__ gate_b,
                                               const float* __restrict__ res_b,
                                               int layer, int cur) {
    constexpr int HOFF = hoffof(D);
    constexpr int WSH = wshof(D);
    float* smf = g_smem;
    unsigned* zA = (unsigned*)smf;            // 4096 words
    unsigned* rA = (unsigned*)smf + 4096;     // 2048 words
    float* tile = smf + 6144;                 // h tile 32 x WSH; later z tile 32 x WSZ

    int tid = threadIdx.x;
    int jt = blockIdx.x;
    int t0 = jt * 256;
    int t0m = t0 & (T_ - 1);
    const float* hin = cur ? g_hB : g_hA;
    float* hout = cur ? g_hA : g_hB;

    pdl_trigger();

    // stage weights (independent of prior layer)
    {
        const unsigned* za = g_wZ + layer * 4096;
#pragma unroll
        for (int i = 0; i < 4; i++) {
            int q = (tid + i * 256) * 4;
            CP16((uint32_t)__cvta_generic_to_shared(zA + q), za + q);
        }
        const unsigned* ra = g_wR + layer * 2048;
#pragma unroll
        for (int i = 0; i < 2; i++) {
            int q = (tid + i * 256) * 4;
            CP16((uint32_t)__cvta_generic_to_shared(rA + q), ra + q);
        }
    }
    CPCOMMIT();
    // fine-grained wait: only the producer tiles we actually read
    if (layer > 0 && tid == 0) {
        if (jt > 0) spin_flag(&g_hflag[layer - 1][jt - 1]);
        spin_flag(&g_hflag[layer - 1][jt]);
    }
    __syncthreads();

    stage_halo<HOFF, WSH>(tile, hin, t0, t0m, 0, tid);
    CPCOMMIT();
    stage_halo<HOFF, WSH>(tile, hin, t0, t0m, 16, tid);
    CPCOMMIT();

    int warp = tid >> 5, lane = tid & 31;
    int grp = lane >> 2, tig = lane & 3;
    int xkey = tig << 3;

    // ---------- phase A: z mma, N=320, warp n-tile 40 ----------
    float acc[4][5][4];
#pragma unroll
    for (int mf = 0; mf < 4; mf++)
#pragma unroll
        for (int nf = 0; nf < 5; nf++)
#pragma unroll
            for (int q = 0; q < 4; q++) acc[mf][nf][q] = 0.f;

    CPWAIT1();
    __syncthreads();

#pragma unroll
    for (int phase = 0; phase < 2; phase++) {
#pragma unroll
        for (int tap = 0; tap < 2; tap++) {
#pragma unroll
            for (int kk = 0; kk < 2; kk++) {
                const int cb = phase * 16 + kk * 8;
                const int kc = tap * 32 + cb;
                const int off = tap ? (HOFF - 64) : (HOFF - 64 - D);
                unsigned a[4][4];
#pragma unroll
                for (int mf = 0; mf < 4; mf++) {
                    int m0 = mf * 16 + grp;
                    a[mf][0] = zA[(kc + tig) * 64 + (m0 ^ xkey)];
                    a[mf][1] = zA[(kc + tig) * 64 + ((m0 + 8) ^ xkey)];
                    a[mf][2] = zA[(kc + tig + 4) * 64 + (m0 ^ xkey)];
                    a[mf][3] = zA[(kc + tig + 4) * 64 + ((m0 + 8) ^ xkey)];
                }
                unsigned b[5][2];
#pragma unroll
                for (int nf = 0; nf < 5; nf++) {
                    int n = warp * 40 + nf * 8 + grp;
                    b[nf][0] = f2tf(tile[(cb + tig) * WSH + off + n]);
                    b[nf][1] = f2tf(tile[(cb + tig + 4) * WSH + off + n]);
                }
#pragma unroll
                for (int mf = 0; mf < 4; mf++)
#pragma unroll
                    for (int nf = 0; nf < 5; nf++) mma8(acc[mf][nf], a[mf], b[nf]);
            }
        }
        if (phase == 0) {
            CPWAIT0();
            __syncthreads();
        }
    }

    // all h-tile reads done; overwrite tile with z
    __syncthreads();
#pragma unroll
    for (int mf = 0; mf < 4; mf++) {
        int o = mf * 8 + grp;
        float fbv = __ldg(filt_b + layer * 32 + o);
        float gbv = __ldg(gate_b + layer * 32 + o);
        float* zrow = g_z + ((size_t)layer * 32 + o) * BT_ + t0;
#pragma unroll
        for (int nf = 0; nf < 5; nf++) {
            int p = warp * 40 + nf * 8 + 2 * tig;   // 0..318, even
            float2 zv;
            zv.x = act_z(acc[mf][nf][0] + fbv, acc[mf][nf][2] + gbv);
            zv.y = act_z(acc[mf][nf][1] + fbv, acc[mf][nf][3] + gbv);
            if (t0m == 0 && p < 64) { zv.x = 0.f; zv.y = 0.f; }  // causal zero before batch start
            *(float2*)(tile + o * WSZ + p) = zv;
            if (p >= 64) *(float2*)(zrow + p - 64) = zv;
        }
    }
    __syncthreads();

    // ---------- phase B: res mma, M=32, N=256 off smem z ----------
    float acr[2][4][4];
#pragma unroll
    for (int mf = 0; mf < 2; mf++)
#pragma unroll
        for (int nf = 0; nf < 4; nf++)
#pragma unroll
            for (int q = 0; q < 4; q++) acr[mf][nf][q] = 0.f;

#pragma unroll
    for (int tap = 0; tap < 2; tap++) {
#pragma unroll
        for (int kk = 0; kk < 4; kk++) {
            const int cb = kk * 8;
            const int kc = tap * 32 + cb;
            const int off = tap ? 64 : (64 - D);
            unsigned a[2][4];
#pragma unroll
            for (int mf = 0; mf < 2; mf++) {
                int m0 = mf * 16 + grp;
                a[mf][0] = rA[(kc + tig) * 32 + (m0 ^ xkey)];
                a[mf][1] = rA[(kc + tig) * 32 + ((m0 + 8) ^ xkey)];
                a[mf][2] = rA[(kc + tig + 4) * 32 + (m0 ^ xkey)];
                a[mf][3] = rA[(kc + tig + 4) * 32 + ((m0 + 8) ^ xkey)];
            }
            unsigned b[4][2];
#pragma unroll
            for (int nf = 0; nf < 4; nf++) {
                int n = warp * 32 + nf * 8 + grp;
                b[nf][0] = __float_as_uint(tile[(cb + tig) * WSZ + off + n]);
                b[nf][1] = __float_as_uint(tile[(cb + tig + 4) * WSZ + off + n]);
            }
#pragma unroll
            for (int mf = 0; mf < 2; mf++)
#pragma unroll
                for (int nf = 0; nf < 4; nf++) mma8(acr[mf][nf], a[mf], b[nf]);
        }
    }

#pragma unroll
    for (int mf = 0; mf < 2; mf++) {
        int o = mf * 16 + grp;
        float b0 = __ldg(res_b + layer * 32 + o);
        float b1 = __ldg(res_b + layer * 32 + o + 8);
        const float* in0 = hin + (size_t)o * BT_ + t0;
        const float* in1 = hin + (size_t)(o + 8) * BT_ + t0;
        float* out0 = hout + (size_t)o * BT_ + t0;
        float* out1 = hout + (size_t)(o + 8) * BT_ + t0;
#pragma unroll
        for (int nf = 0; nf < 4; nf++) {
            int col = warp * 32 + nf * 8 + 2 * tig;
            float2 h0 = *(const float2*)(in0 + col);
            float2 h1 = *(const float2*)(in1 + col);
            h0.x += acr[mf][nf][0] + b0;
            h0.y += acr[mf][nf][1] + b0;
            h1.x += acr[mf][nf][2] + b1;
            h1.y += acr[mf][nf][3] + b1;
            *(float2*)(out0 + col) = h0;
            *(float2*)(out1 + col) = h1;
        }
    }

    __threadfence();
    __syncthreads();
    if (tid == 0) {
        set_flag(&g_hflag[layer][jt]);
        set_flag(&g_zflag[layer][jt]);
    }
}

// ---------------- k_z<D> (mma, unfused; d>=128): TWO-TILE staging -------------
template <int D>
__global__ __launch_bounds__(256, 2) void k_z(const float* __restrict__ filt_b,
                                              const float* __restrict__ gate_b,
                                              int layer, int cur) {
    constexpr int NB = (D + 255) >> 8;
    float* smz = g_smem;
    unsigned* sA = (unsigned*)smz;      // 4096 words
    float* tC = smz + 4096;             // cur tile 32 x 264
    float* tP = smz + 4096 + 32 * WT2;  // prev tile 32 x 264

    int tid = threadIdx.x;
    int jt = blockIdx.x;
    int t0 = jt * 256;
    int t0m = t0 & (T_ - 1);
    const float* hin = cur ? g_hB : g_hA;

    pdl_trigger();
    {
        const unsigned* asrc = g_wZ + layer * 4096;
#pragma unroll
        for (int i = 0; i < 4; i++) {
            int q = (tid + i * 256) * 4;
            CP16((uint32_t)__cvta_generic_to_shared(sA + q), asrc + q);
        }
    }
    CPCOMMIT();
    if (tid == 0) {
#pragma unroll
        for (int b = NB; b >= 0; b--)
            if (jt - b >= 0) spin_flag(&g_hflag[layer - 1][jt - b]);
    }
    __syncthreads();

    stage_shift<0, WT2>(tC, hin, t0, t0m, 0, tid);
    stage_shift<D, WT2>(tP, hin, t0, t0m, 0, tid);
    CPCOMMIT();
    stage_shift<0, WT2>(tC, hin, t0, t0m, 16, tid);
    stage_shift<D, WT2>(tP, hin, t0, t0m, 16, tid);
    CPCOMMIT();

    int warp = tid >> 5, lane = tid & 31;
    int grp = lane >> 2, tig = lane & 3;
    int n_off = warp * 32;
    int xkey = tig << 3;

    float acc[4][4][4];
#pragma unroll
    for (int mf = 0; mf < 4; mf++)
#pragma unroll
        for (int nf = 0; nf < 4; nf++)
#pragma unroll
            for (int q = 0; q < 4; q++) acc[mf][nf][q] = 0.f;

    CPWAIT1();
    __syncthreads();

#pragma unroll
    for (int phase = 0; phase < 2; phase++) {
#pragma unroll
        for (int tap = 0; tap < 2; tap++) {
#pragma unroll
            for (int kk = 0; kk < 2; kk++) {
                const int cb = phase * 16 + kk * 8;
                const int kc = tap * 32 + cb;
                const float* tp = tap ? tC : tP;
                unsigned a[4][4];
#pragma unroll
                for (int mf = 0; mf < 4; mf++) {
                    int m0 = mf * 16 + grp;
                    a[mf][0] = sA[(kc + tig) * 64 + (m0 ^ xkey)];
                    a[mf][1] = sA[(kc + tig) * 64 + ((m0 + 8) ^ xkey)];
                    a[mf][2] = sA[(kc + tig + 4) * 64 + (m0 ^ xkey)];
                    a[mf][3] = sA[(kc + tig + 4) * 64 + ((m0 + 8) ^ xkey)];
                }
                unsigned b[4][2];
#pragma unroll
                for (int nf = 0; nf < 4; nf++) {
                    int n = n_off + nf * 8 + grp;
                    b[nf][0] = f2tf(tp[(cb + tig) * WT2 + n]);
                    b[nf][1] = f2tf(tp[(cb + tig + 4) * WT2 + n]);
                }
#pragma unroll
                for (int mf = 0; mf < 4; mf++)
#pragma unroll
                    for (int nf = 0; nf < 4; nf++) mma8(acc[mf][nf], a[mf], b[nf]);
            }
        }
        if (phase == 0) {
            CPWAIT0();
            __syncthreads();
        }
    }

#pragma unroll
    for (int mf = 0; mf < 4; mf++) {
        int o = mf * 8 + grp;
        float fbv = __ldg(filt_b + layer * 32 + o);
        float gbv = __ldg(gate_b + layer * 32 + o);
        float* zrow = g_z + ((size_t)layer * 32 + o) * BT_ + t0;
#pragma unroll
        for (int nf = 0; nf < 4; nf++) {
            int col = n_off + nf * 8 + 2 * tig;
            float2 zv;
            zv.x = act_z(acc[mf][nf][0] + fbv, acc[mf][nf][2] + gbv);
            zv.y = act_z(acc[mf][nf][1] + fbv, acc[mf][nf][3] + gbv);
            *(float2*)(zrow + col) = zv;
        }
    }

    __threadfence();
    __syncthreads();
    if (tid == 0) set_flag(&g_zflag[layer][jt]);
}

// ---------------- k_res<D> (mma, unfused; d>=128): TWO-TILE, hout=hin+conv(z) -
template <int D>
__global__ __launch_bounds__(256, 2) void k_res(const float* __restrict__ res_b,
                                                int layer, int cur) {
    constexpr int NB = (D + 255) >> 8;
    float* smr = g_smem;
    unsigned* sR = (unsigned*)smr;      // 2048 words
    float* tC = smr + 2048;             // cur z tile 32 x 264
    float* tP = smr + 2048 + 32 * WT2;  // prev z tile 32 x 264

    int tid = threadIdx.x;
    int jt = blockIdx.x;
    int t0 = jt * 256;
    int t0m = t0 & (T_ - 1);
    const float* zL = g_z + (size_t)layer * 32 * BT_;
    const float* hin = cur ? g_hB : g_hA;
    float* hout = cur ? g_hA : g_hB;

    pdl_trigger();
    {
        const unsigned* asrc = g_wR + layer * 2048;
#pragma unroll
        for (int i = 0; i < 2; i++) {
            int q = (tid + i * 256) * 4;
            CP16((uint32_t)__cvta_generic_to_shared(sR + q), asrc + q);
        }
    }
    CPCOMMIT();
    if (tid == 0) {
#pragma unroll
        for (int b = NB; b >= 0; b--)
            if (jt - b >= 0) spin_flag(&g_zflag[layer][jt - b]);
    }
    __syncthreads();

    stage_shift<0, WT2>(tC, zL, t0, t0m, 0, tid);
    stage_shift<D, WT2>(tP, zL, t0, t0m, 0, tid);
    CPCOMMIT();
    stage_shift<0, WT2>(tC, zL, t0, t0m, 16, tid);
    stage_shift<D, WT2>(tP, zL, t0, t0m, 16, tid);
    CPCOMMIT();

    int warp = tid >> 5, lane = tid & 31;
    int grp = lane >> 2, tig = lane & 3;
    int n_off = warp * 32;
    int xkey = tig << 3;

    float acc[2][4][4];
#pragma unroll
    for (int mf = 0; mf < 2; mf++)
#pragma unroll
        for (int nf = 0; nf < 4; nf++)
#pragma unroll
            for (int q = 0; q < 4; q++) acc[mf][nf][q] = 0.f;

    CPWAIT1();
    __syncthreads();

#pragma unroll
    for (int phase = 0; phase < 2; phase++) {
#pragma unroll
        for (int tap = 0; tap < 2; tap++) {
#pragma unroll
            for (int kk = 0; kk < 2; kk++) {
                const int cb = phase * 16 + kk * 8;
                const int kc = tap * 32 + cb;
                const float* tp = tap ? tC : tP;
                unsigned a[2][4];
#pragma unroll
                for (int mf = 0; mf < 2; mf++) {
                    int m0 = mf * 16 + grp;
                    a[mf][0] = sR[(kc + tig) * 32 + (m0 ^ xkey)];
                    a[mf][1] = sR[(kc + tig) * 32 + ((m0 + 8) ^ xkey)];
                    a[mf][2] = sR[(kc + tig + 4) * 32 + (m0 ^ xkey)];
                    a[mf][3] = sR[(kc + tig + 4) * 32 + ((m0 + 8) ^ xkey)];
                }
                unsigned b[4][2];
#pragma unroll
                for (int nf = 0; nf < 4; nf++) {
                    int n = n_off + nf * 8 + grp;
                    b[nf][0] = __float_as_uint(tp[(cb + tig) * WT2 + n]);
                    b[nf][1] = __float_as_uint(tp[(cb + tig + 4) * WT2 + n]);
                }
#pragma unroll
                for (int mf = 0; mf < 2; mf++)
#pragma unroll
                    for (int nf = 0; nf < 4; nf++) mma8(acc[mf][nf], a[mf], b[nf]);
            }
        }
        if (phase == 0) {
            CPWAIT0();
            __syncthreads();
        }
    }

#pragma unroll
    for (int mf = 0; mf < 2; mf++) {
        int o = mf * 16 + grp;
        float b0 = __ldg(res_b + layer * 32 + o);
        float b1 = __ldg(res_b + layer * 32 + o + 8);
        const float* in0 = hin + (size_t)o * BT_ + t0;
        const float* in1 = hin + (size_t)(o + 8) * BT_ + t0;
        float* out0 = hout + (size_t)o * BT_ + t0;
        float* out1 = hout + (size_t)(o + 8) * BT_ + t0;
#pragma unroll
        for (int nf = 0; nf < 4; nf++) {
            int col = n_off + nf * 8 + 2 * tig;
            float2 h0 = *(const float2*)(in0 + col);
            float2 h1 = *(const float2*)(in1 + col);
            h0.x += acc[mf][nf][0] + b0;
            h0.y += acc[mf][nf][1] + b0;
            h1.x += acc[mf][nf][2] + b1;
            h1.y += acc[mf][nf][3] + b1;
            *(float2*)(out0 + col) = h0;
            *(float2*)(out1 + col) = h1;
        }
    }

    __threadfence();
    __syncthreads();
    if (tid == 0) set_flag(&g_hflag[layer][jt]);
}

// ================== unified tf32 GEMM (cp.async staged, double buffered) =====
#define SAS 264
#define SBS 136
#define BUFW 12800

template <int MODE>
__device__ __forceinline__ void stage_step(unsigned* sm, int buf, int s, int t0, int tid) {
    unsigned* sA = sm + buf * BUFW;
    unsigned* sB = sm + buf * BUFW + 32 * SAS;
    const unsigned* asrc = g_wA + (MODE == 0 ? WOFF_SKIP : (MODE == 1 ? WOFF_E1 : WOFF_E2))
                         + (size_t)s * 32 * 256;
#pragma unroll
    for (int i = 0; i < 8; i++) {
        int q = tid + i * 256;
        int row = q >> 6, col = (q & 63) * 4;
        uint32_t dst = (uint32_t)__cvta_generic_to_shared(sA + row * SAS + col);
        CP16(dst, asrc + row * 256 + col);
    }
    if (MODE != 0) {
        const float* gB = (MODE == 1) ? g_skip : g_out1;
#pragma unroll
        for (int i = 0; i < 4; i++) {
            int q = tid + i * 256;
            int row = q >> 5, col = (q & 31) * 4;
            uint32_t dst = (uint32_t)__cvta_generic_to_shared(sB + row * SBS + col);
            CP16(dst, gB + (size_t)(s * 32 + row) * BT_ + t0 + col);
        }
    } else {
        int li = s >> 1, tap = s & 1;
        int d = 1 << (li % LAYERS_);
        int j = tid >> 3, l8 = tid & 7;
        const float* zrow = g_z + ((size_t)li * 32 + j) * BT_;
        if (tap == 1) {
#pragma unroll
            for (int i = 0; i < 4; i++) {
                int q = l8 + i * 8;
                uint32_t dst = (uint32_t)__cvta_generic_to_shared(sB + j * SBS + q * 4);
                CP16(dst, zrow + t0 + q * 4);
            }
        } else {
            int r = (4 - (d & 3)) & 3;
            int t0m = t0 & (T_ - 1);
            if (t0m >= d + 4) {
                const float* src = zrow + t0 - d - r;
#pragma unroll
                for (int i = 0; i < 4; i++) {
                    int q = l8 + i * 8;
                    uint32_t dst = (uint32_t)__cvta_generic_to_shared(sB + j * SBS + q * 4);
                    CP16(dst, src + q * 4);
                }
                if (l8 == 0) {
                    uint32_t dst = (uint32_t)__cvta_generic_to_shared(sB + j * SBS + 128);
                    CP16(dst, src + 128);
                }
            } else {
                for (int t = l8; t < 128; t += 8) {
                    int gm = t0 + t;
                    float v = ((gm & (T_ - 1)) >= d) ? zrow[gm - d] : 0.f;
                    sB[j * SBS + r + t] = __float_as_uint(v);
                }
            }
        }
    }
}

template <int MODE>
__global__ __launch_bounds__(256) void k_gemm(const float* __restrict__ bias,
                                              float* __restrict__ dout) {
    unsigned* sm = (unsigned*)g_smem;
    constexpr int KS = (MODE == 0) ? 80 : 8;
    int tid = threadIdx.x, warp = tid >> 5, lane = tid & 31;
    int grp = lane >> 2, tig = lane & 3;
    int t0 = blockIdx.x * 128;
    int m_off = (warp >> 1) * 64;
    int n_off = (warp & 1) * 64;

    pdl_trigger();

    // fine-grained readiness: only the tiles this CTA reads
    if (MODE == 0) {
        int jt2 = t0 >> 8;
        if (tid < 160) {
            int l = tid >> 2, b = jt2 - (tid & 3);
            if (b >= 0) spin_flag(&g_zflag[l][b]);
        }
    } else if (MODE == 1) {
        if (tid == 0) spin_flag(&g_sflag[blockIdx.x]);
    } else {
        if (tid == 0) spin_flag(&g_oflag[blockIdx.x]);
    }
    __syncthreads();

    float acc[4][8][4];
#pragma unroll
    for (int mf = 0; mf < 4; mf++)
#pragma unroll
        for (int nf = 0; nf < 8; nf++)
#pragma unroll
            for (int q = 0; q < 4; q++) acc[mf][nf][q] = 0.f;

    stage_step<MODE>(sm, 0, 0, t0, tid);
    CPCOMMIT();

    int buf = 0;
#pragma unroll 1
    for (int s = 0; s < KS; s++) {
        if (s + 1 < KS) {
            stage_step<MODE>(sm, buf ^ 1, s + 1, t0, tid);
            CPCOMMIT();
            CPWAIT1();
        } else {
            CPWAIT0();
        }
        __syncthreads();

        unsigned* sA = sm + buf * BUFW;
        unsigned* sB = sm + buf * BUFW + 32 * SAS;
        int roff = 0;
        if (MODE == 0 && !(s & 1)) {
            int d = 1 << ((s >> 1) % LAYERS_);
            roff = (4 - (d & 3)) & 3;
        }
#pragma unroll
        for (int kc = 0; kc < 32; kc += 8) {
            unsigned a[4][4], b[8][2];
#pragma unroll
            for (int mf = 0; mf < 4; mf++) {
                int r0 = m_off + mf * 16 + grp;
                a[mf][0] = sA[(kc + tig) * SAS + r0];
                a[mf][1] = sA[(kc + tig) * SAS + r0 + 8];
                a[mf][2] = sA[(kc + tig + 4) * SAS + r0];
                a[mf][3] = sA[(kc + tig + 4) * SAS + r0 + 8];
            }
#pragma unroll
            for (int nf = 0; nf < 8; nf++) {
                int ci = n_off + nf * 8 + grp + roff;
                b[nf][0] = sB[(kc + tig) * SBS + ci];
                b[nf][1] = sB[(kc + tig + 4) * SBS + ci];
            }
#pragma unroll
            for (int mf = 0; mf < 4; mf++)
#pragma unroll
                for (int nf = 0; nf < 8; nf++) mma8(acc[mf][nf], a[mf], b[nf]);
        }
        __syncthreads();
        buf ^= 1;
    }

    const float* bp = (MODE == 0) ? g_skipb : bias;

    if (MODE != 2) {
        float* out = (MODE == 0) ? g_skip : g_out1;
#pragma unroll
        for (int mf = 0; mf < 4; mf++)
#pragma unroll
            for (int nf = 0; nf < 8; nf++) {
                int row0 = m_off + mf * 16 + grp;
                int col = t0 + n_off + nf * 8 + 2 * tig;
                float b0 = bp[row0];
                float b1 = bp[row0 + 8];
                float2 v0 = make_float2(rtf(fmaxf(acc[mf][nf][0] + b0, 0.f)),
                                        rtf(fmaxf(acc[mf][nf][1] + b0, 0.f)));
                float2 v1 = make_float2(rtf(fmaxf(acc[mf][nf][2] + b1, 0.f)),
                                        rtf(fmaxf(acc[mf][nf][3] + b1, 0.f)));
                *(float2*)&out[(size_t)row0 * BT_ + col] = v0;
                *(float2*)&out[(size_t)(row0 + 8) * BT_ + col] = v1;
            }
        __threadfence();
        __syncthreads();
        if (tid == 0) {
            if (MODE == 0) set_flag(&g_sflag[blockIdx.x]);
            else set_flag(&g_oflag[blockIdx.x]);
        }
    } else {
        float* ts = (float*)sm;  // [64 tok][260]
#pragma unroll 1
        for (int h = 0; h < 2; h++) {
            __syncthreads();
            if ((warp & 1) == h) {
#pragma unroll
                for (int mf = 0; mf < 4; mf++)
#pragma unroll
                    for (int nf = 0; nf < 8; nf++) {
                        int rowL = m_off + mf * 16 + grp;
                        int colL = nf * 8 + 2 * tig;  // 0..63
                        float b0 = bp[rowL];
                        float b1 = bp[rowL + 8];
                        ts[colL * 260 + rowL] = acc[mf][nf][0] + b0;
                        ts[(colL + 1) * 260 + rowL] = acc[mf][nf][1] + b0;
                        ts[colL * 260 + rowL + 8] = acc[mf][nf][2] + b1;
                        ts[(colL + 1) * 260 + rowL + 8] = acc[mf][nf][3] + b1;
                    }
            }
            __syncthreads();
#pragma unroll
            for (int i = 0; i < 16; i++) {
                int q = tid + i * 256;
                int tk = q >> 6, c4 = (q & 63) * 4;
                float4 v = *(const float4*)&ts[tk * 260 + c4];
                *(float4*)&dout[(size_t)(t0 + h * 64 + tk) * 256 + c4] = v;
            }
        }
    }
}

// ---------------- PDL launch helper (trigger-based early launch) ----------------
template <typename... Args>
static void pdl_launch(void (*kern)(Args...), int grid, int block, size_t smem,
                       Args... args) {
    cudaLaunchConfig_t cfg = {};
    cfg.gridDim = dim3(grid, 1, 1);
    cfg.blockDim = dim3(block, 1, 1);
    cfg.dynamicSmemBytes = smem;
    cudaLaunchAttribute attr[1];
    attr[0].id = cudaLaunchAttributeProgrammaticStreamSerialization;
    attr[0].val.programmaticStreamSerializationAllowed = 1;
    cfg.attrs = attr;
    cfg.numAttrs = 1;
    cudaLaunchKernelEx(&cfg, kern, args...);
}

// ---------------- host launcher ----------------
extern "C" void kernel_launch(void* const* d_in, const int* in_sizes, int n_in,
                              void* d_out, int out_size) {
    const float* x      = (const float*)d_in[0];
    const float* w_in   = (const float*)d_in[1];
    const float* b_in   = (const float*)d_in[2];
    const float* filt_w = (const float*)d_in[3];
    const float* filt_b = (const float*)d_in[4];
    const float* gate_w = (const float*)d_in[5];
    const float* gate_b = (const float*)d_in[6];
    const float* res_w  = (const float*)d_in[7];
    const float* res_b  = (const float*)d_in[8];
    const float* skip_w = (const float*)d_in[9];
    const float* skip_b = (const float*)d_in[10];
    const float* end1_w = (const float*)d_in[11];
    const float* end1_b = (const float*)d_in[12];
    const float* end2_w = (const float*)d_in[13];
    const float* end2_b = (const float*)d_in[14];
    float* out = (float*)d_out;

    const int SMEM = 25600 * 4;   // GEMM: 102,400 B dynamic
    const int SMZ2 = (4096 + 2 * 32 * WT2) * 4;   // 83,968 B
    const int SMR2 = (2048 + 2 * 32 * WT2) * 4;   // 75,776 B
    cudaFuncSetAttribute(k_gemm<0>, cudaFuncAttributeMaxDynamicSharedMemorySize, SMEM);
    cudaFuncSetAttribute(k_gemm<1>, cudaFuncAttributeMaxDynamicSharedMemorySize, SMEM);
    cudaFuncSetAttribute(k_gemm<2>, cudaFuncAttributeMaxDynamicSharedMemorySize, SMEM);

#define SETF(D) \
    cudaFuncSetAttribute(k_zr<D>, cudaFuncAttributeMaxDynamicSharedMemorySize, (6144 + 32 * wshof(D)) * 4);
    SETF(1) SETF(2) SETF(4) SETF(8) SETF(16) SETF(32) SETF(64)
#undef SETF
#define SETU(D) \
    cudaFuncSetAttribute(k_z<D>,   cudaFuncAttributeMaxDynamicSharedMemorySize, SMZ2); \
    cudaFuncSetAttribute(k_res<D>, cudaFuncAttributeMaxDynamicSharedMemorySize, SMR2);
    SETU(128) SETU(256) SETU(512)
#undef SETU

    k_reset<<<84, 512>>>();
    k_bias<<<1, 256>>>(skip_b);
    k_pack<<<4032, 256>>>(skip_w, end1_w, end2_w, filt_w, gate_w, res_w);
    k_input<<<BT_ / 512, 256>>>(x, w_in, b_in);

#define LAYERF(D) { \
        pdl_launch(k_zr<D>, BT_ / 256, 256, (size_t)(6144 + 32 * wshof(D)) * 4, \
                   filt_b, gate_b, res_b, i, cur); }
#define LAYERU(D) { \
        pdl_launch(k_z<D>, BT_ / 256, 256, (size_t)SMZ2, filt_b, gate_b, i, cur); \
        pdl_launch(k_res<D>, BT_ / 256, 256, (size_t)SMR2, res_b, i, cur); }

    int cur = 0;
    for (int i = 0; i < NL_; i++) {
        switch (i % LAYERS_) {
            case 0: LAYERF(1)   break;
            case 1: LAYERF(2)   break;
            case 2: LAYERF(4)   break;
            case 3: LAYERF(8)   break;
            case 4: LAYERF(16)  break;
            case 5: LAYERF(32)  break;
            case 6: LAYERF(64)  break;
            case 7: LAYERU(128) break;
            case 8: LAYERU(256) break;
            case 9: LAYERU(512) break;
        }
        cur ^= 1;
    }
#undef LAYERF
#undef LAYERU

    // GEMMs: PDL + per-tile flags -> pipelined with chain tail and each other
    pdl_launch(k_gemm<0>, BT_ / 128, 256, (size_t)SMEM, (const float*)nullptr, (float*)nullptr);
    pdl_launch(k_gemm<1>, BT_ / 128, 256, (size_t)SMEM, end1_b, (float*)nullptr);
    pdl_launch(k_gemm<2>, BT_ / 128, 256, (size_t)SMEM, end2_b, out);
}